// round 10
// baseline (speedup 1.0000x reference)
#include <cuda_runtime.h>
#include <math.h>
#include <stdint.h>

#define BB 16
#define NN 4096
#define MM 1024
#define CF 64
#define INCH 67
#define GRPS (BB*MM)
#define NPT (BB*NN)          // 65536 original points
#define FS 160               // g_f1 row stride (32+64+64)
#define XYZ_OUT ((size_t)BB*MM*3)

// ---------------- device scratch ----------------
__device__ int   g_nbr[(16+32+64)*GRPS];
__device__ float g_f1[(size_t)NPT*FS];    // dense conv0 feature part, point-major
__device__ int   g_cnt[NPT];
__device__ float g_cs[NPT*3];             // sum of centroid coords per point
__device__ float g_aux[9];                // T(3), Qxx,Qyy,Qzz,Qxy,Qxz,Qyz
__device__ float g_s1[128], g_s2[128], g_cr[128*3];
__device__ float g_rawmax[128 * GRPS];
__device__ float g_rawmin[128 * GRPS];
__device__ float g_stats[512];

__device__ __forceinline__ float sqdist_rn(float dx, float dy, float dz){
    return __fadd_rn(__fadd_rn(__fmul_rn(dx,dx),__fmul_rn(dy,dy)),__fmul_rn(dz,dz));
}
__device__ __forceinline__ float gelu_exact(float x){
    return 0.5f * x * (1.0f + erff(x * 0.70710678118654752f));
}
__device__ __forceinline__ void tf32split(float x, float& hi, float& lo){
    uint32_t h; asm("cvt.rna.tf32.f32 %0, %1;" : "=r"(h) : "f"(x));
    hi = __uint_as_float(h);
    float r = x - hi;
    uint32_t l; asm("cvt.rna.tf32.f32 %0, %1;" : "=r"(l) : "f"(r));
    lo = __uint_as_float(l);
}
__device__ __forceinline__ void mma_tf32(float* d,
    uint32_t a0,uint32_t a1,uint32_t a2,uint32_t a3, uint32_t b0,uint32_t b1){
    asm volatile(
        "mma.sync.aligned.m16n8k8.row.col.f32.tf32.tf32.f32 "
        "{%0,%1,%2,%3}, {%4,%5,%6,%7}, {%8,%9}, {%0,%1,%2,%3};"
        : "+f"(d[0]), "+f"(d[1]), "+f"(d[2]), "+f"(d[3])
        : "r"(a0), "r"(a1), "r"(a2), "r"(a3), "r"(b0), "r"(b1));
}
__device__ __forceinline__ void mma3(float* acc, const float4& ah, const float4& al, const float4& bb){
    mma_tf32(acc, __float_as_uint(ah.x),__float_as_uint(ah.y),__float_as_uint(ah.z),__float_as_uint(ah.w),
                  __float_as_uint(bb.x),__float_as_uint(bb.y));
    mma_tf32(acc, __float_as_uint(ah.x),__float_as_uint(ah.y),__float_as_uint(ah.z),__float_as_uint(ah.w),
                  __float_as_uint(bb.z),__float_as_uint(bb.w));
    mma_tf32(acc, __float_as_uint(al.x),__float_as_uint(al.y),__float_as_uint(al.z),__float_as_uint(al.w),
                  __float_as_uint(bb.x),__float_as_uint(bb.y));
}
__device__ __forceinline__ void pack_store(float4* dst, const float* v){
    #pragma unroll
    for (int t=0;t<4;t++){
        float4 fr;
        tf32split(v[t],   fr.x, fr.z);
        tf32split(v[t+4], fr.y, fr.w);
        dst[t]=fr;
    }
}

// ---------------- 1) farthest point sampling ----------------
__global__ void fps_kernel(const float* __restrict__ xyz, float* __restrict__ out_newxyz){
    extern __shared__ float sm[];
    float* sx = sm; float* sy = sm+NN; float* sz = sm+2*NN;
    __shared__ float rv[2][32]; __shared__ int ri[2][32];
    int b = blockIdx.x, t = threadIdx.x, lane = t&31, wid = t>>5;
    for (int i=t;i<NN;i+=blockDim.x){
        const float* p = xyz + ((size_t)b*NN+i)*3;
        sx[i]=p[0]; sy[i]=p[1]; sz[i]=p[2];
    }
    __syncthreads();
    float dreg[4] = {1e10f,1e10f,1e10f,1e10f};
    int far = 0;
    for (int it=0; it<MM; it++){
        float cx=sx[far], cy=sy[far], cz=sz[far];
        if (t==0){
            float* o = out_newxyz + ((size_t)b*MM+it)*3;
            o[0]=cx; o[1]=cy; o[2]=cz;
        }
        float best=-1.0f; int bi=0;
        #pragma unroll
        for (int u=0;u<4;u++){
            int i = t + u*1024;
            float d  = sqdist_rn(sx[i]-cx, sy[i]-cy, sz[i]-cz);
            float nd = fminf(dreg[u], d);
            dreg[u]=nd;
            if (nd>best){ best=nd; bi=i; }
        }
        #pragma unroll
        for (int o=16;o;o>>=1){
            float ov=__shfl_down_sync(0xffffffffu,best,o);
            int   oi=__shfl_down_sync(0xffffffffu,bi,o);
            if (ov>best || (ov==best && oi<bi)){ best=ov; bi=oi; }
        }
        if (lane==0){ rv[it&1][wid]=best; ri[it&1][wid]=bi; }
        __syncthreads();
        float v2 = rv[it&1][lane]; int i2 = ri[it&1][lane];
        #pragma unroll
        for (int o=16;o;o>>=1){
            float ov=__shfl_down_sync(0xffffffffu,v2,o);
            int   oi=__shfl_down_sync(0xffffffffu,i2,o);
            if (ov>v2 || (ov==v2 && oi<i2)){ v2=ov; i2=oi; }
        }
        far = __shfl_sync(0xffffffffu, i2, 0);
    }
}

// ---------------- 2) ball query ----------------
__global__ void __launch_bounds__(256)
ballq_kernel(const float* __restrict__ xyz, const float* __restrict__ newxyz){
    extern __shared__ float sm[];
    float* sx = sm; float* sy = sm+NN; float* sz = sm+2*NN;
    int tid = threadIdx.x;
    int gw0 = blockIdx.x*8;
    int b   = gw0 >> 10;
    const float* base = xyz + (size_t)b*NN*3;
    for (int j=tid;j<NN*3;j+=256){
        float v = base[j];
        int idx = j/3, ch = j-idx*3;
        if (ch==0) sx[idx]=v; else if (ch==1) sy[idx]=v; else sz[idx]=v;
    }
    __syncthreads();
    int w    = tid>>5;
    int lane = tid&31;
    int gw   = gw0 + w;
    float cx=newxyz[gw*3+0], cy=newxyz[gw*3+1], cz=newxyz[gw*3+2];
    const float R2_0=(float)(0.1*0.1), R2_1=(float)(0.2*0.2), R2_2=(float)(0.4*0.4);
    int c0=0,c1=0,c2=0, f0=0,f1=0,f2=0;
    int* n0 = g_nbr + gw*16;
    int* n1 = g_nbr + 16*GRPS + gw*32;
    int* n2 = g_nbr + 48*GRPS + gw*64;
    for (int s=0;s<NN;s+=32){
        int i = s + lane;
        float d = sqdist_rn(sx[i]-cx, sy[i]-cy, sz[i]-cz);
        unsigned m0=__ballot_sync(0xffffffffu, d<=R2_0);
        unsigned m1=__ballot_sync(0xffffffffu, d<=R2_1);
        unsigned m2=__ballot_sync(0xffffffffu, d<=R2_2);
        if (m0 && c0<16){
            if (c0==0) f0 = s + __ffs(m0) - 1;
            int r = __popc(m0 & ((1u<<lane)-1u));
            if ((m0>>lane)&1u){ if (c0+r<16) n0[c0+r]=i; }
            c0 += __popc(m0); if (c0>16) c0=16;
        }
        if (m1 && c1<32){
            if (c1==0) f1 = s + __ffs(m1) - 1;
            int r = __popc(m1 & ((1u<<lane)-1u));
            if ((m1>>lane)&1u){ if (c1+r<32) n1[c1+r]=i; }
            c1 += __popc(m1); if (c1>32) c1=32;
        }
        if (m2 && c2<64){
            if (c2==0) f2 = s + __ffs(m2) - 1;
            int r = __popc(m2 & ((1u<<lane)-1u));
            if ((m2>>lane)&1u){ if (c2+r<64) n2[c2+r]=i; }
            c2 += __popc(m2); if (c2>64) c2=64;
        }
        if (c0>=16 && c1>=32 && c2>=64) break;
    }
    for (int j=c0+lane;j<16;j+=32) n0[j]=f0;
    for (int j=c1+lane;j<32;j+=32) n1[j]=f1;
    for (int j=c2+lane;j<64;j+=32) n2[j]=f2;
}

// ---------------- zero per-scale accumulators ----------------
__global__ void zero_kernel(){
    int i = blockIdx.x*256 + threadIdx.x;
    g_cnt[i]=0;
    g_cs[i*3]=0.0f; g_cs[i*3+1]=0.0f; g_cs[i*3+2]=0.0f;
    if (blockIdx.x==0){
        int t=threadIdx.x;
        g_stats[t]=0.0f; g_stats[256+t]=0.0f;
        if (t<128){ g_s1[t]=0.0f; g_s2[t]=0.0f; }
        if (t<9) g_aux[t]=0.0f;
        g_cr[t]=0.0f; if (t<128) g_cr[256+t]=0.0f;
        g_cr[128+t]=0.0f;
    }
}

// ---------------- dense conv0 (feature part only) -> g_f1[pt][coff..] ----------------
template<int C0>
__global__ void __launch_bounds__(256)
dense_kernel(const float* __restrict__ feat, const float* __restrict__ w0, int coff){
    constexpr int KS = 8;                // 64 feat channels
    constexpr int CT = C0/16;
    extern __shared__ float smf[];
    float4* inb4 = (float4*)smf;         // KS*128*4
    float4* wh4  = inb4 + KS*128*4;      // KS*CT*32
    float4* wl4  = wh4 + KS*CT*32;
    int tid = threadIdx.x;
    int tp  = blockIdx.x*128;

    for (int i=tid;i<KS*CT*32;i+=256){
        int ks=i/(CT*32), rem=i-ks*CT*32, ct=rem>>5, ln=rem&31;
        int g=ln>>2, t=ln&3, c0=ct*16, k=ks*8+3;     // cols 3..66 = feat weights
        float4 H,L;
        tf32split(w0[(c0+g  )*INCH + k+t  ], H.x, L.x);
        tf32split(w0[(c0+g+8)*INCH + k+t  ], H.y, L.y);
        tf32split(w0[(c0+g  )*INCH + k+t+4], H.z, L.z);
        tf32split(w0[(c0+g+8)*INCH + k+t+4], H.w, L.w);
        wh4[i]=H; wl4[i]=L;
    }
    { // coalesced fill: 2 threads per point, half h covers 32 feat channels
        int p = tid>>1, h = tid&1;
        const float* fs = feat + (size_t)(tp+p)*CF + h*32;
        float ch[32];
        #pragma unroll
        for (int q=0;q<8;q++){
            float4 v = *(const float4*)(fs + q*4);
            ch[q*4+0]=v.x; ch[q*4+1]=v.y; ch[q*4+2]=v.z; ch[q*4+3]=v.w;
        }
        #pragma unroll
        for (int ks=0;ks<4;ks++)
            pack_store(inb4 + ((((h*4+ks)<<7)+p)<<2), ch+ks*8);
    }
    __syncthreads();

    constexpr int CT2 = CT/2;
    constexpr int PG2 = 8/CT2;
    constexpr int PW  = 128/PG2;
    constexpr int NT  = PW/8;
    int ln = tid&31, w = tid>>5;
    int g = ln>>2, t = ln&3;
    int ct2 = w%CT2;
    int pb  = (w/CT2)*PW;

    float acc[2][NT][4];
    #pragma unroll
    for (int cc=0;cc<2;cc++)
        #pragma unroll
        for (int nt=0;nt<NT;nt++){ acc[cc][nt][0]=0;acc[cc][nt][1]=0;acc[cc][nt][2]=0;acc[cc][nt][3]=0; }

    for (int ks=0; ks<KS; ks++){
        float4 ah0 = wh4[(ks*CT+ct2*2  )*32+ln];
        float4 al0 = wl4[(ks*CT+ct2*2  )*32+ln];
        float4 ah1 = wh4[(ks*CT+ct2*2+1)*32+ln];
        float4 al1 = wl4[(ks*CT+ct2*2+1)*32+ln];
        #pragma unroll
        for (int nt=0;nt<NT;nt++){
            float4 bb = inb4[((ks<<7) + pb + nt*8 + g)*4 + t];
            mma3(acc[0][nt], ah0, al0, bb);
            mma3(acc[1][nt], ah1, al1, bb);
        }
    }

    #pragma unroll
    for (int cc=0;cc<2;cc++){
        int ch0 = (ct2*2+cc)*16;
        #pragma unroll
        for (int nt=0;nt<NT;nt++){
            int pofs = tp + pb + nt*8 + 2*t;
            size_t base = (size_t)pofs*FS + coff + ch0;
            g_f1[base + g]        = acc[cc][nt][0];
            g_f1[base + FS + g]   = acc[cc][nt][1];
            g_f1[base + g+8]      = acc[cc][nt][2];
            g_f1[base + FS + g+8] = acc[cc][nt][3];
        }
    }
}

// ---------------- histogram over gathered points: cnt, CS, T, Q ----------------
template<int K>
__global__ void hist_kernel(const float* __restrict__ xyz, const float* __restrict__ nxyz, int noff){
    int gp = blockIdx.x*256 + threadIdx.x;
    int g  = gp / K;
    int n  = g_nbr[noff+gp];
    int b  = g >> 10;
    int pt = (b<<12) + n;
    float cgx=nxyz[g*3], cgy=nxyz[g*3+1], cgz=nxyz[g*3+2];
    float dx = xyz[pt*3]-cgx, dy = xyz[pt*3+1]-cgy, dz = xyz[pt*3+2]-cgz;
    atomicAdd(&g_cnt[pt], 1);
    atomicAdd(&g_cs[pt*3+0], cgx);
    atomicAdd(&g_cs[pt*3+1], cgy);
    atomicAdd(&g_cs[pt*3+2], cgz);
    float v[9] = {dx,dy,dz, dx*dx,dy*dy,dz*dz, dx*dy,dx*dz,dy*dz};
    #pragma unroll
    for (int q=0;q<9;q++){
        float s=v[q];
        #pragma unroll
        for (int o=16;o;o>>=1) s += __shfl_down_sync(0xffffffffu,s,o);
        v[q]=s;
    }
    if ((threadIdx.x&31)==0){
        #pragma unroll
        for (int q=0;q<9;q++) atomicAdd(&g_aux[q], v[q]);
    }
}

// ---------------- per-channel stats from F1, cnt, R ----------------
template<int C0>
__global__ void chanstat_kernel(const float* __restrict__ xyz, int coff){
    __shared__ float sCnt[256], sRx[256], sRy[256], sRz[256];
    __shared__ float st1[C0], st2[C0], scx[C0], scy[C0], scz[C0];
    int tid = threadIdx.x, n0 = blockIdx.x*256;
    {
        int n = n0 + tid;
        float c = (float)g_cnt[n];
        sCnt[tid] = c;
        sRx[tid] = c*xyz[n*3+0] - g_cs[n*3+0];
        sRy[tid] = c*xyz[n*3+1] - g_cs[n*3+1];
        sRz[tid] = c*xyz[n*3+2] - g_cs[n*3+2];
    }
    if (tid < C0){ st1[tid]=0; st2[tid]=0; scx[tid]=0; scy[tid]=0; scz[tid]=0; }
    __syncthreads();

    constexpr int QN = C0/4, NR = 256/QN;
    int cq = tid % QN, j = tid / QN;
    float a1[4]={0,0,0,0}, a2[4]={0,0,0,0}, ax[4]={0,0,0,0}, ay[4]={0,0,0,0}, az[4]={0,0,0,0};
    for (int jj=j; jj<256; jj+=NR){
        float4 f = *(const float4*)(g_f1 + (size_t)(n0+jj)*FS + coff + cq*4);
        float c = sCnt[jj], Rx = sRx[jj], Ry = sRy[jj], Rz = sRz[jj];
        float fv[4] = {f.x,f.y,f.z,f.w};
        #pragma unroll
        for (int q=0;q<4;q++){
            a1[q] = fmaf(c, fv[q], a1[q]);
            a2[q] = fmaf(c*fv[q], fv[q], a2[q]);
            ax[q] = fmaf(fv[q], Rx, ax[q]);
            ay[q] = fmaf(fv[q], Ry, ay[q]);
            az[q] = fmaf(fv[q], Rz, az[q]);
        }
    }
    #pragma unroll
    for (int q=0;q<4;q++){
        atomicAdd(&st1[cq*4+q], a1[q]);
        atomicAdd(&st2[cq*4+q], a2[q]);
        atomicAdd(&scx[cq*4+q], ax[q]);
        atomicAdd(&scy[cq*4+q], ay[q]);
        atomicAdd(&scz[cq*4+q], az[q]);
    }
    __syncthreads();
    if (tid < C0){
        atomicAdd(&g_s1[tid], st1[tid]);
        atomicAdd(&g_s2[tid], st2[tid]);
        atomicAdd(&g_cr[tid*3+0], scx[tid]);
        atomicAdd(&g_cr[tid*3+1], scy[tid]);
        atomicAdd(&g_cr[tid*3+2], scz[tid]);
    }
}

// ---------------- fold xyz-weight terms into g_stats ----------------
template<int C0>
__global__ void statfinal_kernel(const float* __restrict__ w0){
    int c = threadIdx.x;
    float wx=w0[c*INCH+0], wy=w0[c*INCH+1], wz=w0[c*INCH+2];
    float T0=g_aux[0], T1=g_aux[1], T2=g_aux[2];
    float Qxx=g_aux[3], Qyy=g_aux[4], Qzz=g_aux[5], Qxy=g_aux[6], Qxz=g_aux[7], Qyz=g_aux[8];
    g_stats[c] = g_s1[c] + wx*T0 + wy*T1 + wz*T2;
    float cr = wx*g_cr[c*3+0] + wy*g_cr[c*3+1] + wz*g_cr[c*3+2];
    float qf = wx*wx*Qxx + wy*wy*Qyy + wz*wz*Qzz
             + 2.0f*(wx*wy*Qxy + wx*wz*Qxz + wy*wz*Qyz);
    g_stats[128+c] = g_s2[c] + 2.0f*cr + qf;
}

// ---------------- pass C: on-the-fly x0 -> norm+gelu -> tf32 mma conv1 ----------------
template<int K,int C0,int C1,int PTS,int NTH>
__global__ void __launch_bounds__(NTH)
passC_kernel(const float* __restrict__ w1,
             const float* __restrict__ g0v, const float* __restrict__ b0v,
             const float* __restrict__ w0,
             const float* __restrict__ xyz, const float* __restrict__ nxyz,
             int noff, int coff)
{
    const int P = GRPS*K;
    constexpr int KS = C0/8;
    constexpr int CT = C1/16;
    extern __shared__ float smf[];
    float4* gsb4 = (float4*)smf;                 // KS*PTS*4
    float4* wh4  = gsb4 + KS*PTS*4;              // KS*CT*32
    float4* wl4  = wh4 + KS*CT*32;
    float*  qa   = (float*)(wl4 + KS*CT*32);     // 5*C0: qa, qb, q0, q1, q2
    float*  qb   = qa + C0;
    float*  q0   = qb + C0;
    float*  q1   = q0 + C0;
    float*  q2   = q1 + C0;
    float*  st   = q2 + C0;                      // 2*C1
    int tid = threadIdx.x, tp = blockIdx.x*PTS;

    if (tid < C0){
        float cnt  = (float)P;
        float mean = g_stats[tid]/cnt;
        float var  = g_stats[128+tid]/cnt - mean*mean;
        float a    = g0v[tid]/sqrtf(var + 1e-5f);
        qa[tid] = a;
        qb[tid] = b0v[tid] - mean*a;
        q0[tid] = a*w0[tid*INCH+0];
        q1[tid] = a*w0[tid*INCH+1];
        q2[tid] = a*w0[tid*INCH+2];
    }
    for (int i=tid;i<KS*CT*32;i+=NTH){
        int ks=i/(CT*32), rem=i-ks*CT*32, ct=rem>>5, ln=rem&31;
        int g=ln>>2, t=ln&3, c0=ct*16, k=ks*8;
        float4 H,L;
        tf32split(w1[(c0+g  )*C0 + k+t  ], H.x, L.x);
        tf32split(w1[(c0+g+8)*C0 + k+t  ], H.y, L.y);
        tf32split(w1[(c0+g  )*C0 + k+t+4], H.z, L.z);
        tf32split(w1[(c0+g+8)*C0 + k+t+4], H.w, L.w);
        wh4[i]=H; wl4[i]=L;
    }
    for (int i=tid;i<2*C1;i+=NTH) st[i]=0.0f;
    __syncthreads();

    { // fill: thread owns (point p, half h): compute x0 = F1 + Wx·rel, normalize+gelu, split
        int p = tid>>1, h = tid&1;
        int gp = tp + p;
        int g  = gp / K;
        int n  = g_nbr[noff+gp];
        int b  = g >> 10;
        int pt = (b<<12) + n;
        float dx = xyz[pt*3+0]-nxyz[g*3+0];
        float dy = xyz[pt*3+1]-nxyz[g*3+1];
        float dz = xyz[pt*3+2]-nxyz[g*3+2];
        const float* f1 = g_f1 + (size_t)pt*FS + coff;
        #pragma unroll
        for (int ks=h*(KS/2); ks<(h+1)*(KS/2); ks++){
            float4 fa = *(const float4*)(f1 + ks*8);
            float4 fb = *(const float4*)(f1 + ks*8 + 4);
            float4 A0 = *(const float4*)(qa + ks*8), A1 = *(const float4*)(qa + ks*8 + 4);
            float4 B0 = *(const float4*)(qb + ks*8), B1 = *(const float4*)(qb + ks*8 + 4);
            float4 X0 = *(const float4*)(q0 + ks*8), X1 = *(const float4*)(q0 + ks*8 + 4);
            float4 Y0 = *(const float4*)(q1 + ks*8), Y1 = *(const float4*)(q1 + ks*8 + 4);
            float4 Z0 = *(const float4*)(q2 + ks*8), Z1 = *(const float4*)(q2 + ks*8 + 4);
            float ch[8];
            ch[0]=fmaf(X0.x,dx,fmaf(Y0.x,dy,fmaf(Z0.x,dz,fmaf(A0.x,fa.x,B0.x))));
            ch[1]=fmaf(X0.y,dx,fmaf(Y0.y,dy,fmaf(Z0.y,dz,fmaf(A0.y,fa.y,B0.y))));
            ch[2]=fmaf(X0.z,dx,fmaf(Y0.z,dy,fmaf(Z0.z,dz,fmaf(A0.z,fa.z,B0.z))));
            ch[3]=fmaf(X0.w,dx,fmaf(Y0.w,dy,fmaf(Z0.w,dz,fmaf(A0.w,fa.w,B0.w))));
            ch[4]=fmaf(X1.x,dx,fmaf(Y1.x,dy,fmaf(Z1.x,dz,fmaf(A1.x,fb.x,B1.x))));
            ch[5]=fmaf(X1.y,dx,fmaf(Y1.y,dy,fmaf(Z1.y,dz,fmaf(A1.y,fb.y,B1.y))));
            ch[6]=fmaf(X1.z,dx,fmaf(Y1.z,dy,fmaf(Z1.z,dz,fmaf(A1.z,fb.z,B1.z))));
            ch[7]=fmaf(X1.w,dx,fmaf(Y1.w,dy,fmaf(Z1.w,dz,fmaf(A1.w,fb.w,B1.w))));
            #pragma unroll
            for (int j=0;j<8;j++) ch[j] = gelu_exact(ch[j]);
            pack_store(gsb4 + ((ks*PTS+p)<<2), ch);
        }
    }
    __syncthreads();

    constexpr int NW  = NTH/32;
    constexpr int CT2 = CT/2;
    constexpr int PG2 = NW/CT2;
    constexpr int PW  = PTS/PG2;
    constexpr int NT  = PW/8;
    int ln = tid&31, w = tid>>5;
    int g = ln>>2, t = ln&3;
    int ct2 = w%CT2;
    int pb  = (w/CT2)*PW;

    float acc[2][NT][4];
    #pragma unroll
    for (int cc=0;cc<2;cc++)
        #pragma unroll
        for (int nt=0;nt<NT;nt++){ acc[cc][nt][0]=0;acc[cc][nt][1]=0;acc[cc][nt][2]=0;acc[cc][nt][3]=0; }

    for (int ks=0; ks<KS; ks++){
        float4 ah0 = wh4[(ks*CT+ct2*2  )*32+ln];
        float4 al0 = wl4[(ks*CT+ct2*2  )*32+ln];
        float4 ah1 = wh4[(ks*CT+ct2*2+1)*32+ln];
        float4 al1 = wl4[(ks*CT+ct2*2+1)*32+ln];
        #pragma unroll
        for (int nt=0;nt<NT;nt++){
            float4 bb = gsb4[(ks*PTS + pb + nt*8 + g)*4 + t];
            mma3(acc[0][nt], ah0, al0, bb);
            mma3(acc[1][nt], ah1, al1, bb);
        }
    }

    constexpr int NTPG = K/8;
    constexpr int NG   = NT/NTPG;
    int gbase = (tp + pb)/K;
    #pragma unroll
    for (int cc=0;cc<2;cc++){
        int ch0 = (ct2*2+cc)*16;
        float sA=0,sA2=0,sB=0,sB2=0;
        #pragma unroll
        for (int nt=0;nt<NT;nt++){
            float x=acc[cc][nt][0], y=acc[cc][nt][1], z=acc[cc][nt][2], v=acc[cc][nt][3];
            sA += x+y; sA2 += x*x+y*y; sB += z+v; sB2 += z*z+v*v;
        }
        #pragma unroll
        for (int o=1;o<4;o<<=1){
            sA  += __shfl_xor_sync(0xffffffffu,sA,o);
            sA2 += __shfl_xor_sync(0xffffffffu,sA2,o);
            sB  += __shfl_xor_sync(0xffffffffu,sB,o);
            sB2 += __shfl_xor_sync(0xffffffffu,sB2,o);
        }
        if (t==0){
            atomicAdd(&st[ch0+g],      sA);  atomicAdd(&st[C1+ch0+g],   sA2);
            atomicAdd(&st[ch0+g+8],    sB);  atomicAdd(&st[C1+ch0+g+8], sB2);
        }
        #pragma unroll
        for (int gi=0; gi<NG; gi++){
            float mxA=-3.4e38f, mnA=3.4e38f, mxB=-3.4e38f, mnB=3.4e38f;
            #pragma unroll
            for (int u=0; u<NTPG; u++){
                float* a = acc[cc][gi*NTPG+u];
                mxA=fmaxf(mxA,fmaxf(a[0],a[1])); mnA=fminf(mnA,fminf(a[0],a[1]));
                mxB=fmaxf(mxB,fmaxf(a[2],a[3])); mnB=fminf(mnB,fminf(a[2],a[3]));
            }
            #pragma unroll
            for (int o=1;o<4;o<<=1){
                mxA=fmaxf(mxA,__shfl_xor_sync(0xffffffffu,mxA,o));
                mnA=fminf(mnA,__shfl_xor_sync(0xffffffffu,mnA,o));
                mxB=fmaxf(mxB,__shfl_xor_sync(0xffffffffu,mxB,o));
                mnB=fminf(mnB,__shfl_xor_sync(0xffffffffu,mnB,o));
            }
            if (t==0){
                int gg = gbase + gi;
                g_rawmax[(ch0+g)*GRPS   + gg] = mxA;  g_rawmin[(ch0+g)*GRPS   + gg] = mnA;
                g_rawmax[(ch0+g+8)*GRPS + gg] = mxB;  g_rawmin[(ch0+g+8)*GRPS + gg] = mnB;
            }
        }
    }
    __syncthreads();
    for (int i=tid;i<C1;i+=NTH){
        atomicAdd(&g_stats[256+i], st[i]);
        atomicAdd(&g_stats[384+i], st[C1+i]);
    }
}

// ---------------- finalize ----------------
template<int K,int C1>
__global__ void out_kernel(const float* __restrict__ g1v, const float* __restrict__ b1v,
                           float* __restrict__ out, int chOff)
{
    int i = blockIdx.x*blockDim.x + threadIdx.x;
    if (i >= C1*GRPS) return;
    int c = i / GRPS; int g = i - c*GRPS;
    int b = g >> 10, m = g & 1023;
    float cnt  = (float)(GRPS*K);
    float mean = g_stats[256+c]/cnt;
    float var  = g_stats[384+c]/cnt - mean*mean;
    float a    = g1v[c]/sqrtf(var + 1e-5f);
    float bb   = b1v[c] - mean*a;
    float v1   = a*g_rawmax[c*GRPS + g] + bb;
    float v2   = a*g_rawmin[c*GRPS + g] + bb;
    out[XYZ_OUT + ((size_t)b*320 + chOff + c)*MM + m] = fmaxf(gelu_exact(v1), gelu_exact(v2));
}

// ---------------- launch ----------------
extern "C" void kernel_launch(void* const* d_in, const int* in_sizes, int n_in,
                              void* d_out, int out_size)
{
    const float* xyz  = (const float*)d_in[0];
    const float* feat = (const float*)d_in[1];
    const float* w00  = (const float*)d_in[2];
    const float* w01  = (const float*)d_in[3];
    const float* w10  = (const float*)d_in[4];
    const float* w11  = (const float*)d_in[5];
    const float* w20  = (const float*)d_in[6];
    const float* w21  = (const float*)d_in[7];
    const float* g00  = (const float*)d_in[8];
    const float* b00  = (const float*)d_in[9];
    const float* g01  = (const float*)d_in[10];
    const float* b01  = (const float*)d_in[11];
    const float* g10  = (const float*)d_in[12];
    const float* b10  = (const float*)d_in[13];
    const float* g11  = (const float*)d_in[14];
    const float* b11  = (const float*)d_in[15];
    const float* g20  = (const float*)d_in[16];
    const float* b20  = (const float*)d_in[17];
    const float* g21  = (const float*)d_in[18];
    const float* b21  = (const float*)d_in[19];
    float* out = (float*)d_out;
    float* newxyz = out;

    const int smFPS = 3*NN*4;
    const int smBQ  = 3*NN*4;
    const int smD32 = (8*128*4 + 2*8*2*32)*16;
    const int smD64 = (8*128*4 + 2*8*4*32)*16;
    const int smC0  = (4*128*4 + 2*4*4*32)*16 + (5*32 + 2*64)*4;
    const int smC12 = (8*256*4 + 2*8*8*32)*16 + (5*64 + 2*128)*4;

    cudaFuncSetAttribute(fps_kernel,       cudaFuncAttributeMaxDynamicSharedMemorySize, smFPS);
    cudaFuncSetAttribute(ballq_kernel,     cudaFuncAttributeMaxDynamicSharedMemorySize, smBQ);
    cudaFuncSetAttribute(dense_kernel<32>, cudaFuncAttributeMaxDynamicSharedMemorySize, smD32);
    cudaFuncSetAttribute(dense_kernel<64>, cudaFuncAttributeMaxDynamicSharedMemorySize, smD64);
    cudaFuncSetAttribute(passC_kernel<16,32,64,128,256>,  cudaFuncAttributeMaxDynamicSharedMemorySize, smC0);
    cudaFuncSetAttribute(passC_kernel<32,64,128,256,512>, cudaFuncAttributeMaxDynamicSharedMemorySize, smC12);
    cudaFuncSetAttribute(passC_kernel<64,64,128,256,512>, cudaFuncAttributeMaxDynamicSharedMemorySize, smC12);

    fps_kernel<<<BB, 1024, smFPS>>>(xyz, newxyz);
    ballq_kernel<<<GRPS/8, 256, smBQ>>>(xyz, newxyz);

    dense_kernel<32><<<NPT/128, 256, smD32>>>(feat, w00, 0);
    dense_kernel<64><<<NPT/128, 256, smD64>>>(feat, w10, 32);
    dense_kernel<64><<<NPT/128, 256, smD64>>>(feat, w20, 96);

    // ---- scale 0: k=16, C0=32, C1=64
    zero_kernel<<<NPT/256, 256>>>();
    hist_kernel<16><<<GRPS*16/256, 256>>>(xyz, newxyz, 0);
    chanstat_kernel<32><<<NPT/256, 256>>>(xyz, 0);
    statfinal_kernel<32><<<1, 32>>>(w00);
    passC_kernel<16,32,64,128,256><<<GRPS*16/128, 256, smC0>>>(w01, g00, b00, w00, xyz, newxyz, 0, 0);
    out_kernel<16,64><<<(64*GRPS)/256, 256>>>(g01, b01, out, 0);

    // ---- scale 1: k=32, C0=64, C1=128
    zero_kernel<<<NPT/256, 256>>>();
    hist_kernel<32><<<GRPS*32/256, 256>>>(xyz, newxyz, 16*GRPS);
    chanstat_kernel<64><<<NPT/256, 256>>>(xyz, 32);
    statfinal_kernel<64><<<1, 64>>>(w10);
    passC_kernel<32,64,128,256,512><<<GRPS*32/256, 512, smC12>>>(w11, g10, b10, w10, xyz, newxyz, 16*GRPS, 32);
    out_kernel<32,128><<<(128*GRPS)/256, 256>>>(g11, b11, out, 64);

    // ---- scale 2: k=64, C0=64, C1=128
    zero_kernel<<<NPT/256, 256>>>();
    hist_kernel<64><<<GRPS*64/256, 256>>>(xyz, newxyz, 48*GRPS);
    chanstat_kernel<64><<<NPT/256, 256>>>(xyz, 96);
    statfinal_kernel<64><<<1, 64>>>(w20);
    passC_kernel<64,64,128,256,512><<<GRPS*64/256, 512, smC12>>>(w21, g20, b20, w20, xyz, newxyz, 48*GRPS, 96);
    out_kernel<64,128><<<(128*GRPS)/256, 256>>>(g21, b21, out, 192);
}

// round 12
// speedup vs baseline: 1.2901x; 1.2901x over previous
#include <cuda_runtime.h>
#include <math.h>
#include <stdint.h>

#define BB 16
#define NN 4096
#define MM 1024
#define CF 64
#define INCH 67
#define GRPS (BB*MM)
#define NPT (BB*NN)          // 65536 original points
#define FS 160               // g_f1 row stride (32+64+64)
#define XYZ_OUT ((size_t)BB*MM*3)

// ---------------- device scratch ----------------
__device__ int   g_nbr[(16+32+64)*GRPS];
__device__ float g_f1[(size_t)NPT*FS];    // dense conv0 feature part, point-major
__device__ int   g_cnt[NPT];
__device__ float g_cs[NPT*3];             // sum of centroid coords per point
__device__ float g_auxp[9*32];            // T(3) + Q(6), each padded 128B apart (slice-spread)
__device__ float g_s1[128], g_s2[128], g_cr[128*3];
__device__ float g_rawmax[128 * GRPS];
__device__ float g_rawmin[128 * GRPS];
__device__ float g_stats[512];

__device__ __forceinline__ float sqdist_rn(float dx, float dy, float dz){
    return __fadd_rn(__fadd_rn(__fmul_rn(dx,dx),__fmul_rn(dy,dy)),__fmul_rn(dz,dz));
}
__device__ __forceinline__ float gelu_exact(float x){
    return 0.5f * x * (1.0f + erff(x * 0.70710678118654752f));
}
__device__ __forceinline__ void tf32split(float x, float& hi, float& lo){
    uint32_t h; asm("cvt.rna.tf32.f32 %0, %1;" : "=r"(h) : "f"(x));
    hi = __uint_as_float(h);
    float r = x - hi;
    uint32_t l; asm("cvt.rna.tf32.f32 %0, %1;" : "=r"(l) : "f"(r));
    lo = __uint_as_float(l);
}
__device__ __forceinline__ void mma_tf32(float* d,
    uint32_t a0,uint32_t a1,uint32_t a2,uint32_t a3, uint32_t b0,uint32_t b1){
    asm volatile(
        "mma.sync.aligned.m16n8k8.row.col.f32.tf32.tf32.f32 "
        "{%0,%1,%2,%3}, {%4,%5,%6,%7}, {%8,%9}, {%0,%1,%2,%3};"
        : "+f"(d[0]), "+f"(d[1]), "+f"(d[2]), "+f"(d[3])
        : "r"(a0), "r"(a1), "r"(a2), "r"(a3), "r"(b0), "r"(b1));
}
__device__ __forceinline__ void mma3(float* acc, const float4& ah, const float4& al, const float4& bb){
    mma_tf32(acc, __float_as_uint(ah.x),__float_as_uint(ah.y),__float_as_uint(ah.z),__float_as_uint(ah.w),
                  __float_as_uint(bb.x),__float_as_uint(bb.y));
    mma_tf32(acc, __float_as_uint(ah.x),__float_as_uint(ah.y),__float_as_uint(ah.z),__float_as_uint(ah.w),
                  __float_as_uint(bb.z),__float_as_uint(bb.w));
    mma_tf32(acc, __float_as_uint(al.x),__float_as_uint(al.y),__float_as_uint(al.z),__float_as_uint(al.w),
                  __float_as_uint(bb.x),__float_as_uint(bb.y));
}
__device__ __forceinline__ void pack_store(float4* dst, const float* v){
    #pragma unroll
    for (int t=0;t<4;t++){
        float4 fr;
        tf32split(v[t],   fr.x, fr.z);
        tf32split(v[t+4], fr.y, fr.w);
        dst[t]=fr;
    }
}

// ---------------- 1) farthest point sampling ----------------
__global__ void fps_kernel(const float* __restrict__ xyz, float* __restrict__ out_newxyz){
    extern __shared__ float sm[];
    float* sx = sm; float* sy = sm+NN; float* sz = sm+2*NN;
    __shared__ float rv[2][32]; __shared__ int ri[2][32];
    int b = blockIdx.x, t = threadIdx.x, lane = t&31, wid = t>>5;
    for (int i=t;i<NN;i+=blockDim.x){
        const float* p = xyz + ((size_t)b*NN+i)*3;
        sx[i]=p[0]; sy[i]=p[1]; sz[i]=p[2];
    }
    __syncthreads();
    float dreg[4] = {1e10f,1e10f,1e10f,1e10f};
    int far = 0;
    for (int it=0; it<MM; it++){
        float cx=sx[far], cy=sy[far], cz=sz[far];
        if (t==0){
            float* o = out_newxyz + ((size_t)b*MM+it)*3;
            o[0]=cx; o[1]=cy; o[2]=cz;
        }
        float best=-1.0f; int bi=0;
        #pragma unroll
        for (int u=0;u<4;u++){
            int i = t + u*1024;
            float d  = sqdist_rn(sx[i]-cx, sy[i]-cy, sz[i]-cz);
            float nd = fminf(dreg[u], d);
            dreg[u]=nd;
            if (nd>best){ best=nd; bi=i; }
        }
        #pragma unroll
        for (int o=16;o;o>>=1){
            float ov=__shfl_down_sync(0xffffffffu,best,o);
            int   oi=__shfl_down_sync(0xffffffffu,bi,o);
            if (ov>best || (ov==best && oi<bi)){ best=ov; bi=oi; }
        }
        if (lane==0){ rv[it&1][wid]=best; ri[it&1][wid]=bi; }
        __syncthreads();
        float v2 = rv[it&1][lane]; int i2 = ri[it&1][lane];
        #pragma unroll
        for (int o=16;o;o>>=1){
            float ov=__shfl_down_sync(0xffffffffu,v2,o);
            int   oi=__shfl_down_sync(0xffffffffu,i2,o);
            if (ov>v2 || (ov==v2 && oi<i2)){ v2=ov; i2=oi; }
        }
        far = __shfl_sync(0xffffffffu, i2, 0);
    }
}

// ---------------- 2) ball query ----------------
__global__ void __launch_bounds__(256)
ballq_kernel(const float* __restrict__ xyz, const float* __restrict__ newxyz){
    extern __shared__ float sm[];
    float* sx = sm; float* sy = sm+NN; float* sz = sm+2*NN;
    int tid = threadIdx.x;
    int gw0 = blockIdx.x*8;
    int b   = gw0 >> 10;
    const float* base = xyz + (size_t)b*NN*3;
    for (int j=tid;j<NN*3;j+=256){
        float v = base[j];
        int idx = j/3, ch = j-idx*3;
        if (ch==0) sx[idx]=v; else if (ch==1) sy[idx]=v; else sz[idx]=v;
    }
    __syncthreads();
    int w    = tid>>5;
    int lane = tid&31;
    int gw   = gw0 + w;
    float cx=newxyz[gw*3+0], cy=newxyz[gw*3+1], cz=newxyz[gw*3+2];
    const float R2_0=(float)(0.1*0.1), R2_1=(float)(0.2*0.2), R2_2=(float)(0.4*0.4);
    int c0=0,c1=0,c2=0, f0=0,f1=0,f2=0;
    int* n0 = g_nbr + gw*16;
    int* n1 = g_nbr + 16*GRPS + gw*32;
    int* n2 = g_nbr + 48*GRPS + gw*64;
    for (int s=0;s<NN;s+=32){
        int i = s + lane;
        float d = sqdist_rn(sx[i]-cx, sy[i]-cy, sz[i]-cz);
        unsigned m0=__ballot_sync(0xffffffffu, d<=R2_0);
        unsigned m1=__ballot_sync(0xffffffffu, d<=R2_1);
        unsigned m2=__ballot_sync(0xffffffffu, d<=R2_2);
        if (m0 && c0<16){
            if (c0==0) f0 = s + __ffs(m0) - 1;
            int r = __popc(m0 & ((1u<<lane)-1u));
            if ((m0>>lane)&1u){ if (c0+r<16) n0[c0+r]=i; }
            c0 += __popc(m0); if (c0>16) c0=16;
        }
        if (m1 && c1<32){
            if (c1==0) f1 = s + __ffs(m1) - 1;
            int r = __popc(m1 & ((1u<<lane)-1u));
            if ((m1>>lane)&1u){ if (c1+r<32) n1[c1+r]=i; }
            c1 += __popc(m1); if (c1>32) c1=32;
        }
        if (m2 && c2<64){
            if (c2==0) f2 = s + __ffs(m2) - 1;
            int r = __popc(m2 & ((1u<<lane)-1u));
            if ((m2>>lane)&1u){ if (c2+r<64) n2[c2+r]=i; }
            c2 += __popc(m2); if (c2>64) c2=64;
        }
        if (c0>=16 && c1>=32 && c2>=64) break;
    }
    for (int j=c0+lane;j<16;j+=32) n0[j]=f0;
    for (int j=c1+lane;j<32;j+=32) n1[j]=f1;
    for (int j=c2+lane;j<64;j+=32) n2[j]=f2;
}

// ---------------- zero per-scale accumulators ----------------
__global__ void zero_kernel(){
    int i = blockIdx.x*256 + threadIdx.x;
    g_cnt[i]=0;
    g_cs[i*3]=0.0f; g_cs[i*3+1]=0.0f; g_cs[i*3+2]=0.0f;
    if (blockIdx.x==0){
        int t=threadIdx.x;
        g_stats[t]=0.0f; g_stats[256+t]=0.0f;
        if (t<128){ g_s1[t]=0.0f; g_s2[t]=0.0f; }
        if (t<9*32) g_auxp[t]=0.0f;
        g_cr[t]=0.0f; if (t<128) g_cr[256+t]=0.0f;
        g_cr[128+t]=0.0f;
    }
}

// ---------------- dense conv0 (feature part only) -> g_f1[pt][coff..] ----------------
template<int C0>
__global__ void __launch_bounds__(256)
dense_kernel(const float* __restrict__ feat, const float* __restrict__ w0, int coff){
    constexpr int KS = 8;
    constexpr int CT = C0/16;
    extern __shared__ float smf[];
    float4* inb4 = (float4*)smf;
    float4* wh4  = inb4 + KS*128*4;
    float4* wl4  = wh4 + KS*CT*32;
    int tid = threadIdx.x;
    int tp  = blockIdx.x*128;

    for (int i=tid;i<KS*CT*32;i+=256){
        int ks=i/(CT*32), rem=i-ks*CT*32, ct=rem>>5, ln=rem&31;
        int g=ln>>2, t=ln&3, c0=ct*16, k=ks*8+3;
        float4 H,L;
        tf32split(w0[(c0+g  )*INCH + k+t  ], H.x, L.x);
        tf32split(w0[(c0+g+8)*INCH + k+t  ], H.y, L.y);
        tf32split(w0[(c0+g  )*INCH + k+t+4], H.z, L.z);
        tf32split(w0[(c0+g+8)*INCH + k+t+4], H.w, L.w);
        wh4[i]=H; wl4[i]=L;
    }
    {
        int p = tid>>1, h = tid&1;
        const float* fs = feat + (size_t)(tp+p)*CF + h*32;
        float ch[32];
        #pragma unroll
        for (int q=0;q<8;q++){
            float4 v = *(const float4*)(fs + q*4);
            ch[q*4+0]=v.x; ch[q*4+1]=v.y; ch[q*4+2]=v.z; ch[q*4+3]=v.w;
        }
        #pragma unroll
        for (int ks=0;ks<4;ks++)
            pack_store(inb4 + ((((h*4+ks)<<7)+p)<<2), ch+ks*8);
    }
    __syncthreads();

    constexpr int CT2 = CT/2;
    constexpr int PG2 = 8/CT2;
    constexpr int PW  = 128/PG2;
    constexpr int NT  = PW/8;
    int ln = tid&31, w = tid>>5;
    int g = ln>>2, t = ln&3;
    int ct2 = w%CT2;
    int pb  = (w/CT2)*PW;

    float acc[2][NT][4];
    #pragma unroll
    for (int cc=0;cc<2;cc++)
        #pragma unroll
        for (int nt=0;nt<NT;nt++){ acc[cc][nt][0]=0;acc[cc][nt][1]=0;acc[cc][nt][2]=0;acc[cc][nt][3]=0; }

    for (int ks=0; ks<KS; ks++){
        float4 ah0 = wh4[(ks*CT+ct2*2  )*32+ln];
        float4 al0 = wl4[(ks*CT+ct2*2  )*32+ln];
        float4 ah1 = wh4[(ks*CT+ct2*2+1)*32+ln];
        float4 al1 = wl4[(ks*CT+ct2*2+1)*32+ln];
        #pragma unroll
        for (int nt=0;nt<NT;nt++){
            float4 bb = inb4[((ks<<7) + pb + nt*8 + g)*4 + t];
            mma3(acc[0][nt], ah0, al0, bb);
            mma3(acc[1][nt], ah1, al1, bb);
        }
    }

    #pragma unroll
    for (int cc=0;cc<2;cc++){
        int ch0 = (ct2*2+cc)*16;
        #pragma unroll
        for (int nt=0;nt<NT;nt++){
            int pofs = tp + pb + nt*8 + 2*t;
            size_t base = (size_t)pofs*FS + coff + ch0;
            g_f1[base + g]        = acc[cc][nt][0];
            g_f1[base + FS + g]   = acc[cc][nt][1];
            g_f1[base + g+8]      = acc[cc][nt][2];
            g_f1[base + FS + g+8] = acc[cc][nt][3];
        }
    }
}

// ---------------- histogram: cnt, CS scattered; T,Q block-reduced then slice-spread ----------------
template<int K>
__global__ void hist_kernel(const float* __restrict__ xyz, const float* __restrict__ nxyz, int noff){
    __shared__ float saux[8][9];
    int tid = threadIdx.x, lane = tid&31, wid = tid>>5;
    int gp = blockIdx.x*256 + tid;
    int g  = gp / K;
    int n  = g_nbr[noff+gp];
    int b  = g >> 10;
    int pt = (b<<12) + n;
    float cgx=nxyz[g*3], cgy=nxyz[g*3+1], cgz=nxyz[g*3+2];
    float dx = xyz[pt*3]-cgx, dy = xyz[pt*3+1]-cgy, dz = xyz[pt*3+2]-cgz;
    atomicAdd(&g_cnt[pt], 1);
    atomicAdd(&g_cs[pt*3+0], cgx);
    atomicAdd(&g_cs[pt*3+1], cgy);
    atomicAdd(&g_cs[pt*3+2], cgz);
    float v[9] = {dx,dy,dz, dx*dx,dy*dy,dz*dz, dx*dy,dx*dz,dy*dz};
    #pragma unroll
    for (int q=0;q<9;q++){
        float s=v[q];
        #pragma unroll
        for (int o=16;o;o>>=1) s += __shfl_down_sync(0xffffffffu,s,o);
        v[q]=s;
    }
    if (lane==0){
        #pragma unroll
        for (int q=0;q<9;q++) saux[wid][q]=v[q];
    }
    __syncthreads();
    if (tid < 9){
        float s=0.0f;
        #pragma unroll
        for (int w=0;w<8;w++) s += saux[w][tid];
        atomicAdd(&g_auxp[tid*32], s);     // 9 atomics per block, 128B apart
    }
}

// ---------------- per-channel stats from F1, cnt, R ----------------
template<int C0>
__global__ void chanstat_kernel(const float* __restrict__ xyz, int coff){
    __shared__ float sCnt[256], sRx[256], sRy[256], sRz[256];
    __shared__ float st1[C0], st2[C0], scx[C0], scy[C0], scz[C0];
    int tid = threadIdx.x, n0 = blockIdx.x*256;
    {
        int n = n0 + tid;
        float c = (float)g_cnt[n];
        sCnt[tid] = c;
        sRx[tid] = c*xyz[n*3+0] - g_cs[n*3+0];
        sRy[tid] = c*xyz[n*3+1] - g_cs[n*3+1];
        sRz[tid] = c*xyz[n*3+2] - g_cs[n*3+2];
    }
    if (tid < C0){ st1[tid]=0; st2[tid]=0; scx[tid]=0; scy[tid]=0; scz[tid]=0; }
    __syncthreads();

    constexpr int QN = C0/4, NR = 256/QN;
    int cq = tid % QN, j = tid / QN;
    float a1[4]={0,0,0,0}, a2[4]={0,0,0,0}, ax[4]={0,0,0,0}, ay[4]={0,0,0,0}, az[4]={0,0,0,0};
    for (int jj=j; jj<256; jj+=NR){
        float4 f = *(const float4*)(g_f1 + (size_t)(n0+jj)*FS + coff + cq*4);
        float c = sCnt[jj], Rx = sRx[jj], Ry = sRy[jj], Rz = sRz[jj];
        float fv[4] = {f.x,f.y,f.z,f.w};
        #pragma unroll
        for (int q=0;q<4;q++){
            a1[q] = fmaf(c, fv[q], a1[q]);
            a2[q] = fmaf(c*fv[q], fv[q], a2[q]);
            ax[q] = fmaf(fv[q], Rx, ax[q]);
            ay[q] = fmaf(fv[q], Ry, ay[q]);
            az[q] = fmaf(fv[q], Rz, az[q]);
        }
    }
    #pragma unroll
    for (int q=0;q<4;q++){
        atomicAdd(&st1[cq*4+q], a1[q]);
        atomicAdd(&st2[cq*4+q], a2[q]);
        atomicAdd(&scx[cq*4+q], ax[q]);
        atomicAdd(&scy[cq*4+q], ay[q]);
        atomicAdd(&scz[cq*4+q], az[q]);
    }
    __syncthreads();
    if (tid < C0){
        atomicAdd(&g_s1[tid], st1[tid]);
        atomicAdd(&g_s2[tid], st2[tid]);
        atomicAdd(&g_cr[tid*3+0], scx[tid]);
        atomicAdd(&g_cr[tid*3+1], scy[tid]);
        atomicAdd(&g_cr[tid*3+2], scz[tid]);
    }
}

// ---------------- fold xyz-weight terms into g_stats ----------------
template<int C0>
__global__ void statfinal_kernel(const float* __restrict__ w0){
    int c = threadIdx.x;
    float wx=w0[c*INCH+0], wy=w0[c*INCH+1], wz=w0[c*INCH+2];
    float T0=g_auxp[0*32], T1=g_auxp[1*32], T2=g_auxp[2*32];
    float Qxx=g_auxp[3*32], Qyy=g_auxp[4*32], Qzz=g_auxp[5*32];
    float Qxy=g_auxp[6*32], Qxz=g_auxp[7*32], Qyz=g_auxp[8*32];
    g_stats[c] = g_s1[c] + wx*T0 + wy*T1 + wz*T2;
    float cr = wx*g_cr[c*3+0] + wy*g_cr[c*3+1] + wz*g_cr[c*3+2];
    float qf = wx*wx*Qxx + wy*wy*Qyy + wz*wz*Qzz
             + 2.0f*(wx*wy*Qxy + wx*wz*Qxz + wy*wz*Qyz);
    g_stats[128+c] = g_s2[c] + 2.0f*cr + qf;
}

// ---------------- pass C: on-the-fly x0 -> norm+gelu -> tf32 mma conv1 ----------------
template<int K,int C0,int C1,int PTS,int NTH>
__global__ void __launch_bounds__(NTH)
passC_kernel(const float* __restrict__ w1,
             const float* __restrict__ g0v, const float* __restrict__ b0v,
             const float* __restrict__ w0,
             const float* __restrict__ xyz, const float* __restrict__ nxyz,
             int noff, int coff)
{
    const int P = GRPS*K;
    constexpr int KS = C0/8;
    constexpr int CT = C1/16;
    extern __shared__ float smf[];
    float4* gsb4 = (float4*)smf;
    float4* wh4  = gsb4 + KS*PTS*4;
    float4* wl4  = wh4 + KS*CT*32;
    float*  qa   = (float*)(wl4 + KS*CT*32);
    float*  qb   = qa + C0;
    float*  q0   = qb + C0;
    float*  q1   = q0 + C0;
    float*  q2   = q1 + C0;
    float*  st   = q2 + C0;
    int tid = threadIdx.x, tp = blockIdx.x*PTS;

    if (tid < C0){
        float cnt  = (float)P;
        float mean = g_stats[tid]/cnt;
        float var  = g_stats[128+tid]/cnt - mean*mean;
        float a    = g0v[tid]/sqrtf(var + 1e-5f);
        qa[tid] = a;
        qb[tid] = b0v[tid] - mean*a;
        q0[tid] = a*w0[tid*INCH+0];
        q1[tid] = a*w0[tid*INCH+1];
        q2[tid] = a*w0[tid*INCH+2];
    }
    for (int i=tid;i<KS*CT*32;i+=NTH){
        int ks=i/(CT*32), rem=i-ks*CT*32, ct=rem>>5, ln=rem&31;
        int g=ln>>2, t=ln&3, c0=ct*16, k=ks*8;
        float4 H,L;
        tf32split(w1[(c0+g  )*C0 + k+t  ], H.x, L.x);
        tf32split(w1[(c0+g+8)*C0 + k+t  ], H.y, L.y);
        tf32split(w1[(c0+g  )*C0 + k+t+4], H.z, L.z);
        tf32split(w1[(c0+g+8)*C0 + k+t+4], H.w, L.w);
        wh4[i]=H; wl4[i]=L;
    }
    for (int i=tid;i<2*C1;i+=NTH) st[i]=0.0f;
    __syncthreads();

    {
        int p = tid>>1, h = tid&1;
        int gp = tp + p;
        int g  = gp / K;
        int n  = g_nbr[noff+gp];
        int b  = g >> 10;
        int pt = (b<<12) + n;
        float dx = xyz[pt*3+0]-nxyz[g*3+0];
        float dy = xyz[pt*3+1]-nxyz[g*3+1];
        float dz = xyz[pt*3+2]-nxyz[g*3+2];
        const float* f1 = g_f1 + (size_t)pt*FS + coff;
        #pragma unroll
        for (int ks=h*(KS/2); ks<(h+1)*(KS/2); ks++){
            float4 fa = *(const float4*)(f1 + ks*8);
            float4 fb = *(const float4*)(f1 + ks*8 + 4);
            float4 A0 = *(const float4*)(qa + ks*8), A1 = *(const float4*)(qa + ks*8 + 4);
            float4 B0 = *(const float4*)(qb + ks*8), B1 = *(const float4*)(qb + ks*8 + 4);
            float4 X0 = *(const float4*)(q0 + ks*8), X1 = *(const float4*)(q0 + ks*8 + 4);
            float4 Y0 = *(const float4*)(q1 + ks*8), Y1 = *(const float4*)(q1 + ks*8 + 4);
            float4 Z0 = *(const float4*)(q2 + ks*8), Z1 = *(const float4*)(q2 + ks*8 + 4);
            float ch[8];
            ch[0]=fmaf(X0.x,dx,fmaf(Y0.x,dy,fmaf(Z0.x,dz,fmaf(A0.x,fa.x,B0.x))));
            ch[1]=fmaf(X0.y,dx,fmaf(Y0.y,dy,fmaf(Z0.y,dz,fmaf(A0.y,fa.y,B0.y))));
            ch[2]=fmaf(X0.z,dx,fmaf(Y0.z,dy,fmaf(Z0.z,dz,fmaf(A0.z,fa.z,B0.z))));
            ch[3]=fmaf(X0.w,dx,fmaf(Y0.w,dy,fmaf(Z0.w,dz,fmaf(A0.w,fa.w,B0.w))));
            ch[4]=fmaf(X1.x,dx,fmaf(Y1.x,dy,fmaf(Z1.x,dz,fmaf(A1.x,fb.x,B1.x))));
            ch[5]=fmaf(X1.y,dx,fmaf(Y1.y,dy,fmaf(Z1.y,dz,fmaf(A1.y,fb.y,B1.y))));
            ch[6]=fmaf(X1.z,dx,fmaf(Y1.z,dy,fmaf(Z1.z,dz,fmaf(A1.z,fb.z,B1.z))));
            ch[7]=fmaf(X1.w,dx,fmaf(Y1.w,dy,fmaf(Z1.w,dz,fmaf(A1.w,fb.w,B1.w))));
            #pragma unroll
            for (int j=0;j<8;j++) ch[j] = gelu_exact(ch[j]);
            pack_store(gsb4 + ((ks*PTS+p)<<2), ch);
        }
    }
    __syncthreads();

    constexpr int NW  = NTH/32;
    constexpr int CT2 = CT/2;
    constexpr int PG2 = NW/CT2;
    constexpr int PW  = PTS/PG2;
    constexpr int NT  = PW/8;
    int ln = tid&31, w = tid>>5;
    int g = ln>>2, t = ln&3;
    int ct2 = w%CT2;
    int pb  = (w/CT2)*PW;

    float acc[2][NT][4];
    #pragma unroll
    for (int cc=0;cc<2;cc++)
        #pragma unroll
        for (int nt=0;nt<NT;nt++){ acc[cc][nt][0]=0;acc[cc][nt][1]=0;acc[cc][nt][2]=0;acc[cc][nt][3]=0; }

    for (int ks=0; ks<KS; ks++){
        float4 ah0 = wh4[(ks*CT+ct2*2  )*32+ln];
        float4 al0 = wl4[(ks*CT+ct2*2  )*32+ln];
        float4 ah1 = wh4[(ks*CT+ct2*2+1)*32+ln];
        float4 al1 = wl4[(ks*CT+ct2*2+1)*32+ln];
        #pragma unroll
        for (int nt=0;nt<NT;nt++){
            float4 bb = gsb4[(ks*PTS + pb + nt*8 + g)*4 + t];
            mma3(acc[0][nt], ah0, al0, bb);
            mma3(acc[1][nt], ah1, al1, bb);
        }
    }

    constexpr int NTPG = K/8;
    constexpr int NG   = NT/NTPG;
    int gbase = (tp + pb)/K;
    #pragma unroll
    for (int cc=0;cc<2;cc++){
        int ch0 = (ct2*2+cc)*16;
        float sA=0,sA2=0,sB=0,sB2=0;
        #pragma unroll
        for (int nt=0;nt<NT;nt++){
            float x=acc[cc][nt][0], y=acc[cc][nt][1], z=acc[cc][nt][2], v=acc[cc][nt][3];
            sA += x+y; sA2 += x*x+y*y; sB += z+v; sB2 += z*z+v*v;
        }
        #pragma unroll
        for (int o=1;o<4;o<<=1){
            sA  += __shfl_xor_sync(0xffffffffu,sA,o);
            sA2 += __shfl_xor_sync(0xffffffffu,sA2,o);
            sB  += __shfl_xor_sync(0xffffffffu,sB,o);
            sB2 += __shfl_xor_sync(0xffffffffu,sB2,o);
        }
        if (t==0){
            atomicAdd(&st[ch0+g],      sA);  atomicAdd(&st[C1+ch0+g],   sA2);
            atomicAdd(&st[ch0+g+8],    sB);  atomicAdd(&st[C1+ch0+g+8], sB2);
        }
        #pragma unroll
        for (int gi=0; gi<NG; gi++){
            float mxA=-3.4e38f, mnA=3.4e38f, mxB=-3.4e38f, mnB=3.4e38f;
            #pragma unroll
            for (int u=0; u<NTPG; u++){
                float* a = acc[cc][gi*NTPG+u];
                mxA=fmaxf(mxA,fmaxf(a[0],a[1])); mnA=fminf(mnA,fminf(a[0],a[1]));
                mxB=fmaxf(mxB,fmaxf(a[2],a[3])); mnB=fminf(mnB,fminf(a[2],a[3]));
            }
            #pragma unroll
            for (int o=1;o<4;o<<=1){
                mxA=fmaxf(mxA,__shfl_xor_sync(0xffffffffu,mxA,o));
                mnA=fminf(mnA,__shfl_xor_sync(0xffffffffu,mnA,o));
                mxB=fmaxf(mxB,__shfl_xor_sync(0xffffffffu,mxB,o));
                mnB=fminf(mnB,__shfl_xor_sync(0xffffffffu,mnB,o));
            }
            if (t==0){
                int gg = gbase + gi;
                g_rawmax[(ch0+g)*GRPS   + gg] = mxA;  g_rawmin[(ch0+g)*GRPS   + gg] = mnA;
                g_rawmax[(ch0+g+8)*GRPS + gg] = mxB;  g_rawmin[(ch0+g+8)*GRPS + gg] = mnB;
            }
        }
    }
    __syncthreads();
    for (int i=tid;i<C1;i+=NTH){
        atomicAdd(&g_stats[256+i], st[i]);
        atomicAdd(&g_stats[384+i], st[C1+i]);
    }
}

// ---------------- finalize ----------------
template<int K,int C1>
__global__ void out_kernel(const float* __restrict__ g1v, const float* __restrict__ b1v,
                           float* __restrict__ out, int chOff)
{
    int i = blockIdx.x*blockDim.x + threadIdx.x;
    if (i >= C1*GRPS) return;
    int c = i / GRPS; int g = i - c*GRPS;
    int b = g >> 10, m = g & 1023;
    float cnt  = (float)(GRPS*K);
    float mean = g_stats[256+c]/cnt;
    float var  = g_stats[384+c]/cnt - mean*mean;
    float a    = g1v[c]/sqrtf(var + 1e-5f);
    float bb   = b1v[c] - mean*a;
    float v1   = a*g_rawmax[c*GRPS + g] + bb;
    float v2   = a*g_rawmin[c*GRPS + g] + bb;
    out[XYZ_OUT + ((size_t)b*320 + chOff + c)*MM + m] = fmaxf(gelu_exact(v1), gelu_exact(v2));
}

// ---------------- launch ----------------
extern "C" void kernel_launch(void* const* d_in, const int* in_sizes, int n_in,
                              void* d_out, int out_size)
{
    const float* xyz  = (const float*)d_in[0];
    const float* feat = (const float*)d_in[1];
    const float* w00  = (const float*)d_in[2];
    const float* w01  = (const float*)d_in[3];
    const float* w10  = (const float*)d_in[4];
    const float* w11  = (const float*)d_in[5];
    const float* w20  = (const float*)d_in[6];
    const float* w21  = (const float*)d_in[7];
    const float* g00  = (const float*)d_in[8];
    const float* b00  = (const float*)d_in[9];
    const float* g01  = (const float*)d_in[10];
    const float* b01  = (const float*)d_in[11];
    const float* g10  = (const float*)d_in[12];
    const float* b10  = (const float*)d_in[13];
    const float* g11  = (const float*)d_in[14];
    const float* b11  = (const float*)d_in[15];
    const float* g20  = (const float*)d_in[16];
    const float* b20  = (const float*)d_in[17];
    const float* g21  = (const float*)d_in[18];
    const float* b21  = (const float*)d_in[19];
    float* out = (float*)d_out;
    float* newxyz = out;

    const int smFPS = 3*NN*4;
    const int smBQ  = 3*NN*4;
    const int smD32 = (8*128*4 + 2*8*2*32)*16;
    const int smD64 = (8*128*4 + 2*8*4*32)*16;
    const int smC0  = (4*128*4 + 2*4*4*32)*16 + (5*32 + 2*64)*4;
    const int smC12 = (8*256*4 + 2*8*8*32)*16 + (5*64 + 2*128)*4;

    cudaFuncSetAttribute(fps_kernel,       cudaFuncAttributeMaxDynamicSharedMemorySize, smFPS);
    cudaFuncSetAttribute(ballq_kernel,     cudaFuncAttributeMaxDynamicSharedMemorySize, smBQ);
    cudaFuncSetAttribute(dense_kernel<32>, cudaFuncAttributeMaxDynamicSharedMemorySize, smD32);
    cudaFuncSetAttribute(dense_kernel<64>, cudaFuncAttributeMaxDynamicSharedMemorySize, smD64);
    cudaFuncSetAttribute(passC_kernel<16,32,64,128,256>,  cudaFuncAttributeMaxDynamicSharedMemorySize, smC0);
    cudaFuncSetAttribute(passC_kernel<32,64,128,256,512>, cudaFuncAttributeMaxDynamicSharedMemorySize, smC12);
    cudaFuncSetAttribute(passC_kernel<64,64,128,256,512>, cudaFuncAttributeMaxDynamicSharedMemorySize, smC12);

    fps_kernel<<<BB, 1024, smFPS>>>(xyz, newxyz);
    ballq_kernel<<<GRPS/8, 256, smBQ>>>(xyz, newxyz);

    dense_kernel<32><<<NPT/128, 256, smD32>>>(feat, w00, 0);
    dense_kernel<64><<<NPT/128, 256, smD64>>>(feat, w10, 32);
    dense_kernel<64><<<NPT/128, 256, smD64>>>(feat, w20, 96);

    // ---- scale 0: k=16, C0=32, C1=64
    zero_kernel<<<NPT/256, 256>>>();
    hist_kernel<16><<<GRPS*16/256, 256>>>(xyz, newxyz, 0);
    chanstat_kernel<32><<<NPT/256, 256>>>(xyz, 0);
    statfinal_kernel<32><<<1, 32>>>(w00);
    passC_kernel<16,32,64,128,256><<<GRPS*16/128, 256, smC0>>>(w01, g00, b00, w00, xyz, newxyz, 0, 0);
    out_kernel<16,64><<<(64*GRPS)/256, 256>>>(g01, b01, out, 0);

    // ---- scale 1: k=32, C0=64, C1=128
    zero_kernel<<<NPT/256, 256>>>();
    hist_kernel<32><<<GRPS*32/256, 256>>>(xyz, newxyz, 16*GRPS);
    chanstat_kernel<64><<<NPT/256, 256>>>(xyz, 32);
    statfinal_kernel<64><<<1, 64>>>(w10);
    passC_kernel<32,64,128,256,512><<<GRPS*32/256, 512, smC12>>>(w11, g10, b10, w10, xyz, newxyz, 16*GRPS, 32);
    out_kernel<32,128><<<(128*GRPS)/256, 256>>>(g11, b11, out, 64);

    // ---- scale 2: k=64, C0=64, C1=128
    zero_kernel<<<NPT/256, 256>>>();
    hist_kernel<64><<<GRPS*64/256, 256>>>(xyz, newxyz, 48*GRPS);
    chanstat_kernel<64><<<NPT/256, 256>>>(xyz, 96);
    statfinal_kernel<64><<<1, 64>>>(w20);
    passC_kernel<64,64,128,256,512><<<GRPS*64/256, 512, smC12>>>(w21, g20, b20, w20, xyz, newxyz, 48*GRPS, 96);
    out_kernel<64,128><<<(128*GRPS)/256, 256>>>(g21, b21, out, 192);
}

// round 13
// speedup vs baseline: 1.6766x; 1.2996x over previous
#include <cuda_runtime.h>
#include <math.h>
#include <stdint.h>

#define BB 16
#define NN 4096
#define MM 1024
#define CF 64
#define INCH 67
#define GRPS (BB*MM)
#define NPT (BB*NN)          // 65536 original points
#define FS 160               // g_f1 row stride (32+64+64)
#define XYZ_OUT ((size_t)BB*MM*3)

// ---------------- device scratch ----------------
__device__ int   g_nbr[(16+32+64)*GRPS];
__device__ float g_f1[(size_t)NPT*FS];    // dense conv0 feature part, point-major
__device__ int   g_cnt[NPT];
__device__ float g_cs[NPT*3];             // sum of centroid coords per point
__device__ float g_auxp[9*32];            // T(3) + Q(6), each padded 128B apart (slice-spread)
__device__ float g_s1[128], g_s2[128], g_cr[128*3];
__device__ float g_rawmax[128 * GRPS];
__device__ float g_rawmin[128 * GRPS];
__device__ float g_stats[512];            // [256:384) sum1, [384:512) sumsq1

__device__ __forceinline__ float sqdist_rn(float dx, float dy, float dz){
    return __fadd_rn(__fadd_rn(__fmul_rn(dx,dx),__fmul_rn(dy,dy)),__fmul_rn(dz,dz));
}
__device__ __forceinline__ float gelu_exact(float x){
    return 0.5f * x * (1.0f + erff(x * 0.70710678118654752f));
}
__device__ __forceinline__ void tf32split(float x, float& hi, float& lo){
    uint32_t h; asm("cvt.rna.tf32.f32 %0, %1;" : "=r"(h) : "f"(x));
    hi = __uint_as_float(h);
    float r = x - hi;
    uint32_t l; asm("cvt.rna.tf32.f32 %0, %1;" : "=r"(l) : "f"(r));
    lo = __uint_as_float(l);
}
__device__ __forceinline__ void mma_tf32(float* d,
    uint32_t a0,uint32_t a1,uint32_t a2,uint32_t a3, uint32_t b0,uint32_t b1){
    asm volatile(
        "mma.sync.aligned.m16n8k8.row.col.f32.tf32.tf32.f32 "
        "{%0,%1,%2,%3}, {%4,%5,%6,%7}, {%8,%9}, {%0,%1,%2,%3};"
        : "+f"(d[0]), "+f"(d[1]), "+f"(d[2]), "+f"(d[3])
        : "r"(a0), "r"(a1), "r"(a2), "r"(a3), "r"(b0), "r"(b1));
}
__device__ __forceinline__ void mma3(float* acc, const float4& ah, const float4& al, const float4& bb){
    mma_tf32(acc, __float_as_uint(ah.x),__float_as_uint(ah.y),__float_as_uint(ah.z),__float_as_uint(ah.w),
                  __float_as_uint(bb.x),__float_as_uint(bb.y));
    mma_tf32(acc, __float_as_uint(ah.x),__float_as_uint(ah.y),__float_as_uint(ah.z),__float_as_uint(ah.w),
                  __float_as_uint(bb.z),__float_as_uint(bb.w));
    mma_tf32(acc, __float_as_uint(al.x),__float_as_uint(al.y),__float_as_uint(al.z),__float_as_uint(al.w),
                  __float_as_uint(bb.x),__float_as_uint(bb.y));
}
__device__ __forceinline__ void pack_store(float4* dst, const float* v){
    #pragma unroll
    for (int t=0;t<4;t++){
        float4 fr;
        tf32split(v[t],   fr.x, fr.z);
        tf32split(v[t+4], fr.y, fr.w);
        dst[t]=fr;
    }
}

// ---------------- 1) farthest point sampling (REDUX reductions) ----------------
// dist >= 0 so float bits are order-isomorphic to u32; max-dist/min-index argmax
// becomes redux_max(bits) + redux_min(tied ? idx : INT_MAX).
__global__ void fps_kernel(const float* __restrict__ xyz, float* __restrict__ out_newxyz){
    extern __shared__ float sm[];
    float* sx = sm; float* sy = sm+NN; float* sz = sm+2*NN;
    __shared__ unsigned rv[2][32]; __shared__ int ri[2][32];
    int b = blockIdx.x, t = threadIdx.x, lane = t&31, wid = t>>5;
    for (int i=t;i<NN;i+=blockDim.x){
        const float* p = xyz + ((size_t)b*NN+i)*3;
        sx[i]=p[0]; sy[i]=p[1]; sz[i]=p[2];
    }
    __syncthreads();
    float dreg[4] = {1e10f,1e10f,1e10f,1e10f};
    int far = 0;
    for (int it=0; it<MM; it++){
        float cx=sx[far], cy=sy[far], cz=sz[far];
        if (t==0){
            float* o = out_newxyz + ((size_t)b*MM+it)*3;
            o[0]=cx; o[1]=cy; o[2]=cz;
        }
        float best=-1.0f; int bi=0;
        #pragma unroll
        for (int u=0;u<4;u++){
            int i = t + u*1024;
            float d  = sqdist_rn(sx[i]-cx, sy[i]-cy, sz[i]-cz);
            float nd = fminf(dreg[u], d);
            dreg[u]=nd;
            if (nd>best){ best=nd; bi=i; }   // ascending i: strict > keeps smallest index
        }
        unsigned ub = __float_as_uint(best);               // best >= 0 after u=0
        unsigned m  = __reduce_max_sync(0xffffffffu, ub);
        unsigned ci = (ub==m)? (unsigned)bi : 0x7FFFFFFFu;
        unsigned mi = __reduce_min_sync(0xffffffffu, ci);
        if (lane==0){ rv[it&1][wid]=m; ri[it&1][wid]=(int)mi; }
        __syncthreads();
        unsigned u2 = rv[it&1][lane];
        int      i2 = ri[it&1][lane];
        unsigned m2 = __reduce_max_sync(0xffffffffu, u2);
        unsigned c2 = (u2==m2)? (unsigned)i2 : 0x7FFFFFFFu;
        far = (int)__reduce_min_sync(0xffffffffu, c2);
    }
}

// ---------------- 2) ball query ----------------
__global__ void __launch_bounds__(256)
ballq_kernel(const float* __restrict__ xyz, const float* __restrict__ newxyz){
    extern __shared__ float sm[];
    float* sx = sm; float* sy = sm+NN; float* sz = sm+2*NN;
    int tid = threadIdx.x;
    int gw0 = blockIdx.x*8;
    int b   = gw0 >> 10;
    const float* base = xyz + (size_t)b*NN*3;
    for (int j=tid;j<NN*3;j+=256){
        float v = base[j];
        int idx = j/3, ch = j-idx*3;
        if (ch==0) sx[idx]=v; else if (ch==1) sy[idx]=v; else sz[idx]=v;
    }
    __syncthreads();
    int w    = tid>>5;
    int lane = tid&31;
    int gw   = gw0 + w;
    float cx=newxyz[gw*3+0], cy=newxyz[gw*3+1], cz=newxyz[gw*3+2];
    const float R2_0=(float)(0.1*0.1), R2_1=(float)(0.2*0.2), R2_2=(float)(0.4*0.4);
    int c0=0,c1=0,c2=0, f0=0,f1=0,f2=0;
    int* n0 = g_nbr + gw*16;
    int* n1 = g_nbr + 16*GRPS + gw*32;
    int* n2 = g_nbr + 48*GRPS + gw*64;
    for (int s=0;s<NN;s+=32){
        int i = s + lane;
        float d = sqdist_rn(sx[i]-cx, sy[i]-cy, sz[i]-cz);
        unsigned m0=__ballot_sync(0xffffffffu, d<=R2_0);
        unsigned m1=__ballot_sync(0xffffffffu, d<=R2_1);
        unsigned m2=__ballot_sync(0xffffffffu, d<=R2_2);
        if (m0 && c0<16){
            if (c0==0) f0 = s + __ffs(m0) - 1;
            int r = __popc(m0 & ((1u<<lane)-1u));
            if ((m0>>lane)&1u){ if (c0+r<16) n0[c0+r]=i; }
            c0 += __popc(m0); if (c0>16) c0=16;
        }
        if (m1 && c1<32){
            if (c1==0) f1 = s + __ffs(m1) - 1;
            int r = __popc(m1 & ((1u<<lane)-1u));
            if ((m1>>lane)&1u){ if (c1+r<32) n1[c1+r]=i; }
            c1 += __popc(m1); if (c1>32) c1=32;
        }
        if (m2 && c2<64){
            if (c2==0) f2 = s + __ffs(m2) - 1;
            int r = __popc(m2 & ((1u<<lane)-1u));
            if ((m2>>lane)&1u){ if (c2+r<64) n2[c2+r]=i; }
            c2 += __popc(m2); if (c2>64) c2=64;
        }
        if (c0>=16 && c1>=32 && c2>=64) break;
    }
    for (int j=c0+lane;j<16;j+=32) n0[j]=f0;
    for (int j=c1+lane;j<32;j+=32) n1[j]=f1;
    for (int j=c2+lane;j<64;j+=32) n2[j]=f2;
}

// ---------------- zero per-scale accumulators ----------------
__global__ void zero_kernel(){
    int i = blockIdx.x*256 + threadIdx.x;
    g_cnt[i]=0;
    g_cs[i*3]=0.0f; g_cs[i*3+1]=0.0f; g_cs[i*3+2]=0.0f;
    if (blockIdx.x==0){
        int t=threadIdx.x;
        g_stats[t]=0.0f; g_stats[256+t]=0.0f;
        if (t<128){ g_s1[t]=0.0f; g_s2[t]=0.0f; }
        if (t<9*32) g_auxp[t]=0.0f;
        g_cr[t]=0.0f; if (t<128) g_cr[256+t]=0.0f;
        g_cr[128+t]=0.0f;
    }
}

// ---------------- dense conv0 (feature part only) -> g_f1[pt][coff..] ----------------
template<int C0>
__global__ void __launch_bounds__(256)
dense_kernel(const float* __restrict__ feat, const float* __restrict__ w0, int coff){
    constexpr int KS = 8;
    constexpr int CT = C0/16;
    extern __shared__ float smf[];
    float4* inb4 = (float4*)smf;
    float4* wh4  = inb4 + KS*128*4;
    float4* wl4  = wh4 + KS*CT*32;
    int tid = threadIdx.x;
    int tp  = blockIdx.x*128;

    for (int i=tid;i<KS*CT*32;i+=256){
        int ks=i/(CT*32), rem=i-ks*CT*32, ct=rem>>5, ln=rem&31;
        int g=ln>>2, t=ln&3, c0=ct*16, k=ks*8+3;
        float4 H,L;
        tf32split(w0[(c0+g  )*INCH + k+t  ], H.x, L.x);
        tf32split(w0[(c0+g+8)*INCH + k+t  ], H.y, L.y);
        tf32split(w0[(c0+g  )*INCH + k+t+4], H.z, L.z);
        tf32split(w0[(c0+g+8)*INCH + k+t+4], H.w, L.w);
        wh4[i]=H; wl4[i]=L;
    }
    {
        int p = tid>>1, h = tid&1;
        const float* fs = feat + (size_t)(tp+p)*CF + h*32;
        float ch[32];
        #pragma unroll
        for (int q=0;q<8;q++){
            float4 v = *(const float4*)(fs + q*4);
            ch[q*4+0]=v.x; ch[q*4+1]=v.y; ch[q*4+2]=v.z; ch[q*4+3]=v.w;
        }
        #pragma unroll
        for (int ks=0;ks<4;ks++)
            pack_store(inb4 + ((((h*4+ks)<<7)+p)<<2), ch+ks*8);
    }
    __syncthreads();

    constexpr int CT2 = CT/2;
    constexpr int PG2 = 8/CT2;
    constexpr int PW  = 128/PG2;
    constexpr int NT  = PW/8;
    int ln = tid&31, w = tid>>5;
    int g = ln>>2, t = ln&3;
    int ct2 = w%CT2;
    int pb  = (w/CT2)*PW;

    float acc[2][NT][4];
    #pragma unroll
    for (int cc=0;cc<2;cc++)
        #pragma unroll
        for (int nt=0;nt<NT;nt++){ acc[cc][nt][0]=0;acc[cc][nt][1]=0;acc[cc][nt][2]=0;acc[cc][nt][3]=0; }

    for (int ks=0; ks<KS; ks++){
        float4 ah0 = wh4[(ks*CT+ct2*2  )*32+ln];
        float4 al0 = wl4[(ks*CT+ct2*2  )*32+ln];
        float4 ah1 = wh4[(ks*CT+ct2*2+1)*32+ln];
        float4 al1 = wl4[(ks*CT+ct2*2+1)*32+ln];
        #pragma unroll
        for (int nt=0;nt<NT;nt++){
            float4 bb = inb4[((ks<<7) + pb + nt*8 + g)*4 + t];
            mma3(acc[0][nt], ah0, al0, bb);
            mma3(acc[1][nt], ah1, al1, bb);
        }
    }

    #pragma unroll
    for (int cc=0;cc<2;cc++){
        int ch0 = (ct2*2+cc)*16;
        #pragma unroll
        for (int nt=0;nt<NT;nt++){
            int pofs = tp + pb + nt*8 + 2*t;
            size_t base = (size_t)pofs*FS + coff + ch0;
            g_f1[base + g]        = acc[cc][nt][0];
            g_f1[base + FS + g]   = acc[cc][nt][1];
            g_f1[base + g+8]      = acc[cc][nt][2];
            g_f1[base + FS + g+8] = acc[cc][nt][3];
        }
    }
}

// ---------------- histogram: cnt, CS scattered; T,Q block-reduced then slice-spread ----------------
template<int K>
__global__ void hist_kernel(const float* __restrict__ xyz, const float* __restrict__ nxyz, int noff){
    __shared__ float saux[8][9];
    int tid = threadIdx.x, lane = tid&31, wid = tid>>5;
    int gp = blockIdx.x*256 + tid;
    int g  = gp / K;
    int n  = g_nbr[noff+gp];
    int b  = g >> 10;
    int pt = (b<<12) + n;
    float cgx=nxyz[g*3], cgy=nxyz[g*3+1], cgz=nxyz[g*3+2];
    float dx = xyz[pt*3]-cgx, dy = xyz[pt*3+1]-cgy, dz = xyz[pt*3+2]-cgz;
    atomicAdd(&g_cnt[pt], 1);
    atomicAdd(&g_cs[pt*3+0], cgx);
    atomicAdd(&g_cs[pt*3+1], cgy);
    atomicAdd(&g_cs[pt*3+2], cgz);
    float v[9] = {dx,dy,dz, dx*dx,dy*dy,dz*dz, dx*dy,dx*dz,dy*dz};
    #pragma unroll
    for (int q=0;q<9;q++){
        float s=v[q];
        #pragma unroll
        for (int o=16;o;o>>=1) s += __shfl_down_sync(0xffffffffu,s,o);
        v[q]=s;
    }
    if (lane==0){
        #pragma unroll
        for (int q=0;q<9;q++) saux[wid][q]=v[q];
    }
    __syncthreads();
    if (tid < 9){
        float s=0.0f;
        #pragma unroll
        for (int w=0;w<8;w++) s += saux[w][tid];
        atomicAdd(&g_auxp[tid*32], s);     // 9 atomics per block, 128B apart
    }
}

// ---------------- per-channel stats from F1, cnt, R ----------------
template<int C0>
__global__ void chanstat_kernel(const float* __restrict__ xyz, int coff){
    __shared__ float sCnt[256], sRx[256], sRy[256], sRz[256];
    __shared__ float st1[C0], st2[C0], scx[C0], scy[C0], scz[C0];
    int tid = threadIdx.x, n0 = blockIdx.x*256;
    {
        int n = n0 + tid;
        float c = (float)g_cnt[n];
        sCnt[tid] = c;
        sRx[tid] = c*xyz[n*3+0] - g_cs[n*3+0];
        sRy[tid] = c*xyz[n*3+1] - g_cs[n*3+1];
        sRz[tid] = c*xyz[n*3+2] - g_cs[n*3+2];
    }
    if (tid < C0){ st1[tid]=0; st2[tid]=0; scx[tid]=0; scy[tid]=0; scz[tid]=0; }
    __syncthreads();

    constexpr int QN = C0/4, NR = 256/QN;
    int cq = tid % QN, j = tid / QN;
    float a1[4]={0,0,0,0}, a2[4]={0,0,0,0}, ax[4]={0,0,0,0}, ay[4]={0,0,0,0}, az[4]={0,0,0,0};
    for (int jj=j; jj<256; jj+=NR){
        float4 f = *(const float4*)(g_f1 + (size_t)(n0+jj)*FS + coff + cq*4);
        float c = sCnt[jj], Rx = sRx[jj], Ry = sRy[jj], Rz = sRz[jj];
        float fv[4] = {f.x,f.y,f.z,f.w};
        #pragma unroll
        for (int q=0;q<4;q++){
            a1[q] = fmaf(c, fv[q], a1[q]);
            a2[q] = fmaf(c*fv[q], fv[q], a2[q]);
            ax[q] = fmaf(fv[q], Rx, ax[q]);
            ay[q] = fmaf(fv[q], Ry, ay[q]);
            az[q] = fmaf(fv[q], Rz, az[q]);
        }
    }
    #pragma unroll
    for (int q=0;q<4;q++){
        atomicAdd(&st1[cq*4+q], a1[q]);
        atomicAdd(&st2[cq*4+q], a2[q]);
        atomicAdd(&scx[cq*4+q], ax[q]);
        atomicAdd(&scy[cq*4+q], ay[q]);
        atomicAdd(&scz[cq*4+q], az[q]);
    }
    __syncthreads();
    if (tid < C0){
        atomicAdd(&g_s1[tid], st1[tid]);
        atomicAdd(&g_s2[tid], st2[tid]);
        atomicAdd(&g_cr[tid*3+0], scx[tid]);
        atomicAdd(&g_cr[tid*3+1], scy[tid]);
        atomicAdd(&g_cr[tid*3+2], scz[tid]);
    }
}

// ---------------- pass C: stats0 finalize + on-the-fly x0 -> norm+gelu -> tf32 mma conv1 ----------------
template<int K,int C0,int C1,int PTS,int NTH>
__global__ void __launch_bounds__(NTH)
passC_kernel(const float* __restrict__ w1,
             const float* __restrict__ g0v, const float* __restrict__ b0v,
             const float* __restrict__ w0,
             const float* __restrict__ xyz, const float* __restrict__ nxyz,
             int noff, int coff)
{
    const int P = GRPS*K;
    constexpr int KS = C0/8;
    constexpr int CT = C1/16;
    extern __shared__ float smf[];
    float4* gsb4 = (float4*)smf;
    float4* wh4  = gsb4 + KS*PTS*4;
    float4* wl4  = wh4 + KS*CT*32;
    float*  qa   = (float*)(wl4 + KS*CT*32);
    float*  qb   = qa + C0;
    float*  q0   = qb + C0;
    float*  q1   = q0 + C0;
    float*  q2   = q1 + C0;
    float*  st   = q2 + C0;
    int tid = threadIdx.x, tp = blockIdx.x*PTS;

    if (tid < C0){
        // statfinal folded in: identical fp op order to the old statfinal_kernel
        float wx=w0[tid*INCH+0], wy=w0[tid*INCH+1], wz=w0[tid*INCH+2];
        float T0=g_auxp[0*32], T1=g_auxp[1*32], T2=g_auxp[2*32];
        float Qxx=g_auxp[3*32], Qyy=g_auxp[4*32], Qzz=g_auxp[5*32];
        float Qxy=g_auxp[6*32], Qxz=g_auxp[7*32], Qyz=g_auxp[8*32];
        float sum = g_s1[tid] + wx*T0 + wy*T1 + wz*T2;
        float cr  = wx*g_cr[tid*3+0] + wy*g_cr[tid*3+1] + wz*g_cr[tid*3+2];
        float qf  = wx*wx*Qxx + wy*wy*Qyy + wz*wz*Qzz
                  + 2.0f*(wx*wy*Qxy + wx*wz*Qxz + wy*wz*Qyz);
        float sumsq = g_s2[tid] + 2.0f*cr + qf;
        float cnt  = (float)P;
        float mean = sum/cnt;
        float var  = sumsq/cnt - mean*mean;
        float a    = g0v[tid]/sqrtf(var + 1e-5f);
        qa[tid] = a;
        qb[tid] = b0v[tid] - mean*a;
        q0[tid] = a*wx;
        q1[tid] = a*wy;
        q2[tid] = a*wz;
    }
    for (int i=tid;i<KS*CT*32;i+=NTH){
        int ks=i/(CT*32), rem=i-ks*CT*32, ct=rem>>5, ln=rem&31;
        int g=ln>>2, t=ln&3, c0=ct*16, k=ks*8;
        float4 H,L;
        tf32split(w1[(c0+g  )*C0 + k+t  ], H.x, L.x);
        tf32split(w1[(c0+g+8)*C0 + k+t  ], H.y, L.y);
        tf32split(w1[(c0+g  )*C0 + k+t+4], H.z, L.z);
        tf32split(w1[(c0+g+8)*C0 + k+t+4], H.w, L.w);
        wh4[i]=H; wl4[i]=L;
    }
    for (int i=tid;i<2*C1;i+=NTH) st[i]=0.0f;
    __syncthreads();

    {
        int p = tid>>1, h = tid&1;
        int gp = tp + p;
        int g  = gp / K;
        int n  = g_nbr[noff+gp];
        int b  = g >> 10;
        int pt = (b<<12) + n;
        float dx = xyz[pt*3+0]-nxyz[g*3+0];
        float dy = xyz[pt*3+1]-nxyz[g*3+1];
        float dz = xyz[pt*3+2]-nxyz[g*3+2];
        const float* f1 = g_f1 + (size_t)pt*FS + coff;
        #pragma unroll
        for (int ks=h*(KS/2); ks<(h+1)*(KS/2); ks++){
            float4 fa = *(const float4*)(f1 + ks*8);
            float4 fb = *(const float4*)(f1 + ks*8 + 4);
            float4 A0 = *(const float4*)(qa + ks*8), A1 = *(const float4*)(qa + ks*8 + 4);
            float4 B0 = *(const float4*)(qb + ks*8), B1 = *(const float4*)(qb + ks*8 + 4);
            float4 X0 = *(const float4*)(q0 + ks*8), X1 = *(const float4*)(q0 + ks*8 + 4);
            float4 Y0 = *(const float4*)(q1 + ks*8), Y1 = *(const float4*)(q1 + ks*8 + 4);
            float4 Z0 = *(const float4*)(q2 + ks*8), Z1 = *(const float4*)(q2 + ks*8 + 4);
            float ch[8];
            ch[0]=fmaf(X0.x,dx,fmaf(Y0.x,dy,fmaf(Z0.x,dz,fmaf(A0.x,fa.x,B0.x))));
            ch[1]=fmaf(X0.y,dx,fmaf(Y0.y,dy,fmaf(Z0.y,dz,fmaf(A0.y,fa.y,B0.y))));
            ch[2]=fmaf(X0.z,dx,fmaf(Y0.z,dy,fmaf(Z0.z,dz,fmaf(A0.z,fa.z,B0.z))));
            ch[3]=fmaf(X0.w,dx,fmaf(Y0.w,dy,fmaf(Z0.w,dz,fmaf(A0.w,fa.w,B0.w))));
            ch[4]=fmaf(X1.x,dx,fmaf(Y1.x,dy,fmaf(Z1.x,dz,fmaf(A1.x,fb.x,B1.x))));
            ch[5]=fmaf(X1.y,dx,fmaf(Y1.y,dy,fmaf(Z1.y,dz,fmaf(A1.y,fb.y,B1.y))));
            ch[6]=fmaf(X1.z,dx,fmaf(Y1.z,dy,fmaf(Z1.z,dz,fmaf(A1.z,fb.z,B1.z))));
            ch[7]=fmaf(X1.w,dx,fmaf(Y1.w,dy,fmaf(Z1.w,dz,fmaf(A1.w,fb.w,B1.w))));
            #pragma unroll
            for (int j=0;j<8;j++) ch[j] = gelu_exact(ch[j]);
            pack_store(gsb4 + ((ks*PTS+p)<<2), ch);
        }
    }
    __syncthreads();

    constexpr int NW  = NTH/32;
    constexpr int CT2 = CT/2;
    constexpr int PG2 = NW/CT2;
    constexpr int PW  = PTS/PG2;
    constexpr int NT  = PW/8;
    int ln = tid&31, w = tid>>5;
    int g = ln>>2, t = ln&3;
    int ct2 = w%CT2;
    int pb  = (w/CT2)*PW;

    float acc[2][NT][4];
    #pragma unroll
    for (int cc=0;cc<2;cc++)
        #pragma unroll
        for (int nt=0;nt<NT;nt++){ acc[cc][nt][0]=0;acc[cc][nt][1]=0;acc[cc][nt][2]=0;acc[cc][nt][3]=0; }

    for (int ks=0; ks<KS; ks++){
        float4 ah0 = wh4[(ks*CT+ct2*2  )*32+ln];
        float4 al0 = wl4[(ks*CT+ct2*2  )*32+ln];
        float4 ah1 = wh4[(ks*CT+ct2*2+1)*32+ln];
        float4 al1 = wl4[(ks*CT+ct2*2+1)*32+ln];
        #pragma unroll
        for (int nt=0;nt<NT;nt++){
            float4 bb = gsb4[(ks*PTS + pb + nt*8 + g)*4 + t];
            mma3(acc[0][nt], ah0, al0, bb);
            mma3(acc[1][nt], ah1, al1, bb);
        }
    }

    constexpr int NTPG = K/8;
    constexpr int NG   = NT/NTPG;
    int gbase = (tp + pb)/K;
    #pragma unroll
    for (int cc=0;cc<2;cc++){
        int ch0 = (ct2*2+cc)*16;
        float sA=0,sA2=0,sB=0,sB2=0;
        #pragma unroll
        for (int nt=0;nt<NT;nt++){
            float x=acc[cc][nt][0], y=acc[cc][nt][1], z=acc[cc][nt][2], v=acc[cc][nt][3];
            sA += x+y; sA2 += x*x+y*y; sB += z+v; sB2 += z*z+v*v;
        }
        #pragma unroll
        for (int o=1;o<4;o<<=1){
            sA  += __shfl_xor_sync(0xffffffffu,sA,o);
            sA2 += __shfl_xor_sync(0xffffffffu,sA2,o);
            sB  += __shfl_xor_sync(0xffffffffu,sB,o);
            sB2 += __shfl_xor_sync(0xffffffffu,sB2,o);
        }
        if (t==0){
            atomicAdd(&st[ch0+g],      sA);  atomicAdd(&st[C1+ch0+g],   sA2);
            atomicAdd(&st[ch0+g+8],    sB);  atomicAdd(&st[C1+ch0+g+8], sB2);
        }
        #pragma unroll
        for (int gi=0; gi<NG; gi++){
            float mxA=-3.4e38f, mnA=3.4e38f, mxB=-3.4e38f, mnB=3.4e38f;
            #pragma unroll
            for (int u=0; u<NTPG; u++){
                float* a = acc[cc][gi*NTPG+u];
                mxA=fmaxf(mxA,fmaxf(a[0],a[1])); mnA=fminf(mnA,fminf(a[0],a[1]));
                mxB=fmaxf(mxB,fmaxf(a[2],a[3])); mnB=fminf(mnB,fminf(a[2],a[3]));
            }
            #pragma unroll
            for (int o=1;o<4;o<<=1){
                mxA=fmaxf(mxA,__shfl_xor_sync(0xffffffffu,mxA,o));
                mnA=fminf(mnA,__shfl_xor_sync(0xffffffffu,mnA,o));
                mxB=fmaxf(mxB,__shfl_xor_sync(0xffffffffu,mxB,o));
                mnB=fminf(mnB,__shfl_xor_sync(0xffffffffu,mnB,o));
            }
            if (t==0){
                int gg = gbase + gi;
                g_rawmax[(ch0+g)*GRPS   + gg] = mxA;  g_rawmin[(ch0+g)*GRPS   + gg] = mnA;
                g_rawmax[(ch0+g+8)*GRPS + gg] = mxB;  g_rawmin[(ch0+g+8)*GRPS + gg] = mnB;
            }
        }
    }
    __syncthreads();
    for (int i=tid;i<C1;i+=NTH){
        atomicAdd(&g_stats[256+i], st[i]);
        atomicAdd(&g_stats[384+i], st[C1+i]);
    }
}

// ---------------- finalize ----------------
template<int K,int C1>
__global__ void out_kernel(const float* __restrict__ g1v, const float* __restrict__ b1v,
                           float* __restrict__ out, int chOff)
{
    int i = blockIdx.x*blockDim.x + threadIdx.x;
    if (i >= C1*GRPS) return;
    int c = i / GRPS; int g = i - c*GRPS;
    int b = g >> 10, m = g & 1023;
    float cnt  = (float)(GRPS*K);
    float mean = g_stats[256+c]/cnt;
    float var  = g_stats[384+c]/cnt - mean*mean;
    float a    = g1v[c]/sqrtf(var + 1e-5f);
    float bb   = b1v[c] - mean*a;
    float v1   = a*g_rawmax[c*GRPS + g] + bb;
    float v2   = a*g_rawmin[c*GRPS + g] + bb;
    out[XYZ_OUT + ((size_t)b*320 + chOff + c)*MM + m] = fmaxf(gelu_exact(v1), gelu_exact(v2));
}

// ---------------- launch ----------------
extern "C" void kernel_launch(void* const* d_in, const int* in_sizes, int n_in,
                              void* d_out, int out_size)
{
    const float* xyz  = (const float*)d_in[0];
    const float* feat = (const float*)d_in[1];
    const float* w00  = (const float*)d_in[2];
    const float* w01  = (const float*)d_in[3];
    const float* w10  = (const float*)d_in[4];
    const float* w11  = (const float*)d_in[5];
    const float* w20  = (const float*)d_in[6];
    const float* w21  = (const float*)d_in[7];
    const float* g00  = (const float*)d_in[8];
    const float* b00  = (const float*)d_in[9];
    const float* g01  = (const float*)d_in[10];
    const float* b01  = (const float*)d_in[11];
    const float* g10  = (const float*)d_in[12];
    const float* b10  = (const float*)d_in[13];
    const float* g11  = (const float*)d_in[14];
    const float* b11  = (const float*)d_in[15];
    const float* g20  = (const float*)d_in[16];
    const float* b20  = (const float*)d_in[17];
    const float* g21  = (const float*)d_in[18];
    const float* b21  = (const float*)d_in[19];
    float* out = (float*)d_out;
    float* newxyz = out;

    const int smFPS = 3*NN*4;
    const int smBQ  = 3*NN*4;
    const int smD32 = (8*128*4 + 2*8*2*32)*16;
    const int smD64 = (8*128*4 + 2*8*4*32)*16;
    const int smC0  = (4*128*4 + 2*4*4*32)*16 + (5*32 + 2*64)*4;
    const int smC12 = (8*256*4 + 2*8*8*32)*16 + (5*64 + 2*128)*4;

    cudaFuncSetAttribute(fps_kernel,       cudaFuncAttributeMaxDynamicSharedMemorySize, smFPS);
    cudaFuncSetAttribute(ballq_kernel,     cudaFuncAttributeMaxDynamicSharedMemorySize, smBQ);
    cudaFuncSetAttribute(dense_kernel<32>, cudaFuncAttributeMaxDynamicSharedMemorySize, smD32);
    cudaFuncSetAttribute(dense_kernel<64>, cudaFuncAttributeMaxDynamicSharedMemorySize, smD64);
    cudaFuncSetAttribute(passC_kernel<16,32,64,128,256>,  cudaFuncAttributeMaxDynamicSharedMemorySize, smC0);
    cudaFuncSetAttribute(passC_kernel<32,64,128,256,512>, cudaFuncAttributeMaxDynamicSharedMemorySize, smC12);
    cudaFuncSetAttribute(passC_kernel<64,64,128,256,512>, cudaFuncAttributeMaxDynamicSharedMemorySize, smC12);

    fps_kernel<<<BB, 1024, smFPS>>>(xyz, newxyz);
    ballq_kernel<<<GRPS/8, 256, smBQ>>>(xyz, newxyz);

    dense_kernel<32><<<NPT/128, 256, smD32>>>(feat, w00, 0);
    dense_kernel<64><<<NPT/128, 256, smD64>>>(feat, w10, 32);
    dense_kernel<64><<<NPT/128, 256, smD64>>>(feat, w20, 96);

    // ---- scale 0: k=16, C0=32, C1=64
    zero_kernel<<<NPT/256, 256>>>();
    hist_kernel<16><<<GRPS*16/256, 256>>>(xyz, newxyz, 0);
    chanstat_kernel<32><<<NPT/256, 256>>>(xyz, 0);
    passC_kernel<16,32,64,128,256><<<GRPS*16/128, 256, smC0>>>(w01, g00, b00, w00, xyz, newxyz, 0, 0);
    out_kernel<16,64><<<(64*GRPS)/256, 256>>>(g01, b01, out, 0);

    // ---- scale 1: k=32, C0=64, C1=128
    zero_kernel<<<NPT/256, 256>>>();
    hist_kernel<32><<<GRPS*32/256, 256>>>(xyz, newxyz, 16*GRPS);
    chanstat_kernel<64><<<NPT/256, 256>>>(xyz, 32);
    passC_kernel<32,64,128,256,512><<<GRPS*32/256, 512, smC12>>>(w11, g10, b10, w10, xyz, newxyz, 16*GRPS, 32);
    out_kernel<32,128><<<(128*GRPS)/256, 256>>>(g11, b11, out, 64);

    // ---- scale 2: k=64, C0=64, C1=128
    zero_kernel<<<NPT/256, 256>>>();
    hist_kernel<64><<<GRPS*64/256, 256>>>(xyz, newxyz, 48*GRPS);
    chanstat_kernel<64><<<NPT/256, 256>>>(xyz, 96);
    passC_kernel<64,64,128,256,512><<<GRPS*64/256, 512, smC12>>>(w21, g20, b20, w20, xyz, newxyz, 48*GRPS, 96);
    out_kernel<64,128><<<(128*GRPS)/256, 256>>>(g21, b21, out, 192);
}

// round 14
// speedup vs baseline: 1.8715x; 1.1162x over previous
#include <cuda_runtime.h>
#include <math.h>
#include <stdint.h>

#define BB 16
#define NN 4096
#define MM 1024
#define CF 64
#define INCH 67
#define GRPS (BB*MM)
#define NPT (BB*NN)          // 65536 original points
#define FS 160               // g_f1 row stride (32+64+64)
#define XYZ_OUT ((size_t)BB*MM*3)

// weight-fragment segment offsets (float4 units)
#define OFF_D0 0
#define OFF_D1 512
#define OFF_D2 1536
#define OFF_C0 2560
#define OFF_C1 3072
#define OFF_C2 5120
#define WF_TOT 7168

// ---------------- device scratch ----------------
__device__ int    g_nbr[(16+32+64)*GRPS];
__device__ float  g_f1[(size_t)NPT*FS];
__device__ float4 g_wfh[WF_TOT], g_wfl[WF_TOT];     // fragment-packed weights hi/lo
__device__ int    g_cnt3[3*NPT];
__device__ float  g_cs3[3*NPT*3];
__device__ float  g_auxp3[3*9*32];                  // per-scale T/Q, 128B-spread
__device__ float  g_s13[3*128], g_s23[3*128], g_cr3[3*384];
__device__ float  g_rawmax[128 * GRPS];
__device__ float  g_rawmin[128 * GRPS];
__device__ float  g_stats1[3*256];                  // per-scale layer1 sum/sumsq

__device__ __forceinline__ float sqdist_rn(float dx, float dy, float dz){
    return __fadd_rn(__fadd_rn(__fmul_rn(dx,dx),__fmul_rn(dy,dy)),__fmul_rn(dz,dz));
}
__device__ __forceinline__ float gelu_exact(float x){
    return 0.5f * x * (1.0f + erff(x * 0.70710678118654752f));
}
__device__ __forceinline__ void tf32split(float x, float& hi, float& lo){
    uint32_t h; asm("cvt.rna.tf32.f32 %0, %1;" : "=r"(h) : "f"(x));
    hi = __uint_as_float(h);
    float r = x - hi;
    uint32_t l; asm("cvt.rna.tf32.f32 %0, %1;" : "=r"(l) : "f"(r));
    lo = __uint_as_float(l);
}
__device__ __forceinline__ void mma_tf32(float* d,
    uint32_t a0,uint32_t a1,uint32_t a2,uint32_t a3, uint32_t b0,uint32_t b1){
    asm volatile(
        "mma.sync.aligned.m16n8k8.row.col.f32.tf32.tf32.f32 "
        "{%0,%1,%2,%3}, {%4,%5,%6,%7}, {%8,%9}, {%0,%1,%2,%3};"
        : "+f"(d[0]), "+f"(d[1]), "+f"(d[2]), "+f"(d[3])
        : "r"(a0), "r"(a1), "r"(a2), "r"(a3), "r"(b0), "r"(b1));
}
__device__ __forceinline__ void mma3(float* acc, const float4& ah, const float4& al, const float4& bb){
    mma_tf32(acc, __float_as_uint(ah.x),__float_as_uint(ah.y),__float_as_uint(ah.z),__float_as_uint(ah.w),
                  __float_as_uint(bb.x),__float_as_uint(bb.y));
    mma_tf32(acc, __float_as_uint(ah.x),__float_as_uint(ah.y),__float_as_uint(ah.z),__float_as_uint(ah.w),
                  __float_as_uint(bb.z),__float_as_uint(bb.w));
    mma_tf32(acc, __float_as_uint(al.x),__float_as_uint(al.y),__float_as_uint(al.z),__float_as_uint(al.w),
                  __float_as_uint(bb.x),__float_as_uint(bb.y));
}
__device__ __forceinline__ void pack_store(float4* dst, const float* v){
    #pragma unroll
    for (int t=0;t<4;t++){
        float4 fr;
        tf32split(v[t],   fr.x, fr.z);
        tf32split(v[t+4], fr.y, fr.w);
        dst[t]=fr;
    }
}

// ---------------- 0) weight fragment prep ----------------
__global__ void prep_kernel(const float* __restrict__ w00, const float* __restrict__ w10,
                            const float* __restrict__ w20, const float* __restrict__ w01,
                            const float* __restrict__ w11, const float* __restrict__ w21){
    int i = blockIdx.x*256 + threadIdx.x;
    if (i >= WF_TOT) return;
    const float* w; int base, CT, ld, k0;
    if      (i < OFF_D1){ w=w00; base=OFF_D0; CT=2; ld=INCH; k0=3; }
    else if (i < OFF_D2){ w=w10; base=OFF_D1; CT=4; ld=INCH; k0=3; }
    else if (i < OFF_C0){ w=w20; base=OFF_D2; CT=4; ld=INCH; k0=3; }
    else if (i < OFF_C1){ w=w01; base=OFF_C0; CT=4; ld=32;   k0=0; }
    else if (i < OFF_C2){ w=w11; base=OFF_C1; CT=8; ld=64;   k0=0; }
    else               { w=w21; base=OFF_C2; CT=8; ld=64;   k0=0; }
    int rem = i - base;
    int ks = rem/(CT*32), r2 = rem - ks*CT*32, ct = r2>>5, ln = r2&31;
    int g = ln>>2, t = ln&3, c0 = ct*16, k = ks*8 + k0;
    float4 H,L;
    tf32split(w[(c0+g  )*ld + k+t  ], H.x, L.x);
    tf32split(w[(c0+g+8)*ld + k+t  ], H.y, L.y);
    tf32split(w[(c0+g  )*ld + k+t+4], H.z, L.z);
    tf32split(w[(c0+g+8)*ld + k+t+4], H.w, L.w);
    g_wfh[i]=H; g_wfl[i]=L;
}

// ---------------- 1) farthest point sampling (REDUX) ----------------
__global__ void fps_kernel(const float* __restrict__ xyz, float* __restrict__ out_newxyz){
    extern __shared__ float sm[];
    float* sx = sm; float* sy = sm+NN; float* sz = sm+2*NN;
    __shared__ unsigned rv[2][32]; __shared__ int ri[2][32];
    int b = blockIdx.x, t = threadIdx.x, lane = t&31, wid = t>>5;
    for (int i=t;i<NN;i+=blockDim.x){
        const float* p = xyz + ((size_t)b*NN+i)*3;
        sx[i]=p[0]; sy[i]=p[1]; sz[i]=p[2];
    }
    __syncthreads();
    float dreg[4] = {1e10f,1e10f,1e10f,1e10f};
    int far = 0;
    for (int it=0; it<MM; it++){
        float cx=sx[far], cy=sy[far], cz=sz[far];
        if (t==0){
            float* o = out_newxyz + ((size_t)b*MM+it)*3;
            o[0]=cx; o[1]=cy; o[2]=cz;
        }
        float best=-1.0f; int bi=0;
        #pragma unroll
        for (int u=0;u<4;u++){
            int i = t + u*1024;
            float d  = sqdist_rn(sx[i]-cx, sy[i]-cy, sz[i]-cz);
            float nd = fminf(dreg[u], d);
            dreg[u]=nd;
            if (nd>best){ best=nd; bi=i; }
        }
        unsigned ub = __float_as_uint(best);
        unsigned m  = __reduce_max_sync(0xffffffffu, ub);
        unsigned ci = (ub==m)? (unsigned)bi : 0x7FFFFFFFu;
        unsigned mi = __reduce_min_sync(0xffffffffu, ci);
        if (lane==0){ rv[it&1][wid]=m; ri[it&1][wid]=(int)mi; }
        __syncthreads();
        unsigned u2 = rv[it&1][lane];
        int      i2 = ri[it&1][lane];
        unsigned m2 = __reduce_max_sync(0xffffffffu, u2);
        unsigned c2 = (u2==m2)? (unsigned)i2 : 0x7FFFFFFFu;
        far = (int)__reduce_min_sync(0xffffffffu, c2);
    }
}

// ---------------- 2) ball query ----------------
__global__ void __launch_bounds__(256)
ballq_kernel(const float* __restrict__ xyz, const float* __restrict__ newxyz){
    extern __shared__ float sm[];
    float* sx = sm; float* sy = sm+NN; float* sz = sm+2*NN;
    int tid = threadIdx.x;
    int gw0 = blockIdx.x*8;
    int b   = gw0 >> 10;
    const float* base = xyz + (size_t)b*NN*3;
    for (int j=tid;j<NN*3;j+=256){
        float v = base[j];
        int idx = j/3, ch = j-idx*3;
        if (ch==0) sx[idx]=v; else if (ch==1) sy[idx]=v; else sz[idx]=v;
    }
    __syncthreads();
    int w    = tid>>5;
    int lane = tid&31;
    int gw   = gw0 + w;
    float cx=newxyz[gw*3+0], cy=newxyz[gw*3+1], cz=newxyz[gw*3+2];
    const float R2_0=(float)(0.1*0.1), R2_1=(float)(0.2*0.2), R2_2=(float)(0.4*0.4);
    int c0=0,c1=0,c2=0, f0=0,f1=0,f2=0;
    int* n0 = g_nbr + gw*16;
    int* n1 = g_nbr + 16*GRPS + gw*32;
    int* n2 = g_nbr + 48*GRPS + gw*64;
    for (int s=0;s<NN;s+=32){
        int i = s + lane;
        float d = sqdist_rn(sx[i]-cx, sy[i]-cy, sz[i]-cz);
        unsigned m0=__ballot_sync(0xffffffffu, d<=R2_0);
        unsigned m1=__ballot_sync(0xffffffffu, d<=R2_1);
        unsigned m2=__ballot_sync(0xffffffffu, d<=R2_2);
        if (m0 && c0<16){
            if (c0==0) f0 = s + __ffs(m0) - 1;
            int r = __popc(m0 & ((1u<<lane)-1u));
            if ((m0>>lane)&1u){ if (c0+r<16) n0[c0+r]=i; }
            c0 += __popc(m0); if (c0>16) c0=16;
        }
        if (m1 && c1<32){
            if (c1==0) f1 = s + __ffs(m1) - 1;
            int r = __popc(m1 & ((1u<<lane)-1u));
            if ((m1>>lane)&1u){ if (c1+r<32) n1[c1+r]=i; }
            c1 += __popc(m1); if (c1>32) c1=32;
        }
        if (m2 && c2<64){
            if (c2==0) f2 = s + __ffs(m2) - 1;
            int r = __popc(m2 & ((1u<<lane)-1u));
            if ((m2>>lane)&1u){ if (c2+r<64) n2[c2+r]=i; }
            c2 += __popc(m2); if (c2>64) c2=64;
        }
        if (c0>=16 && c1>=32 && c2>=64) break;
    }
    for (int j=c0+lane;j<16;j+=32) n0[j]=f0;
    for (int j=c1+lane;j<32;j+=32) n1[j]=f1;
    for (int j=c2+lane;j<64;j+=32) n2[j]=f2;
}

// ---------------- zero ALL per-scale accumulators ----------------
__global__ void zero_all_kernel(){
    int i = blockIdx.x*256 + threadIdx.x;     // grid covers 3*NPT
    if (i < 3*NPT){
        g_cnt3[i]=0;
        g_cs3[i*3]=0.0f; g_cs3[i*3+1]=0.0f; g_cs3[i*3+2]=0.0f;
    }
    if (i < 3*9*32) g_auxp3[i]=0.0f;
    if (i < 3*128){ g_s13[i]=0.0f; g_s23[i]=0.0f; }
    if (i < 3*384) g_cr3[i]=0.0f;
    if (i < 3*256) g_stats1[i]=0.0f;
}

// ---------------- dense conv0 (weights from gmem fragments) ----------------
template<int C0>
__global__ void __launch_bounds__(256,2)
dense_kernel(const float* __restrict__ feat, int wofs, int coff){
    constexpr int KS = 8;
    constexpr int CT = C0/16;
    extern __shared__ float smf[];
    float4* inb4 = (float4*)smf;         // KS*128*4 = 64KB
    int tid = threadIdx.x;
    int tp  = blockIdx.x*128;

    {
        int p = tid>>1, h = tid&1;
        const float* fs = feat + (size_t)(tp+p)*CF + h*32;
        float ch[32];
        #pragma unroll
        for (int q=0;q<8;q++){
            float4 v = *(const float4*)(fs + q*4);
            ch[q*4+0]=v.x; ch[q*4+1]=v.y; ch[q*4+2]=v.z; ch[q*4+3]=v.w;
        }
        #pragma unroll
        for (int ks=0;ks<4;ks++)
            pack_store(inb4 + ((((h*4+ks)<<7)+p)<<2), ch+ks*8);
    }
    __syncthreads();

    constexpr int CT2 = CT/2;
    constexpr int PG2 = 8/CT2;
    constexpr int PW  = 128/PG2;
    constexpr int NT  = PW/8;
    int ln = tid&31, w = tid>>5;
    int g = ln>>2, t = ln&3;
    int ct2 = w%CT2;
    int pb  = (w/CT2)*PW;

    float acc[2][NT][4];
    #pragma unroll
    for (int cc=0;cc<2;cc++)
        #pragma unroll
        for (int nt=0;nt<NT;nt++){ acc[cc][nt][0]=0;acc[cc][nt][1]=0;acc[cc][nt][2]=0;acc[cc][nt][3]=0; }

    for (int ks=0; ks<KS; ks++){
        float4 ah0 = __ldg(&g_wfh[wofs + (ks*CT+ct2*2  )*32+ln]);
        float4 al0 = __ldg(&g_wfl[wofs + (ks*CT+ct2*2  )*32+ln]);
        float4 ah1 = __ldg(&g_wfh[wofs + (ks*CT+ct2*2+1)*32+ln]);
        float4 al1 = __ldg(&g_wfl[wofs + (ks*CT+ct2*2+1)*32+ln]);
        #pragma unroll
        for (int nt=0;nt<NT;nt++){
            float4 bb = inb4[((ks<<7) + pb + nt*8 + g)*4 + t];
            mma3(acc[0][nt], ah0, al0, bb);
            mma3(acc[1][nt], ah1, al1, bb);
        }
    }

    #pragma unroll
    for (int cc=0;cc<2;cc++){
        int ch0 = (ct2*2+cc)*16;
        #pragma unroll
        for (int nt=0;nt<NT;nt++){
            int pofs = tp + pb + nt*8 + 2*t;
            size_t base = (size_t)pofs*FS + coff + ch0;
            g_f1[base + g]        = acc[cc][nt][0];
            g_f1[base + FS + g]   = acc[cc][nt][1];
            g_f1[base + g+8]      = acc[cc][nt][2];
            g_f1[base + FS + g+8] = acc[cc][nt][3];
        }
    }
}

// ---------------- histogram ----------------
template<int K>
__global__ void hist_kernel(const float* __restrict__ xyz, const float* __restrict__ nxyz,
                            int noff, int sidx){
    __shared__ float saux[8][9];
    int tid = threadIdx.x, lane = tid&31, wid = tid>>5;
    int gp = blockIdx.x*256 + tid;
    int g  = gp / K;
    int n  = g_nbr[noff+gp];
    int b  = g >> 10;
    int pt = (b<<12) + n;
    int*   cnt = g_cnt3 + sidx*NPT;
    float* cs  = g_cs3  + sidx*NPT*3;
    float cgx=nxyz[g*3], cgy=nxyz[g*3+1], cgz=nxyz[g*3+2];
    float dx = xyz[pt*3]-cgx, dy = xyz[pt*3+1]-cgy, dz = xyz[pt*3+2]-cgz;
    atomicAdd(&cnt[pt], 1);
    atomicAdd(&cs[pt*3+0], cgx);
    atomicAdd(&cs[pt*3+1], cgy);
    atomicAdd(&cs[pt*3+2], cgz);
    float v[9] = {dx,dy,dz, dx*dx,dy*dy,dz*dz, dx*dy,dx*dz,dy*dz};
    #pragma unroll
    for (int q=0;q<9;q++){
        float s=v[q];
        #pragma unroll
        for (int o=16;o;o>>=1) s += __shfl_down_sync(0xffffffffu,s,o);
        v[q]=s;
    }
    if (lane==0){
        #pragma unroll
        for (int q=0;q<9;q++) saux[wid][q]=v[q];
    }
    __syncthreads();
    if (tid < 9){
        float s=0.0f;
        #pragma unroll
        for (int w=0;w<8;w++) s += saux[w][tid];
        atomicAdd(&g_auxp3[sidx*288 + tid*32], s);
    }
}

// ---------------- per-channel stats ----------------
template<int C0>
__global__ void chanstat_kernel(const float* __restrict__ xyz, int coff, int sidx){
    __shared__ float sCnt[256], sRx[256], sRy[256], sRz[256];
    __shared__ float st1[C0], st2[C0], scx[C0], scy[C0], scz[C0];
    int tid = threadIdx.x, n0 = blockIdx.x*256;
    const int*   cnt = g_cnt3 + sidx*NPT;
    const float* cs  = g_cs3  + sidx*NPT*3;
    {
        int n = n0 + tid;
        float c = (float)cnt[n];
        sCnt[tid] = c;
        sRx[tid] = c*xyz[n*3+0] - cs[n*3+0];
        sRy[tid] = c*xyz[n*3+1] - cs[n*3+1];
        sRz[tid] = c*xyz[n*3+2] - cs[n*3+2];
    }
    if (tid < C0){ st1[tid]=0; st2[tid]=0; scx[tid]=0; scy[tid]=0; scz[tid]=0; }
    __syncthreads();

    constexpr int QN = C0/4, NR = 256/QN;
    int cq = tid % QN, j = tid / QN;
    float a1[4]={0,0,0,0}, a2[4]={0,0,0,0}, ax[4]={0,0,0,0}, ay[4]={0,0,0,0}, az[4]={0,0,0,0};
    for (int jj=j; jj<256; jj+=NR){
        float4 f = *(const float4*)(g_f1 + (size_t)(n0+jj)*FS + coff + cq*4);
        float c = sCnt[jj], Rx = sRx[jj], Ry = sRy[jj], Rz = sRz[jj];
        float fv[4] = {f.x,f.y,f.z,f.w};
        #pragma unroll
        for (int q=0;q<4;q++){
            a1[q] = fmaf(c, fv[q], a1[q]);
            a2[q] = fmaf(c*fv[q], fv[q], a2[q]);
            ax[q] = fmaf(fv[q], Rx, ax[q]);
            ay[q] = fmaf(fv[q], Ry, ay[q]);
            az[q] = fmaf(fv[q], Rz, az[q]);
        }
    }
    #pragma unroll
    for (int q=0;q<4;q++){
        atomicAdd(&st1[cq*4+q], a1[q]);
        atomicAdd(&st2[cq*4+q], a2[q]);
        atomicAdd(&scx[cq*4+q], ax[q]);
        atomicAdd(&scy[cq*4+q], ay[q]);
        atomicAdd(&scz[cq*4+q], az[q]);
    }
    __syncthreads();
    if (tid < C0){
        atomicAdd(&g_s13[sidx*128+tid], st1[tid]);
        atomicAdd(&g_s23[sidx*128+tid], st2[tid]);
        atomicAdd(&g_cr3[sidx*384+tid*3+0], scx[tid]);
        atomicAdd(&g_cr3[sidx*384+tid*3+1], scy[tid]);
        atomicAdd(&g_cr3[sidx*384+tid*3+2], scz[tid]);
    }
}

// ---------------- pass C: stats0 finalize + fill + tf32 mma conv1 ----------------
template<int K,int C0,int C1>
__global__ void __launch_bounds__(256,2)
passC_kernel(const float* __restrict__ g0v, const float* __restrict__ b0v,
             const float* __restrict__ w0,
             const float* __restrict__ xyz, const float* __restrict__ nxyz,
             int noff, int coff, int wofs, int sidx)
{
    const int P = GRPS*K;
    constexpr int PTS = 128, NTH = 256;
    constexpr int KS = C0/8;
    constexpr int CT = C1/16;
    extern __shared__ float smf[];
    float4* gsb4 = (float4*)smf;                 // KS*PTS*4 float4
    float*  qa   = (float*)(gsb4 + KS*PTS*4);
    float*  qb   = qa + C0;
    float*  q0   = qb + C0;
    float*  q1   = q0 + C0;
    float*  q2   = q1 + C0;
    float*  st   = q2 + C0;                      // 2*C1
    int tid = threadIdx.x, tp = blockIdx.x*PTS;

    if (tid < C0){
        float wx=w0[tid*INCH+0], wy=w0[tid*INCH+1], wz=w0[tid*INCH+2];
        const float* ax = g_auxp3 + sidx*288;
        float T0=ax[0*32], T1=ax[1*32], T2=ax[2*32];
        float Qxx=ax[3*32], Qyy=ax[4*32], Qzz=ax[5*32];
        float Qxy=ax[6*32], Qxz=ax[7*32], Qyz=ax[8*32];
        float sum = g_s13[sidx*128+tid] + wx*T0 + wy*T1 + wz*T2;
        float cr  = wx*g_cr3[sidx*384+tid*3+0] + wy*g_cr3[sidx*384+tid*3+1] + wz*g_cr3[sidx*384+tid*3+2];
        float qf  = wx*wx*Qxx + wy*wy*Qyy + wz*wz*Qzz
                  + 2.0f*(wx*wy*Qxy + wx*wz*Qxz + wy*wz*Qyz);
        float sumsq = g_s23[sidx*128+tid] + 2.0f*cr + qf;
        float cnt  = (float)P;
        float mean = sum/cnt;
        float var  = sumsq/cnt - mean*mean;
        float a    = g0v[tid]/sqrtf(var + 1e-5f);
        qa[tid] = a;
        qb[tid] = b0v[tid] - mean*a;
        q0[tid] = a*wx;
        q1[tid] = a*wy;
        q2[tid] = a*wz;
    }
    for (int i=tid;i<2*C1;i+=NTH) st[i]=0.0f;
    __syncthreads();

    {
        int p = tid>>1, h = tid&1;
        int gp = tp + p;
        int g  = gp / K;
        int n  = g_nbr[noff+gp];
        int b  = g >> 10;
        int pt = (b<<12) + n;
        float dx = xyz[pt*3+0]-nxyz[g*3+0];
        float dy = xyz[pt*3+1]-nxyz[g*3+1];
        float dz = xyz[pt*3+2]-nxyz[g*3+2];
        const float* f1 = g_f1 + (size_t)pt*FS + coff;
        #pragma unroll
        for (int ks=h*(KS/2); ks<(h+1)*(KS/2); ks++){
            float4 fa = *(const float4*)(f1 + ks*8);
            float4 fb = *(const float4*)(f1 + ks*8 + 4);
            float4 A0 = *(const float4*)(qa + ks*8), A1 = *(const float4*)(qa + ks*8 + 4);
            float4 B0 = *(const float4*)(qb + ks*8), B1 = *(const float4*)(qb + ks*8 + 4);
            float4 X0 = *(const float4*)(q0 + ks*8), X1 = *(const float4*)(q0 + ks*8 + 4);
            float4 Y0 = *(const float4*)(q1 + ks*8), Y1 = *(const float4*)(q1 + ks*8 + 4);
            float4 Z0 = *(const float4*)(q2 + ks*8), Z1 = *(const float4*)(q2 + ks*8 + 4);
            float ch[8];
            ch[0]=fmaf(X0.x,dx,fmaf(Y0.x,dy,fmaf(Z0.x,dz,fmaf(A0.x,fa.x,B0.x))));
            ch[1]=fmaf(X0.y,dx,fmaf(Y0.y,dy,fmaf(Z0.y,dz,fmaf(A0.y,fa.y,B0.y))));
            ch[2]=fmaf(X0.z,dx,fmaf(Y0.z,dy,fmaf(Z0.z,dz,fmaf(A0.z,fa.z,B0.z))));
            ch[3]=fmaf(X0.w,dx,fmaf(Y0.w,dy,fmaf(Z0.w,dz,fmaf(A0.w,fa.w,B0.w))));
            ch[4]=fmaf(X1.x,dx,fmaf(Y1.x,dy,fmaf(Z1.x,dz,fmaf(A1.x,fb.x,B1.x))));
            ch[5]=fmaf(X1.y,dx,fmaf(Y1.y,dy,fmaf(Z1.y,dz,fmaf(A1.y,fb.y,B1.y))));
            ch[6]=fmaf(X1.z,dx,fmaf(Y1.z,dy,fmaf(Z1.z,dz,fmaf(A1.z,fb.z,B1.z))));
            ch[7]=fmaf(X1.w,dx,fmaf(Y1.w,dy,fmaf(Z1.w,dz,fmaf(A1.w,fb.w,B1.w))));
            #pragma unroll
            for (int j=0;j<8;j++) ch[j] = gelu_exact(ch[j]);
            pack_store(gsb4 + ((ks*PTS+p)<<2), ch);
        }
    }
    __syncthreads();

    constexpr int NW  = NTH/32;
    constexpr int CT2 = CT/2;
    constexpr int PG2 = NW/CT2;
    constexpr int PW  = PTS/PG2;
    constexpr int NT  = PW/8;
    int ln = tid&31, w = tid>>5;
    int g = ln>>2, t = ln&3;
    int ct2 = w%CT2;
    int pb  = (w/CT2)*PW;

    float acc[2][NT][4];
    #pragma unroll
    for (int cc=0;cc<2;cc++)
        #pragma unroll
        for (int nt=0;nt<NT;nt++){ acc[cc][nt][0]=0;acc[cc][nt][1]=0;acc[cc][nt][2]=0;acc[cc][nt][3]=0; }

    for (int ks=0; ks<KS; ks++){
        float4 ah0 = __ldg(&g_wfh[wofs + (ks*CT+ct2*2  )*32+ln]);
        float4 al0 = __ldg(&g_wfl[wofs + (ks*CT+ct2*2  )*32+ln]);
        float4 ah1 = __ldg(&g_wfh[wofs + (ks*CT+ct2*2+1)*32+ln]);
        float4 al1 = __ldg(&g_wfl[wofs + (ks*CT+ct2*2+1)*32+ln]);
        #pragma unroll
        for (int nt=0;nt<NT;nt++){
            float4 bb = gsb4[(ks*PTS + pb + nt*8 + g)*4 + t];
            mma3(acc[0][nt], ah0, al0, bb);
            mma3(acc[1][nt], ah1, al1, bb);
        }
    }

    constexpr int NTPG = K/8;
    constexpr int NG   = (NT/NTPG > 0) ? NT/NTPG : 1;
    int gbase = (tp + pb)/K;
    #pragma unroll
    for (int cc=0;cc<2;cc++){
        int ch0 = (ct2*2+cc)*16;
        float sA=0,sA2=0,sB=0,sB2=0;
        #pragma unroll
        for (int nt=0;nt<NT;nt++){
            float x=acc[cc][nt][0], y=acc[cc][nt][1], z=acc[cc][nt][2], v=acc[cc][nt][3];
            sA += x+y; sA2 += x*x+y*y; sB += z+v; sB2 += z*z+v*v;
        }
        #pragma unroll
        for (int o=1;o<4;o<<=1){
            sA  += __shfl_xor_sync(0xffffffffu,sA,o);
            sA2 += __shfl_xor_sync(0xffffffffu,sA2,o);
            sB  += __shfl_xor_sync(0xffffffffu,sB,o);
            sB2 += __shfl_xor_sync(0xffffffffu,sB2,o);
        }
        if (t==0){
            atomicAdd(&st[ch0+g],      sA);  atomicAdd(&st[C1+ch0+g],   sA2);
            atomicAdd(&st[ch0+g+8],    sB);  atomicAdd(&st[C1+ch0+g+8], sB2);
        }
        #pragma unroll
        for (int gi=0; gi<NG; gi++){
            float mxA=-3.4e38f, mnA=3.4e38f, mxB=-3.4e38f, mnB=3.4e38f;
            #pragma unroll
            for (int u=0; u<NTPG; u++){
                float* a = acc[cc][gi*NTPG+u];
                mxA=fmaxf(mxA,fmaxf(a[0],a[1])); mnA=fminf(mnA,fminf(a[0],a[1]));
                mxB=fmaxf(mxB,fmaxf(a[2],a[3])); mnB=fminf(mnB,fminf(a[2],a[3]));
            }
            #pragma unroll
            for (int o=1;o<4;o<<=1){
                mxA=fmaxf(mxA,__shfl_xor_sync(0xffffffffu,mxA,o));
                mnA=fminf(mnA,__shfl_xor_sync(0xffffffffu,mnA,o));
                mxB=fmaxf(mxB,__shfl_xor_sync(0xffffffffu,mxB,o));
                mnB=fminf(mnB,__shfl_xor_sync(0xffffffffu,mnB,o));
            }
            if (t==0){
                int gg = gbase + gi;
                g_rawmax[(ch0+g)*GRPS   + gg] = mxA;  g_rawmin[(ch0+g)*GRPS   + gg] = mnA;
                g_rawmax[(ch0+g+8)*GRPS + gg] = mxB;  g_rawmin[(ch0+g+8)*GRPS + gg] = mnB;
            }
        }
    }
    __syncthreads();
    for (int i=tid;i<C1;i+=NTH){
        atomicAdd(&g_stats1[sidx*256+i],     st[i]);
        atomicAdd(&g_stats1[sidx*256+128+i], st[C1+i]);
    }
}

// ---------------- finalize ----------------
template<int K,int C1>
__global__ void out_kernel(const float* __restrict__ g1v, const float* __restrict__ b1v,
                           float* __restrict__ out, int chOff, int sidx)
{
    int i = blockIdx.x*blockDim.x + threadIdx.x;
    if (i >= C1*GRPS) return;
    int c = i / GRPS; int g = i - c*GRPS;
    int b = g >> 10, m = g & 1023;
    float cnt  = (float)(GRPS*K);
    float mean = g_stats1[sidx*256+c]/cnt;
    float var  = g_stats1[sidx*256+128+c]/cnt - mean*mean;
    float a    = g1v[c]/sqrtf(var + 1e-5f);
    float bb   = b1v[c] - mean*a;
    float v1   = a*g_rawmax[c*GRPS + g] + bb;
    float v2   = a*g_rawmin[c*GRPS + g] + bb;
    out[XYZ_OUT + ((size_t)b*320 + chOff + c)*MM + m] = fmaxf(gelu_exact(v1), gelu_exact(v2));
}

// ---------------- launch ----------------
extern "C" void kernel_launch(void* const* d_in, const int* in_sizes, int n_in,
                              void* d_out, int out_size)
{
    const float* xyz  = (const float*)d_in[0];
    const float* feat = (const float*)d_in[1];
    const float* w00  = (const float*)d_in[2];
    const float* w01  = (const float*)d_in[3];
    const float* w10  = (const float*)d_in[4];
    const float* w11  = (const float*)d_in[5];
    const float* w20  = (const float*)d_in[6];
    const float* w21  = (const float*)d_in[7];
    const float* g00  = (const float*)d_in[8];
    const float* b00  = (const float*)d_in[9];
    const float* g01  = (const float*)d_in[10];
    const float* b01  = (const float*)d_in[11];
    const float* g10  = (const float*)d_in[12];
    const float* b10  = (const float*)d_in[13];
    const float* g11  = (const float*)d_in[14];
    const float* b11  = (const float*)d_in[15];
    const float* g20  = (const float*)d_in[16];
    const float* b20  = (const float*)d_in[17];
    const float* g21  = (const float*)d_in[18];
    const float* b21  = (const float*)d_in[19];
    float* out = (float*)d_out;
    float* newxyz = out;

    const int smFPS = 3*NN*4;
    const int smBQ  = 3*NN*4;
    const int smDEN = 8*128*4*16;                              // 64KB
    const int smC0  = 4*128*4*16 + (5*32 + 2*64)*4;            // ~33KB
    const int smC12 = 8*128*4*16 + (5*64 + 2*128)*4;           // ~66KB

    cudaFuncSetAttribute(fps_kernel,       cudaFuncAttributeMaxDynamicSharedMemorySize, smFPS);
    cudaFuncSetAttribute(ballq_kernel,     cudaFuncAttributeMaxDynamicSharedMemorySize, smBQ);
    cudaFuncSetAttribute(dense_kernel<32>, cudaFuncAttributeMaxDynamicSharedMemorySize, smDEN);
    cudaFuncSetAttribute(dense_kernel<64>, cudaFuncAttributeMaxDynamicSharedMemorySize, smDEN);
    cudaFuncSetAttribute(passC_kernel<16,32,64>,  cudaFuncAttributeMaxDynamicSharedMemorySize, smC0);
    cudaFuncSetAttribute(passC_kernel<32,64,128>, cudaFuncAttributeMaxDynamicSharedMemorySize, smC12);
    cudaFuncSetAttribute(passC_kernel<64,64,128>, cudaFuncAttributeMaxDynamicSharedMemorySize, smC12);

    fps_kernel<<<BB, 1024, smFPS>>>(xyz, newxyz);
    ballq_kernel<<<GRPS/8, 256, smBQ>>>(xyz, newxyz);

    prep_kernel<<<(WF_TOT+255)/256, 256>>>(w00, w10, w20, w01, w11, w21);
    dense_kernel<32><<<NPT/128, 256, smDEN>>>(feat, OFF_D0, 0);
    dense_kernel<64><<<NPT/128, 256, smDEN>>>(feat, OFF_D1, 32);
    dense_kernel<64><<<NPT/128, 256, smDEN>>>(feat, OFF_D2, 96);

    zero_all_kernel<<<(3*NPT)/256, 256>>>();
    hist_kernel<16><<<GRPS*16/256, 256>>>(xyz, newxyz, 0,        0);
    hist_kernel<32><<<GRPS*32/256, 256>>>(xyz, newxyz, 16*GRPS,  1);
    hist_kernel<64><<<GRPS*64/256, 256>>>(xyz, newxyz, 48*GRPS,  2);
    chanstat_kernel<32><<<NPT/256, 256>>>(xyz, 0,  0);
    chanstat_kernel<64><<<NPT/256, 256>>>(xyz, 32, 1);
    chanstat_kernel<64><<<NPT/256, 256>>>(xyz, 96, 2);

    passC_kernel<16,32,64><<<GRPS*16/128, 256, smC0>>>(g00, b00, w00, xyz, newxyz, 0, 0, OFF_C0, 0);
    out_kernel<16,64><<<(64*GRPS)/256, 256>>>(g01, b01, out, 0, 0);

    passC_kernel<32,64,128><<<GRPS*32/128, 256, smC12>>>(g10, b10, w10, xyz, newxyz, 16*GRPS, 32, OFF_C1, 1);
    out_kernel<32,128><<<(128*GRPS)/256, 256>>>(g11, b11, out, 64, 1);

    passC_kernel<64,64,128><<<GRPS*64/128, 256, smC12>>>(g20, b20, w20, xyz, newxyz, 48*GRPS, 96, OFF_C2, 2);
    out_kernel<64,128><<<(128*GRPS)/256, 256>>>(g21, b21, out, 192, 2);
}

// round 15
// speedup vs baseline: 2.0682x; 1.1051x over previous
#include <cuda_runtime.h>
#include <math.h>
#include <stdint.h>

#define BB 16
#define NN 4096
#define MM 1024
#define CF 64
#define INCH 67
#define GRPS (BB*MM)
#define NPT (BB*NN)          // 65536 original points
#define FS 160               // g_f1 row stride (32+64+64)
#define XYZ_OUT ((size_t)BB*MM*3)

// weight-fragment segment offsets (float4 units)
#define OFF_D0 0
#define OFF_D1 512
#define OFF_D2 1536
#define OFF_C0 2560
#define OFF_C1 3072
#define OFF_C2 5120
#define WF_TOT 7168

// ---------------- device scratch ----------------
__device__ int    g_nbr[(16+32+64)*GRPS];
__device__ float  g_f1[(size_t)NPT*FS];
__device__ float4 g_wfh[WF_TOT], g_wfl[WF_TOT];     // fragment-packed weights hi/lo
__device__ int    g_cnt3[3*NPT];
__device__ float  g_cs3[3*NPT*3];
__device__ float  g_auxp3[3*9*32];                  // per-scale T/Q, 128B-spread
__device__ float  g_s13[3*128], g_s23[3*128], g_cr3[3*384];
__device__ float  g_rawmax[128 * GRPS];
__device__ float  g_rawmin[128 * GRPS];
__device__ float  g_stats1[3*256];                  // per-scale layer1 sum/sumsq

__device__ __forceinline__ float sqdist_rn(float dx, float dy, float dz){
    return __fadd_rn(__fadd_rn(__fmul_rn(dx,dx),__fmul_rn(dy,dy)),__fmul_rn(dz,dz));
}
__device__ __forceinline__ float gelu_exact(float x){
    return 0.5f * x * (1.0f + erff(x * 0.70710678118654752f));
}
__device__ __forceinline__ float tf32rna(float x){
    uint32_t h; asm("cvt.rna.tf32.f32 %0, %1;" : "=r"(h) : "f"(x));
    return __uint_as_float(h);
}
__device__ __forceinline__ void tf32split(float x, float& hi, float& lo){
    hi = tf32rna(x);
    lo = tf32rna(x - hi);
}
__device__ __forceinline__ void mma_tf32(float* d,
    uint32_t a0,uint32_t a1,uint32_t a2,uint32_t a3, uint32_t b0,uint32_t b1){
    asm volatile(
        "mma.sync.aligned.m16n8k8.row.col.f32.tf32.tf32.f32 "
        "{%0,%1,%2,%3}, {%4,%5,%6,%7}, {%8,%9}, {%0,%1,%2,%3};"
        : "+f"(d[0]), "+f"(d[1]), "+f"(d[2]), "+f"(d[3])
        : "r"(a0), "r"(a1), "r"(a2), "r"(a3), "r"(b0), "r"(b1));
}
// 2-term: (Ah + Al) x B  — A exact, B single tf32
__device__ __forceinline__ void mma2(float* acc, const float4& ah, const float4& al, const float2& bb){
    mma_tf32(acc, __float_as_uint(ah.x),__float_as_uint(ah.y),__float_as_uint(ah.z),__float_as_uint(ah.w),
                  __float_as_uint(bb.x),__float_as_uint(bb.y));
    mma_tf32(acc, __float_as_uint(al.x),__float_as_uint(al.y),__float_as_uint(al.z),__float_as_uint(al.w),
                  __float_as_uint(bb.x),__float_as_uint(bb.y));
}
// 8 channel values -> 4 fragment float2 (hi-only), contiguous
__device__ __forceinline__ void pack_store_h(float2* dst, const float* v){
    #pragma unroll
    for (int t=0;t<4;t++)
        dst[t] = make_float2(tf32rna(v[t]), tf32rna(v[t+4]));
}

// ---------------- 0) weight fragment prep ----------------
__global__ void prep_kernel(const float* __restrict__ w00, const float* __restrict__ w10,
                            const float* __restrict__ w20, const float* __restrict__ w01,
                            const float* __restrict__ w11, const float* __restrict__ w21){
    int i = blockIdx.x*256 + threadIdx.x;
    if (i >= WF_TOT) return;
    const float* w; int base, CT, ld, k0;
    if      (i < OFF_D1){ w=w00; base=OFF_D0; CT=2; ld=INCH; k0=3; }
    else if (i < OFF_D2){ w=w10; base=OFF_D1; CT=4; ld=INCH; k0=3; }
    else if (i < OFF_C0){ w=w20; base=OFF_D2; CT=4; ld=INCH; k0=3; }
    else if (i < OFF_C1){ w=w01; base=OFF_C0; CT=4; ld=32;   k0=0; }
    else if (i < OFF_C2){ w=w11; base=OFF_C1; CT=8; ld=64;   k0=0; }
    else               { w=w21; base=OFF_C2; CT=8; ld=64;   k0=0; }
    int rem = i - base;
    int ks = rem/(CT*32), r2 = rem - ks*CT*32, ct = r2>>5, ln = r2&31;
    int g = ln>>2, t = ln&3, c0 = ct*16, k = ks*8 + k0;
    float4 H,L;
    tf32split(w[(c0+g  )*ld + k+t  ], H.x, L.x);
    tf32split(w[(c0+g+8)*ld + k+t  ], H.y, L.y);
    tf32split(w[(c0+g  )*ld + k+t+4], H.z, L.z);
    tf32split(w[(c0+g+8)*ld + k+t+4], H.w, L.w);
    g_wfh[i]=H; g_wfl[i]=L;
}

// ---------------- 1) farthest point sampling (REDUX) ----------------
__global__ void fps_kernel(const float* __restrict__ xyz, float* __restrict__ out_newxyz){
    extern __shared__ float sm[];
    float* sx = sm; float* sy = sm+NN; float* sz = sm+2*NN;
    __shared__ unsigned rv[2][32]; __shared__ int ri[2][32];
    int b = blockIdx.x, t = threadIdx.x, lane = t&31, wid = t>>5;
    for (int i=t;i<NN;i+=blockDim.x){
        const float* p = xyz + ((size_t)b*NN+i)*3;
        sx[i]=p[0]; sy[i]=p[1]; sz[i]=p[2];
    }
    __syncthreads();
    float dreg[4] = {1e10f,1e10f,1e10f,1e10f};
    int far = 0;
    for (int it=0; it<MM; it++){
        float cx=sx[far], cy=sy[far], cz=sz[far];
        if (t==0){
            float* o = out_newxyz + ((size_t)b*MM+it)*3;
            o[0]=cx; o[1]=cy; o[2]=cz;
        }
        float best=-1.0f; int bi=0;
        #pragma unroll
        for (int u=0;u<4;u++){
            int i = t + u*1024;
            float d  = sqdist_rn(sx[i]-cx, sy[i]-cy, sz[i]-cz);
            float nd = fminf(dreg[u], d);
            dreg[u]=nd;
            if (nd>best){ best=nd; bi=i; }
        }
        unsigned ub = __float_as_uint(best);
        unsigned m  = __reduce_max_sync(0xffffffffu, ub);
        unsigned ci = (ub==m)? (unsigned)bi : 0x7FFFFFFFu;
        unsigned mi = __reduce_min_sync(0xffffffffu, ci);
        if (lane==0){ rv[it&1][wid]=m; ri[it&1][wid]=(int)mi; }
        __syncthreads();
        unsigned u2 = rv[it&1][lane];
        int      i2 = ri[it&1][lane];
        unsigned m2 = __reduce_max_sync(0xffffffffu, u2);
        unsigned c2 = (u2==m2)? (unsigned)i2 : 0x7FFFFFFFu;
        far = (int)__reduce_min_sync(0xffffffffu, c2);
    }
}

// ---------------- 2) ball query ----------------
__global__ void __launch_bounds__(256)
ballq_kernel(const float* __restrict__ xyz, const float* __restrict__ newxyz){
    extern __shared__ float sm[];
    float* sx = sm; float* sy = sm+NN; float* sz = sm+2*NN;
    int tid = threadIdx.x;
    int gw0 = blockIdx.x*8;
    int b   = gw0 >> 10;
    const float* base = xyz + (size_t)b*NN*3;
    for (int j=tid;j<NN*3;j+=256){
        float v = base[j];
        int idx = j/3, ch = j-idx*3;
        if (ch==0) sx[idx]=v; else if (ch==1) sy[idx]=v; else sz[idx]=v;
    }
    __syncthreads();
    int w    = tid>>5;
    int lane = tid&31;
    int gw   = gw0 + w;
    float cx=newxyz[gw*3+0], cy=newxyz[gw*3+1], cz=newxyz[gw*3+2];
    const float R2_0=(float)(0.1*0.1), R2_1=(float)(0.2*0.2), R2_2=(float)(0.4*0.4);
    int c0=0,c1=0,c2=0, f0=0,f1=0,f2=0;
    int* n0 = g_nbr + gw*16;
    int* n1 = g_nbr + 16*GRPS + gw*32;
    int* n2 = g_nbr + 48*GRPS + gw*64;
    for (int s=0;s<NN;s+=32){
        int i = s + lane;
        float d = sqdist_rn(sx[i]-cx, sy[i]-cy, sz[i]-cz);
        unsigned m0=__ballot_sync(0xffffffffu, d<=R2_0);
        unsigned m1=__ballot_sync(0xffffffffu, d<=R2_1);
        unsigned m2=__ballot_sync(0xffffffffu, d<=R2_2);
        if (m0 && c0<16){
            if (c0==0) f0 = s + __ffs(m0) - 1;
            int r = __popc(m0 & ((1u<<lane)-1u));
            if ((m0>>lane)&1u){ if (c0+r<16) n0[c0+r]=i; }
            c0 += __popc(m0); if (c0>16) c0=16;
        }
        if (m1 && c1<32){
            if (c1==0) f1 = s + __ffs(m1) - 1;
            int r = __popc(m1 & ((1u<<lane)-1u));
            if ((m1>>lane)&1u){ if (c1+r<32) n1[c1+r]=i; }
            c1 += __popc(m1); if (c1>32) c1=32;
        }
        if (m2 && c2<64){
            if (c2==0) f2 = s + __ffs(m2) - 1;
            int r = __popc(m2 & ((1u<<lane)-1u));
            if ((m2>>lane)&1u){ if (c2+r<64) n2[c2+r]=i; }
            c2 += __popc(m2); if (c2>64) c2=64;
        }
        if (c0>=16 && c1>=32 && c2>=64) break;
    }
    for (int j=c0+lane;j<16;j+=32) n0[j]=f0;
    for (int j=c1+lane;j<32;j+=32) n1[j]=f1;
    for (int j=c2+lane;j<64;j+=32) n2[j]=f2;
}

// ---------------- zero ALL per-scale accumulators ----------------
__global__ void zero_all_kernel(){
    int i = blockIdx.x*256 + threadIdx.x;     // grid covers 3*NPT
    if (i < 3*NPT){
        g_cnt3[i]=0;
        g_cs3[i*3]=0.0f; g_cs3[i*3+1]=0.0f; g_cs3[i*3+2]=0.0f;
    }
    if (i < 3*9*32) g_auxp3[i]=0.0f;
    if (i < 3*128){ g_s13[i]=0.0f; g_s23[i]=0.0f; }
    if (i < 3*384) g_cr3[i]=0.0f;
    if (i < 3*256) g_stats1[i]=0.0f;
}

// ---------------- dense conv0 (hi-only activations, 2-term mma) ----------------
template<int C0>
__global__ void __launch_bounds__(256,2)
dense_kernel(const float* __restrict__ feat, int wofs, int coff){
    constexpr int KS = 8;
    constexpr int CT = C0/16;
    extern __shared__ float smf[];
    float2* inb2 = (float2*)smf;         // KS*128*4 float2 = 32KB
    int tid = threadIdx.x;
    int tp  = blockIdx.x*128;

    {
        int p = tid>>1, h = tid&1;
        const float* fs = feat + (size_t)(tp+p)*CF + h*32;
        float ch[32];
        #pragma unroll
        for (int q=0;q<8;q++){
            float4 v = *(const float4*)(fs + q*4);
            ch[q*4+0]=v.x; ch[q*4+1]=v.y; ch[q*4+2]=v.z; ch[q*4+3]=v.w;
        }
        #pragma unroll
        for (int ks=0;ks<4;ks++)
            pack_store_h(inb2 + ((((h*4+ks)<<7)+p)<<2), ch+ks*8);
    }
    __syncthreads();

    constexpr int CT2 = CT/2;
    constexpr int PG2 = 8/CT2;
    constexpr int PW  = 128/PG2;
    constexpr int NT  = PW/8;
    int ln = tid&31, w = tid>>5;
    int g = ln>>2, t = ln&3;
    int ct2 = w%CT2;
    int pb  = (w/CT2)*PW;

    float acc[2][NT][4];
    #pragma unroll
    for (int cc=0;cc<2;cc++)
        #pragma unroll
        for (int nt=0;nt<NT;nt++){ acc[cc][nt][0]=0;acc[cc][nt][1]=0;acc[cc][nt][2]=0;acc[cc][nt][3]=0; }

    for (int ks=0; ks<KS; ks++){
        float4 ah0 = __ldg(&g_wfh[wofs + (ks*CT+ct2*2  )*32+ln]);
        float4 al0 = __ldg(&g_wfl[wofs + (ks*CT+ct2*2  )*32+ln]);
        float4 ah1 = __ldg(&g_wfh[wofs + (ks*CT+ct2*2+1)*32+ln]);
        float4 al1 = __ldg(&g_wfl[wofs + (ks*CT+ct2*2+1)*32+ln]);
        #pragma unroll
        for (int nt=0;nt<NT;nt++){
            float2 bb = inb2[((ks<<7) + pb + nt*8 + g)*4 + t];
            mma2(acc[0][nt], ah0, al0, bb);
            mma2(acc[1][nt], ah1, al1, bb);
        }
    }

    #pragma unroll
    for (int cc=0;cc<2;cc++){
        int ch0 = (ct2*2+cc)*16;
        #pragma unroll
        for (int nt=0;nt<NT;nt++){
            int pofs = tp + pb + nt*8 + 2*t;
            size_t base = (size_t)pofs*FS + coff + ch0;
            g_f1[base + g]        = acc[cc][nt][0];
            g_f1[base + FS + g]   = acc[cc][nt][1];
            g_f1[base + g+8]      = acc[cc][nt][2];
            g_f1[base + FS + g+8] = acc[cc][nt][3];
        }
    }
}

// ---------------- histogram ----------------
template<int K>
__global__ void hist_kernel(const float* __restrict__ xyz, const float* __restrict__ nxyz,
                            int noff, int sidx){
    __shared__ float saux[8][9];
    int tid = threadIdx.x, lane = tid&31, wid = tid>>5;
    int gp = blockIdx.x*256 + tid;
    int g  = gp / K;
    int n  = g_nbr[noff+gp];
    int b  = g >> 10;
    int pt = (b<<12) + n;
    int*   cnt = g_cnt3 + sidx*NPT;
    float* cs  = g_cs3  + sidx*NPT*3;
    float cgx=nxyz[g*3], cgy=nxyz[g*3+1], cgz=nxyz[g*3+2];
    float dx = xyz[pt*3]-cgx, dy = xyz[pt*3+1]-cgy, dz = xyz[pt*3+2]-cgz;
    atomicAdd(&cnt[pt], 1);
    atomicAdd(&cs[pt*3+0], cgx);
    atomicAdd(&cs[pt*3+1], cgy);
    atomicAdd(&cs[pt*3+2], cgz);
    float v[9] = {dx,dy,dz, dx*dx,dy*dy,dz*dz, dx*dy,dx*dz,dy*dz};
    #pragma unroll
    for (int q=0;q<9;q++){
        float s=v[q];
        #pragma unroll
        for (int o=16;o;o>>=1) s += __shfl_down_sync(0xffffffffu,s,o);
        v[q]=s;
    }
    if (lane==0){
        #pragma unroll
        for (int q=0;q<9;q++) saux[wid][q]=v[q];
    }
    __syncthreads();
    if (tid < 9){
        float s=0.0f;
        #pragma unroll
        for (int w=0;w<8;w++) s += saux[w][tid];
        atomicAdd(&g_auxp3[sidx*288 + tid*32], s);
    }
}

// ---------------- per-channel stats ----------------
template<int C0>
__global__ void chanstat_kernel(const float* __restrict__ xyz, int coff, int sidx){
    __shared__ float sCnt[256], sRx[256], sRy[256], sRz[256];
    __shared__ float st1[C0], st2[C0], scx[C0], scy[C0], scz[C0];
    int tid = threadIdx.x, n0 = blockIdx.x*256;
    const int*   cnt = g_cnt3 + sidx*NPT;
    const float* cs  = g_cs3  + sidx*NPT*3;
    {
        int n = n0 + tid;
        float c = (float)cnt[n];
        sCnt[tid] = c;
        sRx[tid] = c*xyz[n*3+0] - cs[n*3+0];
        sRy[tid] = c*xyz[n*3+1] - cs[n*3+1];
        sRz[tid] = c*xyz[n*3+2] - cs[n*3+2];
    }
    if (tid < C0){ st1[tid]=0; st2[tid]=0; scx[tid]=0; scy[tid]=0; scz[tid]=0; }
    __syncthreads();

    constexpr int QN = C0/4, NR = 256/QN;
    int cq = tid % QN, j = tid / QN;
    float a1[4]={0,0,0,0}, a2[4]={0,0,0,0}, ax[4]={0,0,0,0}, ay[4]={0,0,0,0}, az[4]={0,0,0,0};
    for (int jj=j; jj<256; jj+=NR){
        float4 f = *(const float4*)(g_f1 + (size_t)(n0+jj)*FS + coff + cq*4);
        float c = sCnt[jj], Rx = sRx[jj], Ry = sRy[jj], Rz = sRz[jj];
        float fv[4] = {f.x,f.y,f.z,f.w};
        #pragma unroll
        for (int q=0;q<4;q++){
            a1[q] = fmaf(c, fv[q], a1[q]);
            a2[q] = fmaf(c*fv[q], fv[q], a2[q]);
            ax[q] = fmaf(fv[q], Rx, ax[q]);
            ay[q] = fmaf(fv[q], Ry, ay[q]);
            az[q] = fmaf(fv[q], Rz, az[q]);
        }
    }
    #pragma unroll
    for (int q=0;q<4;q++){
        atomicAdd(&st1[cq*4+q], a1[q]);
        atomicAdd(&st2[cq*4+q], a2[q]);
        atomicAdd(&scx[cq*4+q], ax[q]);
        atomicAdd(&scy[cq*4+q], ay[q]);
        atomicAdd(&scz[cq*4+q], az[q]);
    }
    __syncthreads();
    if (tid < C0){
        atomicAdd(&g_s13[sidx*128+tid], st1[tid]);
        atomicAdd(&g_s23[sidx*128+tid], st2[tid]);
        atomicAdd(&g_cr3[sidx*384+tid*3+0], scx[tid]);
        atomicAdd(&g_cr3[sidx*384+tid*3+1], scy[tid]);
        atomicAdd(&g_cr3[sidx*384+tid*3+2], scz[tid]);
    }
}

// ---------------- pass C: stats0 finalize + fill (hi-only) + 2-term tf32 mma conv1 ----------------
template<int K,int C0,int C1>
__global__ void __launch_bounds__(256,2)
passC_kernel(const float* __restrict__ g0v, const float* __restrict__ b0v,
             const float* __restrict__ w0,
             const float* __restrict__ xyz, const float* __restrict__ nxyz,
             int noff, int coff, int wofs, int sidx)
{
    const int P = GRPS*K;
    constexpr int PTS = 128, NTH = 256;
    constexpr int KS = C0/8;
    constexpr int CT = C1/16;
    extern __shared__ float smf[];
    float2* gsb2 = (float2*)smf;                 // KS*PTS*4 float2
    float*  qa   = (float*)(gsb2 + KS*PTS*4);
    float*  qb   = qa + C0;
    float*  q0   = qb + C0;
    float*  q1   = q0 + C0;
    float*  q2   = q1 + C0;
    float*  st   = q2 + C0;                      // 2*C1
    int tid = threadIdx.x, tp = blockIdx.x*PTS;

    if (tid < C0){
        float wx=w0[tid*INCH+0], wy=w0[tid*INCH+1], wz=w0[tid*INCH+2];
        const float* ax = g_auxp3 + sidx*288;
        float T0=ax[0*32], T1=ax[1*32], T2=ax[2*32];
        float Qxx=ax[3*32], Qyy=ax[4*32], Qzz=ax[5*32];
        float Qxy=ax[6*32], Qxz=ax[7*32], Qyz=ax[8*32];
        float sum = g_s13[sidx*128+tid] + wx*T0 + wy*T1 + wz*T2;
        float cr  = wx*g_cr3[sidx*384+tid*3+0] + wy*g_cr3[sidx*384+tid*3+1] + wz*g_cr3[sidx*384+tid*3+2];
        float qf  = wx*wx*Qxx + wy*wy*Qyy + wz*wz*Qzz
                  + 2.0f*(wx*wy*Qxy + wx*wz*Qxz + wy*wz*Qyz);
        float sumsq = g_s23[sidx*128+tid] + 2.0f*cr + qf;
        float cnt  = (float)P;
        float mean = sum/cnt;
        float var  = sumsq/cnt - mean*mean;
        float a    = g0v[tid]/sqrtf(var + 1e-5f);
        qa[tid] = a;
        qb[tid] = b0v[tid] - mean*a;
        q0[tid] = a*wx;
        q1[tid] = a*wy;
        q2[tid] = a*wz;
    }
    for (int i=tid;i<2*C1;i+=NTH) st[i]=0.0f;
    __syncthreads();

    {
        int p = tid>>1, h = tid&1;
        int gp = tp + p;
        int g  = gp / K;
        int n  = g_nbr[noff+gp];
        int b  = g >> 10;
        int pt = (b<<12) + n;
        float dx = xyz[pt*3+0]-nxyz[g*3+0];
        float dy = xyz[pt*3+1]-nxyz[g*3+1];
        float dz = xyz[pt*3+2]-nxyz[g*3+2];
        const float* f1 = g_f1 + (size_t)pt*FS + coff;
        #pragma unroll
        for (int ks=h*(KS/2); ks<(h+1)*(KS/2); ks++){
            float4 fa = *(const float4*)(f1 + ks*8);
            float4 fb = *(const float4*)(f1 + ks*8 + 4);
            float4 A0 = *(const float4*)(qa + ks*8), A1 = *(const float4*)(qa + ks*8 + 4);
            float4 B0 = *(const float4*)(qb + ks*8), B1 = *(const float4*)(qb + ks*8 + 4);
            float4 X0 = *(const float4*)(q0 + ks*8), X1 = *(const float4*)(q0 + ks*8 + 4);
            float4 Y0 = *(const float4*)(q1 + ks*8), Y1 = *(const float4*)(q1 + ks*8 + 4);
            float4 Z0 = *(const float4*)(q2 + ks*8), Z1 = *(const float4*)(q2 + ks*8 + 4);
            float ch[8];
            ch[0]=fmaf(X0.x,dx,fmaf(Y0.x,dy,fmaf(Z0.x,dz,fmaf(A0.x,fa.x,B0.x))));
            ch[1]=fmaf(X0.y,dx,fmaf(Y0.y,dy,fmaf(Z0.y,dz,fmaf(A0.y,fa.y,B0.y))));
            ch[2]=fmaf(X0.z,dx,fmaf(Y0.z,dy,fmaf(Z0.z,dz,fmaf(A0.z,fa.z,B0.z))));
            ch[3]=fmaf(X0.w,dx,fmaf(Y0.w,dy,fmaf(Z0.w,dz,fmaf(A0.w,fa.w,B0.w))));
            ch[4]=fmaf(X1.x,dx,fmaf(Y1.x,dy,fmaf(Z1.x,dz,fmaf(A1.x,fb.x,B1.x))));
            ch[5]=fmaf(X1.y,dx,fmaf(Y1.y,dy,fmaf(Z1.y,dz,fmaf(A1.y,fb.y,B1.y))));
            ch[6]=fmaf(X1.z,dx,fmaf(Y1.z,dy,fmaf(Z1.z,dz,fmaf(A1.z,fb.z,B1.z))));
            ch[7]=fmaf(X1.w,dx,fmaf(Y1.w,dy,fmaf(Z1.w,dz,fmaf(A1.w,fb.w,B1.w))));
            #pragma unroll
            for (int j=0;j<8;j++) ch[j] = gelu_exact(ch[j]);
            pack_store_h(gsb2 + ((ks*PTS+p)<<2), ch);
        }
    }
    __syncthreads();

    constexpr int NW  = NTH/32;
    constexpr int CT2 = CT/2;
    constexpr int PG2 = NW/CT2;
    constexpr int PW  = PTS/PG2;
    constexpr int NT  = PW/8;
    int ln = tid&31, w = tid>>5;
    int g = ln>>2, t = ln&3;
    int ct2 = w%CT2;
    int pb  = (w/CT2)*PW;

    float acc[2][NT][4];
    #pragma unroll
    for (int cc=0;cc<2;cc++)
        #pragma unroll
        for (int nt=0;nt<NT;nt++){ acc[cc][nt][0]=0;acc[cc][nt][1]=0;acc[cc][nt][2]=0;acc[cc][nt][3]=0; }

    for (int ks=0; ks<KS; ks++){
        float4 ah0 = __ldg(&g_wfh[wofs + (ks*CT+ct2*2  )*32+ln]);
        float4 al0 = __ldg(&g_wfl[wofs + (ks*CT+ct2*2  )*32+ln]);
        float4 ah1 = __ldg(&g_wfh[wofs + (ks*CT+ct2*2+1)*32+ln]);
        float4 al1 = __ldg(&g_wfl[wofs + (ks*CT+ct2*2+1)*32+ln]);
        #pragma unroll
        for (int nt=0;nt<NT;nt++){
            float2 bb = gsb2[(ks*PTS + pb + nt*8 + g)*4 + t];
            mma2(acc[0][nt], ah0, al0, bb);
            mma2(acc[1][nt], ah1, al1, bb);
        }
    }

    constexpr int NTPG = K/8;
    constexpr int NG   = (NT/NTPG > 0) ? NT/NTPG : 1;
    int gbase = (tp + pb)/K;
    #pragma unroll
    for (int cc=0;cc<2;cc++){
        int ch0 = (ct2*2+cc)*16;
        float sA=0,sA2=0,sB=0,sB2=0;
        #pragma unroll
        for (int nt=0;nt<NT;nt++){
            float x=acc[cc][nt][0], y=acc[cc][nt][1], z=acc[cc][nt][2], v=acc[cc][nt][3];
            sA += x+y; sA2 += x*x+y*y; sB += z+v; sB2 += z*z+v*v;
        }
        #pragma unroll
        for (int o=1;o<4;o<<=1){
            sA  += __shfl_xor_sync(0xffffffffu,sA,o);
            sA2 += __shfl_xor_sync(0xffffffffu,sA2,o);
            sB  += __shfl_xor_sync(0xffffffffu,sB,o);
            sB2 += __shfl_xor_sync(0xffffffffu,sB2,o);
        }
        if (t==0){
            atomicAdd(&st[ch0+g],      sA);  atomicAdd(&st[C1+ch0+g],   sA2);
            atomicAdd(&st[ch0+g+8],    sB);  atomicAdd(&st[C1+ch0+g+8], sB2);
        }
        #pragma unroll
        for (int gi=0; gi<NG; gi++){
            float mxA=-3.4e38f, mnA=3.4e38f, mxB=-3.4e38f, mnB=3.4e38f;
            #pragma unroll
            for (int u=0; u<NTPG; u++){
                float* a = acc[cc][gi*NTPG+u];
                mxA=fmaxf(mxA,fmaxf(a[0],a[1])); mnA=fminf(mnA,fminf(a[0],a[1]));
                mxB=fmaxf(mxB,fmaxf(a[2],a[3])); mnB=fminf(mnB,fminf(a[2],a[3]));
            }
            #pragma unroll
            for (int o=1;o<4;o<<=1){
                mxA=fmaxf(mxA,__shfl_xor_sync(0xffffffffu,mxA,o));
                mnA=fminf(mnA,__shfl_xor_sync(0xffffffffu,mnA,o));
                mxB=fmaxf(mxB,__shfl_xor_sync(0xffffffffu,mxB,o));
                mnB=fminf(mnB,__shfl_xor_sync(0xffffffffu,mnB,o));
            }
            if (t==0){
                int gg = gbase + gi;
                g_rawmax[(ch0+g)*GRPS   + gg] = mxA;  g_rawmin[(ch0+g)*GRPS   + gg] = mnA;
                g_rawmax[(ch0+g+8)*GRPS + gg] = mxB;  g_rawmin[(ch0+g+8)*GRPS + gg] = mnB;
            }
        }
    }
    __syncthreads();
    for (int i=tid;i<C1;i+=NTH){
        atomicAdd(&g_stats1[sidx*256+i],     st[i]);
        atomicAdd(&g_stats1[sidx*256+128+i], st[C1+i]);
    }
}

// ---------------- finalize ----------------
template<int K,int C1>
__global__ void out_kernel(const float* __restrict__ g1v, const float* __restrict__ b1v,
                           float* __restrict__ out, int chOff, int sidx)
{
    int i = blockIdx.x*blockDim.x + threadIdx.x;
    if (i >= C1*GRPS) return;
    int c = i / GRPS; int g = i - c*GRPS;
    int b = g >> 10, m = g & 1023;
    float cnt  = (float)(GRPS*K);
    float mean = g_stats1[sidx*256+c]/cnt;
    float var  = g_stats1[sidx*256+128+c]/cnt - mean*mean;
    float a    = g1v[c]/sqrtf(var + 1e-5f);
    float bb   = b1v[c] - mean*a;
    float v1   = a*g_rawmax[c*GRPS + g] + bb;
    float v2   = a*g_rawmin[c*GRPS + g] + bb;
    out[XYZ_OUT + ((size_t)b*320 + chOff + c)*MM + m] = fmaxf(gelu_exact(v1), gelu_exact(v2));
}

// ---------------- launch ----------------
extern "C" void kernel_launch(void* const* d_in, const int* in_sizes, int n_in,
                              void* d_out, int out_size)
{
    const float* xyz  = (const float*)d_in[0];
    const float* feat = (const float*)d_in[1];
    const float* w00  = (const float*)d_in[2];
    const float* w01  = (const float*)d_in[3];
    const float* w10  = (const float*)d_in[4];
    const float* w11  = (const float*)d_in[5];
    const float* w20  = (const float*)d_in[6];
    const float* w21  = (const float*)d_in[7];
    const float* g00  = (const float*)d_in[8];
    const float* b00  = (const float*)d_in[9];
    const float* g01  = (const float*)d_in[10];
    const float* b01  = (const float*)d_in[11];
    const float* g10  = (const float*)d_in[12];
    const float* b10  = (const float*)d_in[13];
    const float* g11  = (const float*)d_in[14];
    const float* b11  = (const float*)d_in[15];
    const float* g20  = (const float*)d_in[16];
    const float* b20  = (const float*)d_in[17];
    const float* g21  = (const float*)d_in[18];
    const float* b21  = (const float*)d_in[19];
    float* out = (float*)d_out;
    float* newxyz = out;

    const int smFPS = 3*NN*4;
    const int smBQ  = 3*NN*4;
    const int smDEN = 8*128*4*8;                               // 32KB
    const int smC0  = 4*128*4*8 + (5*32 + 2*64)*4;             // ~17.2KB
    const int smC12 = 8*128*4*8 + (5*64 + 2*128)*4;            // ~34.3KB

    cudaFuncSetAttribute(fps_kernel,       cudaFuncAttributeMaxDynamicSharedMemorySize, smFPS);
    cudaFuncSetAttribute(ballq_kernel,     cudaFuncAttributeMaxDynamicSharedMemorySize, smBQ);
    cudaFuncSetAttribute(dense_kernel<32>, cudaFuncAttributeMaxDynamicSharedMemorySize, smDEN);
    cudaFuncSetAttribute(dense_kernel<64>, cudaFuncAttributeMaxDynamicSharedMemorySize, smDEN);
    cudaFuncSetAttribute(passC_kernel<16,32,64>,  cudaFuncAttributeMaxDynamicSharedMemorySize, smC0);
    cudaFuncSetAttribute(passC_kernel<32,64,128>, cudaFuncAttributeMaxDynamicSharedMemorySize, smC12);
    cudaFuncSetAttribute(passC_kernel<64,64,128>, cudaFuncAttributeMaxDynamicSharedMemorySize, smC12);

    fps_kernel<<<BB, 1024, smFPS>>>(xyz, newxyz);
    ballq_kernel<<<GRPS/8, 256, smBQ>>>(xyz, newxyz);

    prep_kernel<<<(WF_TOT+255)/256, 256>>>(w00, w10, w20, w01, w11, w21);
    dense_kernel<32><<<NPT/128, 256, smDEN>>>(feat, OFF_D0, 0);
    dense_kernel<64><<<NPT/128, 256, smDEN>>>(feat, OFF_D1, 32);
    dense_kernel<64><<<NPT/128, 256, smDEN>>>(feat, OFF_D2, 96);

    zero_all_kernel<<<(3*NPT)/256, 256>>>();
    hist_kernel<16><<<GRPS*16/256, 256>>>(xyz, newxyz, 0,        0);
    hist_kernel<32><<<GRPS*32/256, 256>>>(xyz, newxyz, 16*GRPS,  1);
    hist_kernel<64><<<GRPS*64/256, 256>>>(xyz, newxyz, 48*GRPS,  2);
    chanstat_kernel<32><<<NPT/256, 256>>>(xyz, 0,  0);
    chanstat_kernel<64><<<NPT/256, 256>>>(xyz, 32, 1);
    chanstat_kernel<64><<<NPT/256, 256>>>(xyz, 96, 2);

    passC_kernel<16,32,64><<<GRPS*16/128, 256, smC0>>>(g00, b00, w00, xyz, newxyz, 0, 0, OFF_C0, 0);
    out_kernel<16,64><<<(64*GRPS)/256, 256>>>(g01, b01, out, 0, 0);

    passC_kernel<32,64,128><<<GRPS*32/128, 256, smC12>>>(g10, b10, w10, xyz, newxyz, 16*GRPS, 32, OFF_C1, 1);
    out_kernel<32,128><<<(128*GRPS)/256, 256>>>(g11, b11, out, 64, 1);

    passC_kernel<64,64,128><<<GRPS*64/128, 256, smC12>>>(g20, b20, w20, xyz, newxyz, 48*GRPS, 96, OFF_C2, 2);
    out_kernel<64,128><<<(128*GRPS)/256, 256>>>(g21, b21, out, 192, 2);
}

// round 17
// speedup vs baseline: 2.2010x; 1.0642x over previous
#include <cuda_runtime.h>
#include <math.h>
#include <stdint.h>

#define BB 16
#define NN 4096
#define MM 1024
#define CF 64
#define INCH 67
#define GRPS (BB*MM)
#define NPT (BB*NN)          // 65536 original points
#define FS 160               // g_f1 row stride (32+64+64)
#define XYZ_OUT ((size_t)BB*MM*3)

// weight-fragment segment offsets (float4 units)
#define OFF_D0 0
#define OFF_D1 512
#define OFF_D2 1536
#define OFF_C0 2560
#define OFF_C1 3072
#define OFF_C2 5120
#define WF_TOT 7168

// ---------------- device scratch ----------------
__device__ int    g_nbr[(16+32+64)*GRPS];
__device__ float  g_f1[(size_t)NPT*FS];
__device__ float4 g_wfh[WF_TOT];                    // fragment-packed weights (hi tf32)
__device__ int    g_cnt3[3*NPT];
__device__ float  g_cs3[3*NPT*3];
__device__ float  g_auxp3[3*9*32];                  // per-scale T/Q, 128B-spread
__device__ float  g_s13[3*128], g_s23[3*128], g_cr3[3*384];
__device__ float  g_rawmax[128 * GRPS];
__device__ float  g_rawmin[128 * GRPS];
__device__ float  g_stats1[3*256];                  // per-scale layer1 sum/sumsq

__device__ __forceinline__ float sqdist_rn(float dx, float dy, float dz){
    return __fadd_rn(__fadd_rn(__fmul_rn(dx,dx),__fmul_rn(dy,dy)),__fmul_rn(dz,dz));
}
__device__ __forceinline__ float gelu_exact(float x){
    return 0.5f * x * (1.0f + erff(x * 0.70710678118654752f));
}
__device__ __forceinline__ float tf32rna(float x){
    uint32_t h; asm("cvt.rna.tf32.f32 %0, %1;" : "=r"(h) : "f"(x));
    return __uint_as_float(h);
}
__device__ __forceinline__ void mma_tf32(float* d,
    uint32_t a0,uint32_t a1,uint32_t a2,uint32_t a3, uint32_t b0,uint32_t b1){
    asm volatile(
        "mma.sync.aligned.m16n8k8.row.col.f32.tf32.tf32.f32 "
        "{%0,%1,%2,%3}, {%4,%5,%6,%7}, {%8,%9}, {%0,%1,%2,%3};"
        : "+f"(d[0]), "+f"(d[1]), "+f"(d[2]), "+f"(d[3])
        : "r"(a0), "r"(a1), "r"(a2), "r"(a3), "r"(b0), "r"(b1));
}
// 1-term: A hi-only x B hi-only
__device__ __forceinline__ void mma1(float* acc, const float4& ah, const float2& bb){
    mma_tf32(acc, __float_as_uint(ah.x),__float_as_uint(ah.y),__float_as_uint(ah.z),__float_as_uint(ah.w),
                  __float_as_uint(bb.x),__float_as_uint(bb.y));
}
// 8 channel values -> 4 fragment float2 (hi-only), contiguous
__device__ __forceinline__ void pack_store_h(float2* dst, const float* v){
    #pragma unroll
    for (int t=0;t<4;t++)
        dst[t] = make_float2(tf32rna(v[t]), tf32rna(v[t+4]));
}

// ---------------- 0) weight fragment prep (hi tf32 only) ----------------
__global__ void prep_kernel(const float* __restrict__ w00, const float* __restrict__ w10,
                            const float* __restrict__ w20, const float* __restrict__ w01,
                            const float* __restrict__ w11, const float* __restrict__ w21){
    int i = blockIdx.x*256 + threadIdx.x;
    if (i >= WF_TOT) return;
    const float* w; int base, CT, ld, k0;
    if      (i < OFF_D1){ w=w00; base=OFF_D0; CT=2; ld=INCH; k0=3; }
    else if (i < OFF_D2){ w=w10; base=OFF_D1; CT=4; ld=INCH; k0=3; }
    else if (i < OFF_C0){ w=w20; base=OFF_D2; CT=4; ld=INCH; k0=3; }
    else if (i < OFF_C1){ w=w01; base=OFF_C0; CT=4; ld=32;   k0=0; }
    else if (i < OFF_C2){ w=w11; base=OFF_C1; CT=8; ld=64;   k0=0; }
    else               { w=w21; base=OFF_C2; CT=8; ld=64;   k0=0; }
    int rem = i - base;
    int ks = rem/(CT*32), r2 = rem - ks*CT*32, ct = r2>>5, ln = r2&31;
    int g = ln>>2, t = ln&3, c0 = ct*16, k = ks*8 + k0;
    float4 H;
    H.x = tf32rna(w[(c0+g  )*ld + k+t  ]);
    H.y = tf32rna(w[(c0+g+8)*ld + k+t  ]);
    H.z = tf32rna(w[(c0+g  )*ld + k+t+4]);
    H.w = tf32rna(w[(c0+g+8)*ld + k+t+4]);
    g_wfh[i]=H;
}

// ---------------- 1) farthest point sampling (REDUX) ----------------
__global__ void fps_kernel(const float* __restrict__ xyz, float* __restrict__ out_newxyz){
    extern __shared__ float sm[];
    float* sx = sm; float* sy = sm+NN; float* sz = sm+2*NN;
    __shared__ unsigned rv[2][32]; __shared__ int ri[2][32];
    int b = blockIdx.x, t = threadIdx.x, lane = t&31, wid = t>>5;
    for (int i=t;i<NN;i+=blockDim.x){
        const float* p = xyz + ((size_t)b*NN+i)*3;
        sx[i]=p[0]; sy[i]=p[1]; sz[i]=p[2];
    }
    __syncthreads();
    float dreg[4] = {1e10f,1e10f,1e10f,1e10f};
    int far = 0;
    for (int it=0; it<MM; it++){
        float cx=sx[far], cy=sy[far], cz=sz[far];
        if (t==0){
            float* o = out_newxyz + ((size_t)b*MM+it)*3;
            o[0]=cx; o[1]=cy; o[2]=cz;
        }
        float best=-1.0f; int bi=0;
        #pragma unroll
        for (int u=0;u<4;u++){
            int i = t + u*1024;
            float d  = sqdist_rn(sx[i]-cx, sy[i]-cy, sz[i]-cz);
            float nd = fminf(dreg[u], d);
            dreg[u]=nd;
            if (nd>best){ best=nd; bi=i; }
        }
        unsigned ub = __float_as_uint(best);
        unsigned m  = __reduce_max_sync(0xffffffffu, ub);
        unsigned ci = (ub==m)? (unsigned)bi : 0x7FFFFFFFu;
        unsigned mi = __reduce_min_sync(0xffffffffu, ci);
        if (lane==0){ rv[it&1][wid]=m; ri[it&1][wid]=(int)mi; }
        __syncthreads();
        unsigned u2 = rv[it&1][lane];
        int      i2 = ri[it&1][lane];
        unsigned m2 = __reduce_max_sync(0xffffffffu, u2);
        unsigned c2 = (u2==m2)? (unsigned)i2 : 0x7FFFFFFFu;
        far = (int)__reduce_min_sync(0xffffffffu, c2);
    }
}

// ---------------- 2) ball query ----------------
__global__ void __launch_bounds__(256)
ballq_kernel(const float* __restrict__ xyz, const float* __restrict__ newxyz){
    extern __shared__ float sm[];
    float* sx = sm; float* sy = sm+NN; float* sz = sm+2*NN;
    int tid = threadIdx.x;
    int gw0 = blockIdx.x*8;
    int b   = gw0 >> 10;
    const float* base = xyz + (size_t)b*NN*3;
    for (int j=tid;j<NN*3;j+=256){
        float v = base[j];
        int idx = j/3, ch = j-idx*3;
        if (ch==0) sx[idx]=v; else if (ch==1) sy[idx]=v; else sz[idx]=v;
    }
    __syncthreads();
    int w    = tid>>5;
    int lane = tid&31;
    int gw   = gw0 + w;
    float cx=newxyz[gw*3+0], cy=newxyz[gw*3+1], cz=newxyz[gw*3+2];
    const float R2_0=(float)(0.1*0.1), R2_1=(float)(0.2*0.2), R2_2=(float)(0.4*0.4);
    int c0=0,c1=0,c2=0, f0=0,f1=0,f2=0;
    int* n0 = g_nbr + gw*16;
    int* n1 = g_nbr + 16*GRPS + gw*32;
    int* n2 = g_nbr + 48*GRPS + gw*64;
    for (int s=0;s<NN;s+=32){
        int i = s + lane;
        float d = sqdist_rn(sx[i]-cx, sy[i]-cy, sz[i]-cz);
        unsigned m0=__ballot_sync(0xffffffffu, d<=R2_0);
        unsigned m1=__ballot_sync(0xffffffffu, d<=R2_1);
        unsigned m2=__ballot_sync(0xffffffffu, d<=R2_2);
        if (m0 && c0<16){
            if (c0==0) f0 = s + __ffs(m0) - 1;
            int r = __popc(m0 & ((1u<<lane)-1u));
            if ((m0>>lane)&1u){ if (c0+r<16) n0[c0+r]=i; }
            c0 += __popc(m0); if (c0>16) c0=16;
        }
        if (m1 && c1<32){
            if (c1==0) f1 = s + __ffs(m1) - 1;
            int r = __popc(m1 & ((1u<<lane)-1u));
            if ((m1>>lane)&1u){ if (c1+r<32) n1[c1+r]=i; }
            c1 += __popc(m1); if (c1>32) c1=32;
        }
        if (m2 && c2<64){
            if (c2==0) f2 = s + __ffs(m2) - 1;
            int r = __popc(m2 & ((1u<<lane)-1u));
            if ((m2>>lane)&1u){ if (c2+r<64) n2[c2+r]=i; }
            c2 += __popc(m2); if (c2>64) c2=64;
        }
        if (c0>=16 && c1>=32 && c2>=64) break;
    }
    for (int j=c0+lane;j<16;j+=32) n0[j]=f0;
    for (int j=c1+lane;j<32;j+=32) n1[j]=f1;
    for (int j=c2+lane;j<64;j+=32) n2[j]=f2;
}

// ---------------- zero ALL per-scale accumulators ----------------
__global__ void zero_all_kernel(){
    int i = blockIdx.x*256 + threadIdx.x;     // grid covers 3*NPT
    if (i < 3*NPT){
        g_cnt3[i]=0;
        g_cs3[i*3]=0.0f; g_cs3[i*3+1]=0.0f; g_cs3[i*3+2]=0.0f;
    }
    if (i < 3*9*32) g_auxp3[i]=0.0f;
    if (i < 3*128){ g_s13[i]=0.0f; g_s23[i]=0.0f; }
    if (i < 3*384) g_cr3[i]=0.0f;
    if (i < 3*256) g_stats1[i]=0.0f;
}

// ---------------- dense conv0 (hi-only, 1-term mma) ----------------
template<int C0>
__global__ void __launch_bounds__(256,2)
dense_kernel(const float* __restrict__ feat, int wofs, int coff){
    constexpr int KS = 8;
    constexpr int CT = C0/16;
    extern __shared__ float smf[];
    float2* inb2 = (float2*)smf;         // KS*128*4 float2 = 32KB
    int tid = threadIdx.x;
    int tp  = blockIdx.x*128;

    {
        int p = tid>>1, h = tid&1;
        const float* fs = feat + (size_t)(tp+p)*CF + h*32;
        float ch[32];
        #pragma unroll
        for (int q=0;q<8;q++){
            float4 v = *(const float4*)(fs + q*4);
            ch[q*4+0]=v.x; ch[q*4+1]=v.y; ch[q*4+2]=v.z; ch[q*4+3]=v.w;
        }
        #pragma unroll
        for (int ks=0;ks<4;ks++)
            pack_store_h(inb2 + ((((h*4+ks)<<7)+p)<<2), ch+ks*8);
    }
    __syncthreads();

    constexpr int CT2 = CT/2;
    constexpr int PG2 = 8/CT2;
    constexpr int PW  = 128/PG2;
    constexpr int NT  = PW/8;
    int ln = tid&31, w = tid>>5;
    int g = ln>>2, t = ln&3;
    int ct2 = w%CT2;
    int pb  = (w/CT2)*PW;

    float acc[2][NT][4];
    #pragma unroll
    for (int cc=0;cc<2;cc++)
        #pragma unroll
        for (int nt=0;nt<NT;nt++){ acc[cc][nt][0]=0;acc[cc][nt][1]=0;acc[cc][nt][2]=0;acc[cc][nt][3]=0; }

    for (int ks=0; ks<KS; ks++){
        float4 ah0 = __ldg(&g_wfh[wofs + (ks*CT+ct2*2  )*32+ln]);
        float4 ah1 = __ldg(&g_wfh[wofs + (ks*CT+ct2*2+1)*32+ln]);
        #pragma unroll
        for (int nt=0;nt<NT;nt++){
            float2 bb = inb2[((ks<<7) + pb + nt*8 + g)*4 + t];
            mma1(acc[0][nt], ah0, bb);
            mma1(acc[1][nt], ah1, bb);
        }
    }

    #pragma unroll
    for (int cc=0;cc<2;cc++){
        int ch0 = (ct2*2+cc)*16;
        #pragma unroll
        for (int nt=0;nt<NT;nt++){
            int pofs = tp + pb + nt*8 + 2*t;
            size_t base = (size_t)pofs*FS + coff + ch0;
            g_f1[base + g]        = acc[cc][nt][0];
            g_f1[base + FS + g]   = acc[cc][nt][1];
            g_f1[base + g+8]      = acc[cc][nt][2];
            g_f1[base + FS + g+8] = acc[cc][nt][3];
        }
    }
}

// ---------------- histogram ----------------
template<int K>
__global__ void hist_kernel(const float* __restrict__ xyz, const float* __restrict__ nxyz,
                            int noff, int sidx){
    __shared__ float saux[8][9];
    int tid = threadIdx.x, lane = tid&31, wid = tid>>5;
    int gp = blockIdx.x*256 + tid;
    int g  = gp / K;
    int n  = g_nbr[noff+gp];
    int b  = g >> 10;
    int pt = (b<<12) + n;
    int*   cnt = g_cnt3 + sidx*NPT;
    float* cs  = g_cs3  + sidx*NPT*3;
    float cgx=nxyz[g*3], cgy=nxyz[g*3+1], cgz=nxyz[g*3+2];
    float dx = xyz[pt*3]-cgx, dy = xyz[pt*3+1]-cgy, dz = xyz[pt*3+2]-cgz;
    atomicAdd(&cnt[pt], 1);
    atomicAdd(&cs[pt*3+0], cgx);
    atomicAdd(&cs[pt*3+1], cgy);
    atomicAdd(&cs[pt*3+2], cgz);
    float v[9] = {dx,dy,dz, dx*dx,dy*dy,dz*dz, dx*dy,dx*dz,dy*dz};
    #pragma unroll
    for (int q=0;q<9;q++){
        float s=v[q];
        #pragma unroll
        for (int o=16;o;o>>=1) s += __shfl_down_sync(0xffffffffu,s,o);
        v[q]=s;
    }
    if (lane==0){
        #pragma unroll
        for (int q=0;q<9;q++) saux[wid][q]=v[q];
    }
    __syncthreads();
    if (tid < 9){
        float s=0.0f;
        #pragma unroll
        for (int w=0;w<8;w++) s += saux[w][tid];
        atomicAdd(&g_auxp3[sidx*288 + tid*32], s);
    }
}

// ---------------- per-channel stats ----------------
template<int C0>
__global__ void chanstat_kernel(const float* __restrict__ xyz, int coff, int sidx){
    __shared__ float sCnt[256], sRx[256], sRy[256], sRz[256];
    __shared__ float st1[C0], st2[C0], scx[C0], scy[C0], scz[C0];
    int tid = threadIdx.x, n0 = blockIdx.x*256;
    const int*   cnt = g_cnt3 + sidx*NPT;
    const float* cs  = g_cs3  + sidx*NPT*3;
    {
        int n = n0 + tid;
        float c = (float)cnt[n];
        sCnt[tid] = c;
        sRx[tid] = c*xyz[n*3+0] - cs[n*3+0];
        sRy[tid] = c*xyz[n*3+1] - cs[n*3+1];
        sRz[tid] = c*xyz[n*3+2] - cs[n*3+2];
    }
    if (tid < C0){ st1[tid]=0; st2[tid]=0; scx[tid]=0; scy[tid]=0; scz[tid]=0; }
    __syncthreads();

    constexpr int QN = C0/4, NR = 256/QN;
    int cq = tid % QN, j = tid / QN;
    float a1[4]={0,0,0,0}, a2[4]={0,0,0,0}, ax[4]={0,0,0,0}, ay[4]={0,0,0,0}, az[4]={0,0,0,0};
    for (int jj=j; jj<256; jj+=NR){
        float4 f = *(const float4*)(g_f1 + (size_t)(n0+jj)*FS + coff + cq*4);
        float c = sCnt[jj], Rx = sRx[jj], Ry = sRy[jj], Rz = sRz[jj];
        float fv[4] = {f.x,f.y,f.z,f.w};
        #pragma unroll
        for (int q=0;q<4;q++){
            a1[q] = fmaf(c, fv[q], a1[q]);
            a2[q] = fmaf(c*fv[q], fv[q], a2[q]);
            ax[q] = fmaf(fv[q], Rx, ax[q]);
            ay[q] = fmaf(fv[q], Ry, ay[q]);
            az[q] = fmaf(fv[q], Rz, az[q]);
        }
    }
    #pragma unroll
    for (int q=0;q<4;q++){
        atomicAdd(&st1[cq*4+q], a1[q]);
        atomicAdd(&st2[cq*4+q], a2[q]);
        atomicAdd(&scx[cq*4+q], ax[q]);
        atomicAdd(&scy[cq*4+q], ay[q]);
        atomicAdd(&scz[cq*4+q], az[q]);
    }
    __syncthreads();
    if (tid < C0){
        atomicAdd(&g_s13[sidx*128+tid], st1[tid]);
        atomicAdd(&g_s23[sidx*128+tid], st2[tid]);
        atomicAdd(&g_cr3[sidx*384+tid*3+0], scx[tid]);
        atomicAdd(&g_cr3[sidx*384+tid*3+1], scy[tid]);
        atomicAdd(&g_cr3[sidx*384+tid*3+2], scz[tid]);
    }
}

// ---------------- pass C: stats0 finalize + fill (hi-only) + 1-term tf32 mma conv1 ----------------
template<int K,int C0,int C1>
__global__ void __launch_bounds__(256,2)
passC_kernel(const float* __restrict__ g0v, const float* __restrict__ b0v,
             const float* __restrict__ w0,
             const float* __restrict__ xyz, const float* __restrict__ nxyz,
             int noff, int coff, int wofs, int sidx)
{
    const int P = GRPS*K;
    constexpr int PTS = 128, NTH = 256;
    constexpr int KS = C0/8;
    constexpr int CT = C1/16;
    extern __shared__ float smf[];
    float2* gsb2 = (float2*)smf;                 // KS*PTS*4 float2
    float*  qa   = (float*)(gsb2 + KS*PTS*4);
    float*  qb   = qa + C0;
    float*  q0   = qb + C0;
    float*  q1   = q0 + C0;
    float*  q2   = q1 + C0;
    float*  st   = q2 + C0;                      // 2*C1
    int tid = threadIdx.x, tp = blockIdx.x*PTS;

    if (tid < C0){
        float wx=w0[tid*INCH+0], wy=w0[tid*INCH+1], wz=w0[tid*INCH+2];
        const float* ax = g_auxp3 + sidx*288;
        float T0=ax[0*32], T1=ax[1*32], T2=ax[2*32];
        float Qxx=ax[3*32], Qyy=ax[4*32], Qzz=ax[5*32];
        float Qxy=ax[6*32], Qxz=ax[7*32], Qyz=ax[8*32];
        float sum = g_s13[sidx*128+tid] + wx*T0 + wy*T1 + wz*T2;
        float cr  = wx*g_cr3[sidx*384+tid*3+0] + wy*g_cr3[sidx*384+tid*3+1] + wz*g_cr3[sidx*384+tid*3+2];
        float qf  = wx*wx*Qxx + wy*wy*Qyy + wz*wz*Qzz
                  + 2.0f*(wx*wy*Qxy + wx*wz*Qxz + wy*wz*Qyz);
        float sumsq = g_s23[sidx*128+tid] + 2.0f*cr + qf;
        float cnt  = (float)P;
        float mean = sum/cnt;
        float var  = sumsq/cnt - mean*mean;
        float a    = g0v[tid]/sqrtf(var + 1e-5f);
        qa[tid] = a;
        qb[tid] = b0v[tid] - mean*a;
        q0[tid] = a*wx;
        q1[tid] = a*wy;
        q2[tid] = a*wz;
    }
    for (int i=tid;i<2*C1;i+=NTH) st[i]=0.0f;
    __syncthreads();

    {
        int p = tid>>1, h = tid&1;
        int gp = tp + p;
        int g  = gp / K;
        int n  = g_nbr[noff+gp];
        int b  = g >> 10;
        int pt = (b<<12) + n;
        float dx = xyz[pt*3+0]-nxyz[g*3+0];
        float dy = xyz[pt*3+1]-nxyz[g*3+1];
        float dz = xyz[pt*3+2]-nxyz[g*3+2];
        const float* f1 = g_f1 + (size_t)pt*FS + coff;
        #pragma unroll
        for (int ks=h*(KS/2); ks<(h+1)*(KS/2); ks++){
            float4 fa = *(const float4*)(f1 + ks*8);
            float4 fb = *(const float4*)(f1 + ks*8 + 4);
            float4 A0 = *(const float4*)(qa + ks*8), A1 = *(const float4*)(qa + ks*8 + 4);
            float4 B0 = *(const float4*)(qb + ks*8), B1 = *(const float4*)(qb + ks*8 + 4);
            float4 X0 = *(const float4*)(q0 + ks*8), X1 = *(const float4*)(q0 + ks*8 + 4);
            float4 Y0 = *(const float4*)(q1 + ks*8), Y1 = *(const float4*)(q1 + ks*8 + 4);
            float4 Z0 = *(const float4*)(q2 + ks*8), Z1 = *(const float4*)(q2 + ks*8 + 4);
            float ch[8];
            ch[0]=fmaf(X0.x,dx,fmaf(Y0.x,dy,fmaf(Z0.x,dz,fmaf(A0.x,fa.x,B0.x))));
            ch[1]=fmaf(X0.y,dx,fmaf(Y0.y,dy,fmaf(Z0.y,dz,fmaf(A0.y,fa.y,B0.y))));
            ch[2]=fmaf(X0.z,dx,fmaf(Y0.z,dy,fmaf(Z0.z,dz,fmaf(A0.z,fa.z,B0.z))));
            ch[3]=fmaf(X0.w,dx,fmaf(Y0.w,dy,fmaf(Z0.w,dz,fmaf(A0.w,fa.w,B0.w))));
            ch[4]=fmaf(X1.x,dx,fmaf(Y1.x,dy,fmaf(Z1.x,dz,fmaf(A1.x,fb.x,B1.x))));
            ch[5]=fmaf(X1.y,dx,fmaf(Y1.y,dy,fmaf(Z1.y,dz,fmaf(A1.y,fb.y,B1.y))));
            ch[6]=fmaf(X1.z,dx,fmaf(Y1.z,dy,fmaf(Z1.z,dz,fmaf(A1.z,fb.z,B1.z))));
            ch[7]=fmaf(X1.w,dx,fmaf(Y1.w,dy,fmaf(Z1.w,dz,fmaf(A1.w,fb.w,B1.w))));
            #pragma unroll
            for (int j=0;j<8;j++) ch[j] = gelu_exact(ch[j]);
            pack_store_h(gsb2 + ((ks*PTS+p)<<2), ch);
        }
    }
    __syncthreads();

    constexpr int NW  = NTH/32;
    constexpr int CT2 = CT/2;
    constexpr int PG2 = NW/CT2;
    constexpr int PW  = PTS/PG2;
    constexpr int NT  = PW/8;
    int ln = tid&31, w = tid>>5;
    int g = ln>>2, t = ln&3;
    int ct2 = w%CT2;
    int pb  = (w/CT2)*PW;

    float acc[2][NT][4];
    #pragma unroll
    for (int cc=0;cc<2;cc++)
        #pragma unroll
        for (int nt=0;nt<NT;nt++){ acc[cc][nt][0]=0;acc[cc][nt][1]=0;acc[cc][nt][2]=0;acc[cc][nt][3]=0; }

    for (int ks=0; ks<KS; ks++){
        float4 ah0 = __ldg(&g_wfh[wofs + (ks*CT+ct2*2  )*32+ln]);
        float4 ah1 = __ldg(&g_wfh[wofs + (ks*CT+ct2*2+1)*32+ln]);
        #pragma unroll
        for (int nt=0;nt<NT;nt++){
            float2 bb = gsb2[(ks*PTS + pb + nt*8 + g)*4 + t];
            mma1(acc[0][nt], ah0, bb);
            mma1(acc[1][nt], ah1, bb);
        }
    }

    constexpr int NTPG = K/8;
    constexpr int NG   = (NT/NTPG > 0) ? NT/NTPG : 1;
    int gbase = (tp + pb)/K;
    #pragma unroll
    for (int cc=0;cc<2;cc++){
        int ch0 = (ct2*2+cc)*16;
        float sA=0,sA2=0,sB=0,sB2=0;
        #pragma unroll
        for (int nt=0;nt<NT;nt++){
            float x=acc[cc][nt][0], y=acc[cc][nt][1], z=acc[cc][nt][2], v=acc[cc][nt][3];
            sA += x+y; sA2 += x*x+y*y; sB += z+v; sB2 += z*z+v*v;
        }
        #pragma unroll
        for (int o=1;o<4;o<<=1){
            sA  += __shfl_xor_sync(0xffffffffu,sA,o);
            sA2 += __shfl_xor_sync(0xffffffffu,sA2,o);
            sB  += __shfl_xor_sync(0xffffffffu,sB,o);
            sB2 += __shfl_xor_sync(0xffffffffu,sB2,o);
        }
        if (t==0){
            atomicAdd(&st[ch0+g],      sA);  atomicAdd(&st[C1+ch0+g],   sA2);
            atomicAdd(&st[ch0+g+8],    sB);  atomicAdd(&st[C1+ch0+g+8], sB2);
        }
        #pragma unroll
        for (int gi=0; gi<NG; gi++){
            float mxA=-3.4e38f, mnA=3.4e38f, mxB=-3.4e38f, mnB=3.4e38f;
            #pragma unroll
            for (int u=0; u<NTPG; u++){
                float* a = acc[cc][gi*NTPG+u];
                mxA=fmaxf(mxA,fmaxf(a[0],a[1])); mnA=fminf(mnA,fminf(a[0],a[1]));
                mxB=fmaxf(mxB,fmaxf(a[2],a[3])); mnB=fminf(mnB,fminf(a[2],a[3]));
            }
            #pragma unroll
            for (int o=1;o<4;o<<=1){
                mxA=fmaxf(mxA,__shfl_xor_sync(0xffffffffu,mxA,o));
                mnA=fminf(mnA,__shfl_xor_sync(0xffffffffu,mnA,o));
                mxB=fmaxf(mxB,__shfl_xor_sync(0xffffffffu,mxB,o));
                mnB=fminf(mnB,__shfl_xor_sync(0xffffffffu,mnB,o));
            }
            if (t==0){
                int gg = gbase + gi;
                g_rawmax[(ch0+g)*GRPS   + gg] = mxA;  g_rawmin[(ch0+g)*GRPS   + gg] = mnA;
                g_rawmax[(ch0+g+8)*GRPS + gg] = mxB;  g_rawmin[(ch0+g+8)*GRPS + gg] = mnB;
            }
        }
    }
    __syncthreads();
    for (int i=tid;i<C1;i+=NTH){
        atomicAdd(&g_stats1[sidx*256+i],     st[i]);
        atomicAdd(&g_stats1[sidx*256+128+i], st[C1+i]);
    }
}

// ---------------- finalize ----------------
template<int K,int C1>
__global__ void out_kernel(const float* __restrict__ g1v, const float* __restrict__ b1v,
                           float* __restrict__ out, int chOff, int sidx)
{
    int i = blockIdx.x*blockDim.x + threadIdx.x;
    if (i >= C1*GRPS) return;
    int c = i / GRPS; int g = i - c*GRPS;
    int b = g >> 10, m = g & 1023;
    float cnt  = (float)(GRPS*K);
    float mean = g_stats1[sidx*256+c]/cnt;
    float var  = g_stats1[sidx*256+128+c]/cnt - mean*mean;
    float a    = g1v[c]/sqrtf(var + 1e-5f);
    float bb   = b1v[c] - mean*a;
    float v1   = a*g_rawmax[c*GRPS + g] + bb;
    float v2   = a*g_rawmin[c*GRPS + g] + bb;
    out[XYZ_OUT + ((size_t)b*320 + chOff + c)*MM + m] = fmaxf(gelu_exact(v1), gelu_exact(v2));
}

// ---------------- launch ----------------
extern "C" void kernel_launch(void* const* d_in, const int* in_sizes, int n_in,
                              void* d_out, int out_size)
{
    const float* xyz  = (const float*)d_in[0];
    const float* feat = (const float*)d_in[1];
    const float* w00  = (const float*)d_in[2];
    const float* w01  = (const float*)d_in[3];
    const float* w10  = (const float*)d_in[4];
    const float* w11  = (const float*)d_in[5];
    const float* w20  = (const float*)d_in[6];
    const float* w21  = (const float*)d_in[7];
    const float* g00  = (const float*)d_in[8];
    const float* b00  = (const float*)d_in[9];
    const float* g01  = (const float*)d_in[10];
    const float* b01  = (const float*)d_in[11];
    const float* g10  = (const float*)d_in[12];
    const float* b10  = (const float*)d_in[13];
    const float* g11  = (const float*)d_in[14];
    const float* b11  = (const float*)d_in[15];
    const float* g20  = (const float*)d_in[16];
    const float* b20  = (const float*)d_in[17];
    const float* g21  = (const float*)d_in[18];
    const float* b21  = (const float*)d_in[19];
    float* out = (float*)d_out;
    float* newxyz = out;

    const int smFPS = 3*NN*4;
    const int smBQ  = 3*NN*4;
    const int smDEN = 8*128*4*8;                               // 32KB
    const int smC0  = 4*128*4*8 + (5*32 + 2*64)*4;             // ~17.2KB
    const int smC12 = 8*128*4*8 + (5*64 + 2*128)*4;            // ~34.3KB

    cudaFuncSetAttribute(fps_kernel,       cudaFuncAttributeMaxDynamicSharedMemorySize, smFPS);
    cudaFuncSetAttribute(ballq_kernel,     cudaFuncAttributeMaxDynamicSharedMemorySize, smBQ);
    cudaFuncSetAttribute(dense_kernel<32>, cudaFuncAttributeMaxDynamicSharedMemorySize, smDEN);
    cudaFuncSetAttribute(dense_kernel<64>, cudaFuncAttributeMaxDynamicSharedMemorySize, smDEN);
    cudaFuncSetAttribute(passC_kernel<16,32,64>,  cudaFuncAttributeMaxDynamicSharedMemorySize, smC0);
    cudaFuncSetAttribute(passC_kernel<32,64,128>, cudaFuncAttributeMaxDynamicSharedMemorySize, smC12);
    cudaFuncSetAttribute(passC_kernel<64,64,128>, cudaFuncAttributeMaxDynamicSharedMemorySize, smC12);

    fps_kernel<<<BB, 1024, smFPS>>>(xyz, newxyz);
    ballq_kernel<<<GRPS/8, 256, smBQ>>>(xyz, newxyz);

    prep_kernel<<<(WF_TOT+255)/256, 256>>>(w00, w10, w20, w01, w11, w21);
    dense_kernel<32><<<NPT/128, 256, smDEN>>>(feat, OFF_D0, 0);
    dense_kernel<64><<<NPT/128, 256, smDEN>>>(feat, OFF_D1, 32);
    dense_kernel<64><<<NPT/128, 256, smDEN>>>(feat, OFF_D2, 96);

    zero_all_kernel<<<(3*NPT)/256, 256>>>();
    hist_kernel<16><<<GRPS*16/256, 256>>>(xyz, newxyz, 0,        0);
    hist_kernel<32><<<GRPS*32/256, 256>>>(xyz, newxyz, 16*GRPS,  1);
    hist_kernel<64><<<GRPS*64/256, 256>>>(xyz, newxyz, 48*GRPS,  2);
    chanstat_kernel<32><<<NPT/256, 256>>>(xyz, 0,  0);
    chanstat_kernel<64><<<NPT/256, 256>>>(xyz, 32, 1);
    chanstat_kernel<64><<<NPT/256, 256>>>(xyz, 96, 2);

    passC_kernel<16,32,64><<<GRPS*16/128, 256, smC0>>>(g00, b00, w00, xyz, newxyz, 0, 0, OFF_C0, 0);
    out_kernel<16,64><<<(64*GRPS)/256, 256>>>(g01, b01, out, 0, 0);

    passC_kernel<32,64,128><<<GRPS*32/128, 256, smC12>>>(g10, b10, w10, xyz, newxyz, 16*GRPS, 32, OFF_C1, 1);
    out_kernel<32,128><<<(128*GRPS)/256, 256>>>(g11, b11, out, 64, 1);

    passC_kernel<64,64,128><<<GRPS*64/128, 256, smC12>>>(g20, b20, w20, xyz, newxyz, 48*GRPS, 96, OFF_C2, 2);
    out_kernel<64,128><<<(128*GRPS)/256, 256>>>(g21, b21, out, 192, 2);
}